// round 2
// baseline (speedup 1.0000x reference)
#include <cuda_runtime.h>
#include <cuda_bf16.h>
#include <cstdint>

#define NPTS   50000
#define MPTS   50001
#define DIM    512
#define HID    512
#define TSTEPS 16
#define NBP    444            // blocks for the big pass kernels (148*3)
#define NEGINF (__int_as_float(0xff800000))

// ---------------- device scratch (no cudaMalloc allowed) ----------------
__device__ float g_af[(size_t)MPTS * DIM];     // attn_feat  (102.4 MB)
__device__ float g_hf[(size_t)MPTS * DIM];     // hop_feat   (102.4 MB)
__device__ float g_gates[4 * HID];
__device__ float g_h[HID];
__device__ float g_cbuf[2][HID];               // double buffered c
__device__ float g_x[DIM];
__device__ float g_qh[HID];                    // h @ hop_wq
__device__ float g_ba[HID];                    // q @ attn_wq
__device__ unsigned char g_sel[MPTS];
__device__ int   g_done;
__device__ float g_hpart[NBP][514];            // [max, sumw, acc512]
__device__ float g_apart[NBP][3];              // [best(score+g), max score, sumexp]
__device__ int   g_aidx[NBP];

// ---------------- helpers ----------------
__device__ __forceinline__ float tanhe(float x) {
    float e = __expf(2.f * x);
    return 1.f - __fdividef(2.f, e + 1.f);     // handles +/-inf saturations
}
__device__ __forceinline__ float sigm(float x) {
    return __fdividef(1.f, 1.f + __expf(-x));
}
__device__ __forceinline__ void ffma2(unsigned long long &d, unsigned long long a, unsigned long long b) {
    asm("fma.rn.f32x2 %0, %1, %2, %0;" : "+l"(d) : "l"(a), "l"(b));
}
__device__ __forceinline__ unsigned long long dup2(float b) {
    unsigned long long r; asm("mov.b64 %0, {%1, %1};" : "=l"(r) : "f"(b)); return r;
}
__device__ __forceinline__ float2 upk(unsigned long long v) {
    float2 f; asm("mov.b64 {%0, %1}, %2;" : "=f"(f.x), "=f"(f.y) : "l"(v)); return f;
}
__device__ __forceinline__ float4 ld_memrow(const float* __restrict__ mem,
                                            const float* __restrict__ stop, int r, int k) {
    if (r < NPTS)   return *(const float4*)&mem[(size_t)r * DIM + k];
    if (r == NPTS)  return *(const float4*)&stop[k];
    return make_float4(0.f, 0.f, 0.f, 0.f);
}

// ---------------- K0: state init (must run every launch) ----------------
__global__ void k_init(const float* __restrict__ ih, const float* __restrict__ ic,
                       const float* __restrict__ ii) {
    int i = blockIdx.x * blockDim.x + threadIdx.x;
    if (i < MPTS) g_sel[i] = 0;
    if (i < HID) { g_h[i] = ih[i]; g_cbuf[0][i] = ic[i]; g_x[i] = ii[i]; }
    if (i == 0) g_done = 0;
}

// ---------------- GEMM: feats = mem @ [attn_wm | hop_wm] ----------------
// 128x64 tile, 256 threads, 8x4 per thread, fp32x2 packed FMA.
__global__ void __launch_bounds__(256) k_feat(const float* __restrict__ mem,
                                              const float* __restrict__ stop,
                                              const float* __restrict__ attn_wm,
                                              const float* __restrict__ hop_wm) {
    __shared__ float As[16][130];
    __shared__ float Bs[16][68];
    int tid = threadIdx.x;
    int bx = blockIdx.x, by = blockIdx.y;
    int rowBase = by * 128;

    const float* wptr; int cb; float* outp;
    if (bx < 8) { wptr = attn_wm; cb = bx * 64;       outp = g_af; }
    else        { wptr = hop_wm;  cb = (bx - 8) * 64; outp = g_hf; }

    int trow = (tid / 16) * 8;
    int tcol = (tid % 16) * 4;

    unsigned long long acc[4][4];
#pragma unroll
    for (int p = 0; p < 4; p++)
#pragma unroll
        for (int j = 0; j < 4; j++) acc[p][j] = 0ULL;

    int ar0 = tid >> 2,        ak0 = (tid & 3) * 4;
    int ar1 = (tid >> 2) + 64, ak1 = ak0;
    int bK = tid >> 4, bC = (tid & 15) * 4;

    for (int kb = 0; kb < DIM; kb += 16) {
        float4 a0 = ld_memrow(mem, stop, rowBase + ar0, kb + ak0);
        float4 a1 = ld_memrow(mem, stop, rowBase + ar1, kb + ak1);
        float4 b0 = *(const float4*)&wptr[(size_t)(kb + bK) * DIM + cb + bC];
        __syncthreads();
        As[ak0 + 0][ar0] = a0.x; As[ak0 + 1][ar0] = a0.y;
        As[ak0 + 2][ar0] = a0.z; As[ak0 + 3][ar0] = a0.w;
        As[ak1 + 0][ar1] = a1.x; As[ak1 + 1][ar1] = a1.y;
        As[ak1 + 2][ar1] = a1.z; As[ak1 + 3][ar1] = a1.w;
        *(float4*)&Bs[bK][bC] = b0;
        __syncthreads();
#pragma unroll
        for (int kk = 0; kk < 16; kk++) {
            const unsigned long long* ap = (const unsigned long long*)&As[kk][trow];
            unsigned long long a_0 = ap[0], a_1 = ap[1], a_2 = ap[2], a_3 = ap[3];
            float4 bq = *(const float4*)&Bs[kk][tcol];
            unsigned long long bb0 = dup2(bq.x), bb1 = dup2(bq.y);
            unsigned long long bb2 = dup2(bq.z), bb3 = dup2(bq.w);
            ffma2(acc[0][0], a_0, bb0); ffma2(acc[0][1], a_0, bb1);
            ffma2(acc[0][2], a_0, bb2); ffma2(acc[0][3], a_0, bb3);
            ffma2(acc[1][0], a_1, bb0); ffma2(acc[1][1], a_1, bb1);
            ffma2(acc[1][2], a_1, bb2); ffma2(acc[1][3], a_1, bb3);
            ffma2(acc[2][0], a_2, bb0); ffma2(acc[2][1], a_2, bb1);
            ffma2(acc[2][2], a_2, bb2); ffma2(acc[2][3], a_2, bb3);
            ffma2(acc[3][0], a_3, bb0); ffma2(acc[3][1], a_3, bb1);
            ffma2(acc[3][2], a_3, bb2); ffma2(acc[3][3], a_3, bb3);
        }
    }
#pragma unroll
    for (int p = 0; p < 4; p++) {
#pragma unroll
        for (int j = 0; j < 4; j++) {
            float2 f = upk(acc[p][j]);
            int gr = rowBase + trow + 2 * p;
            int gc = cb + tcol + j;
            if (gr < MPTS)     outp[(size_t)gr * DIM + gc]       = f.x;
            if (gr + 1 < MPTS) outp[(size_t)(gr + 1) * DIM + gc] = f.y;
        }
    }
}

// ---------------- K1: LSTM gates = x@w_ih.T + h@w_hh.T + biases ----------------
__global__ void k_gates(const float* __restrict__ w_ih, const float* __restrict__ w_hh,
                        const float* __restrict__ b_ih, const float* __restrict__ b_hh) {
    int w = blockIdx.x * 8 + (threadIdx.x >> 5);
    int lane = threadIdx.x & 31;
    const float* wi = w_ih + (size_t)w * DIM;
    const float* wh = w_hh + (size_t)w * HID;
    float s = 0.f;
#pragma unroll 4
    for (int k = lane; k < DIM; k += 32) s += wi[k] * g_x[k] + wh[k] * g_h[k];
#pragma unroll
    for (int o = 16; o; o >>= 1) s += __shfl_xor_sync(0xffffffffu, s, o);
    if (!lane) g_gates[w] = s + b_ih[w] + b_hh[w];
}

// ---------------- K2: h,c update (redundant per block) + qh = h @ hop_wq ----------------
__global__ void k_hc_qh(const float* __restrict__ hop_wq, int t) {
    __shared__ float sh[HID];
    int tid = threadIdx.x;                 // 128 threads, 4 blocks
    const float* cold = g_cbuf[t & 1];
    float* cnew = g_cbuf[(t + 1) & 1];
    for (int j = tid; j < HID; j += 128) {
        float gi = sigm(g_gates[j]);
        float gf = sigm(g_gates[HID + j]);
        float gg = tanhe(g_gates[2 * HID + j]);
        float go = sigm(g_gates[3 * HID + j]);
        float c = gf * cold[j] + gi * gg;
        float h = go * tanhe(c);
        sh[j] = h;
        if (blockIdx.x == 0) { g_h[j] = h; cnew[j] = c; }
    }
    __syncthreads();
    int col = blockIdx.x * 128 + tid;
    float acc = 0.f;
#pragma unroll 8
    for (int k = 0; k < HID; k++) acc += sh[k] * hop_wq[(size_t)k * HID + col];
    g_qh[col] = acc;
}

// ---------------- K3: hop pass — fused score + online-softmax weighted sum ----------------
__global__ void __launch_bounds__(256) k_hop(const float* __restrict__ hop_v) {
    int tid = threadIdx.x, wz = tid >> 5, lane = tid & 31;
    int gw = blockIdx.x * 8 + wz;
    const int tot = NBP * 8;

    float q0[16], v0[16];
#pragma unroll
    for (int r = 0; r < 4; r++) {
        float4 qq = *(const float4*)&g_qh[r * 128 + lane * 4];
        float4 vv = *(const float4*)&hop_v[r * 128 + lane * 4];
        q0[r*4+0]=qq.x; q0[r*4+1]=qq.y; q0[r*4+2]=qq.z; q0[r*4+3]=qq.w;
        v0[r*4+0]=vv.x; v0[r*4+1]=vv.y; v0[r*4+2]=vv.z; v0[r*4+3]=vv.w;
    }
    float mx = NEGINF, sw = 0.f, acc[16];
#pragma unroll
    for (int i = 0; i < 16; i++) acc[i] = 0.f;

    for (int m = gw; m < MPTS; m += tot) {
        const float4* rp = (const float4*)(g_hf + (size_t)m * DIM);
        float vals[16]; float sp = 0.f;
#pragma unroll
        for (int r = 0; r < 4; r++) {
            float4 f4 = rp[r * 32 + lane];
            vals[r*4+0]=f4.x; vals[r*4+1]=f4.y; vals[r*4+2]=f4.z; vals[r*4+3]=f4.w;
            sp += tanhe(f4.x + q0[r*4+0]) * v0[r*4+0];
            sp += tanhe(f4.y + q0[r*4+1]) * v0[r*4+1];
            sp += tanhe(f4.z + q0[r*4+2]) * v0[r*4+2];
            sp += tanhe(f4.w + q0[r*4+3]) * v0[r*4+3];
        }
#pragma unroll
        for (int o = 16; o; o >>= 1) sp += __shfl_xor_sync(0xffffffffu, sp, o);
        if (sp > mx) {
            float f = __expf(mx - sp);
            sw *= f;
#pragma unroll
            for (int i = 0; i < 16; i++) acc[i] *= f;
            mx = sp;
        }
        float wgt = __expf(sp - mx);
        sw += wgt;
#pragma unroll
        for (int i = 0; i < 16; i++) acc[i] += wgt * vals[i];
    }
    __shared__ float smx[8], ssw[8], sacc[8][512];
#pragma unroll
    for (int r = 0; r < 4; r++)
#pragma unroll
        for (int s = 0; s < 4; s++) sacc[wz][r * 128 + lane * 4 + s] = acc[r * 4 + s];
    if (!lane) { smx[wz] = mx; ssw[wz] = sw; }
    __syncthreads();

    float M = smx[0];
#pragma unroll
    for (int w = 1; w < 8; w++) M = fmaxf(M, smx[w]);
    for (int c = tid; c < 512; c += 256) {
        float a = 0.f;
#pragma unroll
        for (int w = 0; w < 8; w++) a += sacc[w][c] * __expf(smx[w] - M);
        g_hpart[blockIdx.x][2 + c] = a;
    }
    if (tid == 0) {
        float W = 0.f;
#pragma unroll
        for (int w = 0; w < 8; w++) W += ssw[w] * __expf(smx[w] - M);
        g_hpart[blockIdx.x][0] = M;
        g_hpart[blockIdx.x][1] = W;
    }
}

// ---------------- K4: reduce q partials + bias = q @ attn_wq (redundant per block) ----------------
__global__ void k_qred_bias(const float* __restrict__ attn_wq) {
    __shared__ float red[128];
    __shared__ float f[NBP];
    __shared__ float qn[512];
    int tid = threadIdx.x;                 // 128 threads, 4 blocks
    float m = NEGINF;
    for (int b = tid; b < NBP; b += 128) m = fmaxf(m, g_hpart[b][0]);
    red[tid] = m; __syncthreads();
    for (int o = 64; o; o >>= 1) { if (tid < o) red[tid] = fmaxf(red[tid], red[tid + o]); __syncthreads(); }
    float M = red[0];
    __syncthreads();
    float wsum = 0.f;
    for (int b = tid; b < NBP; b += 128) {
        float e = __expf(g_hpart[b][0] - M);
        f[b] = e;
        wsum += e * g_hpart[b][1];
    }
    red[tid] = wsum; __syncthreads();
    for (int o = 64; o; o >>= 1) { if (tid < o) red[tid] += red[tid + o]; __syncthreads(); }
    float W = red[0];
    __syncthreads();
    float a0 = 0.f, a1 = 0.f, a2 = 0.f, a3 = 0.f;
    for (int b = 0; b < NBP; b++) {
        float e = f[b];
        const float* p = &g_hpart[b][2];
        a0 += e * p[tid]; a1 += e * p[tid + 128];
        a2 += e * p[tid + 256]; a3 += e * p[tid + 384];
    }
    float inv = 1.f / W;
    qn[tid] = a0 * inv; qn[tid + 128] = a1 * inv;
    qn[tid + 256] = a2 * inv; qn[tid + 384] = a3 * inv;
    __syncthreads();
    int col = blockIdx.x * 128 + tid;
    float acc = 0.f;
#pragma unroll 8
    for (int k = 0; k < HID; k++) acc += qn[k] * attn_wq[(size_t)k * HID + col];
    g_ba[col] = acc;
}

// ---------------- K5: attn pass — masked score, argmax(score+g), online LSE ----------------
__global__ void __launch_bounds__(256) k_attn(const float* __restrict__ attn_v,
                                              const float* __restrict__ gumbel, int t) {
    int tid = threadIdx.x, wz = tid >> 5, lane = tid & 31;
    int gw = blockIdx.x * 8 + wz;
    const int tot = NBP * 8;
    const float* gum = gumbel + (size_t)t * MPTS;

    float b0[16], v0[16];
#pragma unroll
    for (int r = 0; r < 4; r++) {
        float4 bb = *(const float4*)&g_ba[r * 128 + lane * 4];
        float4 vv = *(const float4*)&attn_v[r * 128 + lane * 4];
        b0[r*4+0]=bb.x; b0[r*4+1]=bb.y; b0[r*4+2]=bb.z; b0[r*4+3]=bb.w;
        v0[r*4+0]=vv.x; v0[r*4+1]=vv.y; v0[r*4+2]=vv.z; v0[r*4+3]=vv.w;
    }
    float mxs = NEGINF, ssum = 0.f, best = NEGINF;
    int bidx = 0x7fffffff;

    for (int m = gw; m < MPTS; m += tot) {
        const float4* rp = (const float4*)(g_af + (size_t)m * DIM);
        float sp = 0.f;
#pragma unroll
        for (int r = 0; r < 4; r++) {
            float4 f4 = rp[r * 32 + lane];
            sp += tanhe(f4.x + b0[r*4+0]) * v0[r*4+0];
            sp += tanhe(f4.y + b0[r*4+1]) * v0[r*4+1];
            sp += tanhe(f4.z + b0[r*4+2]) * v0[r*4+2];
            sp += tanhe(f4.w + b0[r*4+3]) * v0[r*4+3];
        }
#pragma unroll
        for (int o = 16; o; o >>= 1) sp += __shfl_xor_sync(0xffffffffu, sp, o);
        float sc = g_sel[m] ? -1e18f : sp;
        if (sc > mxs) { ssum *= __expf(mxs - sc); mxs = sc; }
        ssum += __expf(sc - mxs);
        float tv = sc + gum[m];
        if (tv > best || (tv == best && m < bidx)) { best = tv; bidx = m; }
    }
    __shared__ float sb[8]; __shared__ int si[8];
    __shared__ float sm[8]; __shared__ float ss[8];
    if (!lane) { sb[wz] = best; si[wz] = bidx; sm[wz] = mxs; ss[wz] = ssum; }
    __syncthreads();
    if (tid == 0) {
        float B = sb[0]; int I = si[0];
        float M2 = sm[0], S = ss[0];
#pragma unroll
        for (int w = 1; w < 8; w++) {
            if (sb[w] > B || (sb[w] == B && si[w] < I)) { B = sb[w]; I = si[w]; }
            float m2 = sm[w], s2 = ss[w];
            if (m2 > M2) { S = S * __expf(M2 - m2) + s2; M2 = m2; }
            else S += s2 * __expf(m2 - M2);
        }
        g_apart[blockIdx.x][0] = B; g_apart[blockIdx.x][1] = M2;
        g_apart[blockIdx.x][2] = S; g_aidx[blockIdx.x] = I;
    }
}

// ---------------- K6: final select + state update + outputs ----------------
__global__ void k_final(const float* __restrict__ attn_mem, const float* __restrict__ stop,
                        const float* __restrict__ gumbel, float* __restrict__ out, int t) {
    __shared__ float sb[512]; __shared__ int si[512];
    __shared__ float sm[512]; __shared__ float ss[512];
    __shared__ int s_out, s_nd;
    int tid = threadIdx.x;
    float B = NEGINF; int I = 0x7fffffff; float M = NEGINF; float S = 0.f;
    if (tid < NBP) { B = g_apart[tid][0]; M = g_apart[tid][1]; S = g_apart[tid][2]; I = g_aidx[tid]; }
    sb[tid] = B; si[tid] = I; sm[tid] = M; ss[tid] = S;
    __syncthreads();
    for (int o = 256; o; o >>= 1) {
        if (tid < o) {
            if (sb[tid + o] > sb[tid] || (sb[tid + o] == sb[tid] && si[tid + o] < si[tid])) {
                sb[tid] = sb[tid + o]; si[tid] = si[tid + o];
            }
            float m1 = sm[tid], s1 = ss[tid];
            float m2 = sm[tid + o], s2 = ss[tid + o];
            float Mn = fmaxf(m1, m2);
            float Sn = 0.f;
            if (s1 > 0.f) Sn += s1 * __expf(m1 - Mn);
            if (s2 > 0.f) Sn += s2 * __expf(m2 - Mn);
            sm[tid] = Mn; ss[tid] = Sn;
        }
        __syncthreads();
    }
    if (tid == 0) {
        int done = g_done;
        int o_ = si[0];
        float sc = sb[0] - gumbel[(size_t)t * MPTS + o_];
        float lse = sm[0] + logf(ss[0]);
        float logp = sc - lse;
        out[t]          = done ? (float)NPTS : (float)o_;
        out[TSTEPS + t] = done ? 0.f : logp;
        if (!done) g_sel[o_] = 1;
        int nd = done || (o_ == NPTS);
        g_done = nd;
        s_out = o_; s_nd = nd;
    }
    __syncthreads();
    if (!s_nd && tid < DIM) {
        int o_ = s_out;
        const float* src = (o_ == NPTS) ? stop : attn_mem + (size_t)o_ * DIM;
        g_x[tid] = src[tid];
    }
}

// ---------------- launch ----------------
extern "C" void kernel_launch(void* const* d_in, const int* in_sizes, int n_in,
                              void* d_out, int out_size) {
    const float* attn_mem = (const float*)d_in[0];
    const float* stop     = (const float*)d_in[1];
    const float* init_h   = (const float*)d_in[2];
    const float* init_c   = (const float*)d_in[3];
    const float* init_i   = (const float*)d_in[4];
    const float* attn_wm  = (const float*)d_in[5];
    const float* attn_wq  = (const float*)d_in[6];
    const float* attn_v   = (const float*)d_in[7];
    const float* hop_wm   = (const float*)d_in[8];
    const float* hop_wq   = (const float*)d_in[9];
    const float* hop_v    = (const float*)d_in[10];
    const float* w_ih     = (const float*)d_in[11];
    const float* w_hh     = (const float*)d_in[12];
    const float* b_ih     = (const float*)d_in[13];
    const float* b_hh     = (const float*)d_in[14];
    const float* gumbel   = (const float*)d_in[15];
    float* out = (float*)d_out;

    k_init<<<(MPTS + 255) / 256, 256>>>(init_h, init_c, init_i);

    dim3 gg(16, (MPTS + 127) / 128);
    k_feat<<<gg, 256>>>(attn_mem, stop, attn_wm, hop_wm);

    for (int t = 0; t < TSTEPS; t++) {
        k_gates<<<256, 256>>>(w_ih, w_hh, b_ih, b_hh);
        k_hc_qh<<<4, 128>>>(hop_wq, t);
        k_hop<<<NBP, 256>>>(hop_v);
        k_qred_bias<<<4, 128>>>(attn_wq);
        k_attn<<<NBP, 256>>>(attn_v, gumbel, t);
        k_final<<<1, 512>>>(attn_mem, stop, gumbel, out, t);
    }
}

// round 3
// speedup vs baseline: 1.7939x; 1.7939x over previous
#include <cuda_runtime.h>
#include <cuda_bf16.h>
#include <cstdint>

#define NPTS   50000
#define MPTS   50001
#define DIM    512
#define HID    512
#define TSTEPS 16
#define NBP    444            // blocks for the big pass kernels (148*3)
#define NEGINF (__int_as_float(0xff800000))

// ---------------- device scratch (no cudaMalloc allowed) ----------------
__device__ float g_af[(size_t)MPTS * DIM];     // attn_feat  (102.4 MB)
__device__ float g_hf[(size_t)MPTS * DIM];     // hop_feat   (102.4 MB)
__device__ float g_gates[4 * HID];
__device__ float g_h[HID];
__device__ float g_cbuf[2][HID];               // double buffered c
__device__ float g_x[DIM];
__device__ float g_qh[HID];                    // h @ hop_wq (atomic acc)
__device__ float g_ba[HID];                    // q @ attn_wq (atomic acc)
__device__ unsigned char g_sel[MPTS];
__device__ int   g_done;
__device__ float g_hpart[NBP][514];            // [max, sumw, acc512]
__device__ float g_apart[NBP][3];              // [best(score+g), max score, sumexp]
__device__ int   g_aidx[NBP];

// ---------------- helpers ----------------
__device__ __forceinline__ float tanhe(float x) {
    float e = __expf(2.f * x);
    return 1.f - __fdividef(2.f, e + 1.f);     // handles +/-inf saturations
}
__device__ __forceinline__ float sigm(float x) {
    return __fdividef(1.f, 1.f + __expf(-x));
}
__device__ __forceinline__ void ffma2(unsigned long long &d, unsigned long long a, unsigned long long b) {
    asm("fma.rn.f32x2 %0, %1, %2, %0;" : "+l"(d) : "l"(a), "l"(b));
}
__device__ __forceinline__ unsigned long long dup2(float b) {
    unsigned long long r; asm("mov.b64 %0, {%1, %1};" : "=l"(r) : "f"(b)); return r;
}
__device__ __forceinline__ float2 upk(unsigned long long v) {
    float2 f; asm("mov.b64 {%0, %1}, %2;" : "=f"(f.x), "=f"(f.y) : "l"(v)); return f;
}
__device__ __forceinline__ float4 ld_memrow(const float* __restrict__ mem,
                                            const float* __restrict__ stop, int r, int k) {
    if (r < NPTS)   return *(const float4*)&mem[(size_t)r * DIM + k];
    if (r == NPTS)  return *(const float4*)&stop[k];
    return make_float4(0.f, 0.f, 0.f, 0.f);
}

// ---------------- K0: state init (must run every launch) ----------------
__global__ void k_init(const float* __restrict__ ih, const float* __restrict__ ic,
                       const float* __restrict__ ii) {
    int i = blockIdx.x * blockDim.x + threadIdx.x;
    if (i < MPTS) g_sel[i] = 0;
    if (i < HID) { g_h[i] = ih[i]; g_cbuf[0][i] = ic[i]; g_x[i] = ii[i]; }
    if (i == 0) g_done = 0;
}

// ---------------- GEMM: feats = mem @ [attn_wm | hop_wm] ----------------
// 128x64 tile, 256 threads, 8x4 per thread, fp32x2 packed FMA.
__global__ void __launch_bounds__(256) k_feat(const float* __restrict__ mem,
                                              const float* __restrict__ stop,
                                              const float* __restrict__ attn_wm,
                                              const float* __restrict__ hop_wm) {
    __shared__ float As[16][130];
    __shared__ float Bs[16][68];
    int tid = threadIdx.x;
    int bx = blockIdx.x, by = blockIdx.y;
    int rowBase = by * 128;

    const float* wptr; int cb; float* outp;
    if (bx < 8) { wptr = attn_wm; cb = bx * 64;       outp = g_af; }
    else        { wptr = hop_wm;  cb = (bx - 8) * 64; outp = g_hf; }

    int trow = (tid / 16) * 8;
    int tcol = (tid % 16) * 4;

    unsigned long long acc[4][4];
#pragma unroll
    for (int p = 0; p < 4; p++)
#pragma unroll
        for (int j = 0; j < 4; j++) acc[p][j] = 0ULL;

    int ar0 = tid >> 2,        ak0 = (tid & 3) * 4;
    int ar1 = (tid >> 2) + 64, ak1 = ak0;
    int bK = tid >> 4, bC = (tid & 15) * 4;

    for (int kb = 0; kb < DIM; kb += 16) {
        float4 a0 = ld_memrow(mem, stop, rowBase + ar0, kb + ak0);
        float4 a1 = ld_memrow(mem, stop, rowBase + ar1, kb + ak1);
        float4 b0 = *(const float4*)&wptr[(size_t)(kb + bK) * DIM + cb + bC];
        __syncthreads();
        As[ak0 + 0][ar0] = a0.x; As[ak0 + 1][ar0] = a0.y;
        As[ak0 + 2][ar0] = a0.z; As[ak0 + 3][ar0] = a0.w;
        As[ak1 + 0][ar1] = a1.x; As[ak1 + 1][ar1] = a1.y;
        As[ak1 + 2][ar1] = a1.z; As[ak1 + 3][ar1] = a1.w;
        *(float4*)&Bs[bK][bC] = b0;
        __syncthreads();
#pragma unroll
        for (int kk = 0; kk < 16; kk++) {
            const unsigned long long* ap = (const unsigned long long*)&As[kk][trow];
            unsigned long long a_0 = ap[0], a_1 = ap[1], a_2 = ap[2], a_3 = ap[3];
            float4 bq = *(const float4*)&Bs[kk][tcol];
            unsigned long long bb0 = dup2(bq.x), bb1 = dup2(bq.y);
            unsigned long long bb2 = dup2(bq.z), bb3 = dup2(bq.w);
            ffma2(acc[0][0], a_0, bb0); ffma2(acc[0][1], a_0, bb1);
            ffma2(acc[0][2], a_0, bb2); ffma2(acc[0][3], a_0, bb3);
            ffma2(acc[1][0], a_1, bb0); ffma2(acc[1][1], a_1, bb1);
            ffma2(acc[1][2], a_1, bb2); ffma2(acc[1][3], a_1, bb3);
            ffma2(acc[2][0], a_2, bb0); ffma2(acc[2][1], a_2, bb1);
            ffma2(acc[2][2], a_2, bb2); ffma2(acc[2][3], a_2, bb3);
            ffma2(acc[3][0], a_3, bb0); ffma2(acc[3][1], a_3, bb1);
            ffma2(acc[3][2], a_3, bb2); ffma2(acc[3][3], a_3, bb3);
        }
    }
#pragma unroll
    for (int p = 0; p < 4; p++) {
#pragma unroll
        for (int j = 0; j < 4; j++) {
            float2 f = upk(acc[p][j]);
            int gr = rowBase + trow + 2 * p;
            int gc = cb + tcol + j;
            if (gr < MPTS)     outp[(size_t)gr * DIM + gc]       = f.x;
            if (gr + 1 < MPTS) outp[(size_t)(gr + 1) * DIM + gc] = f.y;
        }
    }
}

// ---------------- K1: LSTM gates = x@w_ih.T + h@w_hh.T + biases ----------------
// Also zeroes g_qh for this step's k_qh atomics (block 0).
__global__ void k_gates(const float* __restrict__ w_ih, const float* __restrict__ w_hh,
                        const float* __restrict__ b_ih, const float* __restrict__ b_hh) {
    int tid = threadIdx.x;
    if (blockIdx.x == 0) { g_qh[tid] = 0.f; g_qh[tid + 256] = 0.f; }
    int w = blockIdx.x * 8 + (tid >> 5);
    int lane = tid & 31;
    const float* wi = w_ih + (size_t)w * DIM;
    const float* wh = w_hh + (size_t)w * HID;
    float s = 0.f;
#pragma unroll 4
    for (int k = lane; k < DIM; k += 32) s += wi[k] * g_x[k] + wh[k] * g_h[k];
#pragma unroll
    for (int o = 16; o; o >>= 1) s += __shfl_xor_sync(0xffffffffu, s, o);
    if (!lane) g_gates[w] = s + b_ih[w] + b_hh[w];
}

// ---------------- K2: h,c update + qh = h @ hop_wq (wide, atomic acc) ----------------
// 32 blocks x 256 threads; block b owns k-chunk [16b, 16b+16).
__global__ void __launch_bounds__(256) k_qh(const float* __restrict__ hop_wq, int t) {
    __shared__ float sh[16];
    int tid = threadIdx.x;
    int kb = blockIdx.x * 16;
    const float* cold = g_cbuf[t & 1];
    float* cnew = g_cbuf[(t + 1) & 1];

    // block 0 publishes the full new h, c for later kernels / next step
    if (blockIdx.x == 0) {
#pragma unroll
        for (int j = tid; j < HID; j += 256) {
            float gi = sigm(g_gates[j]);
            float gf = sigm(g_gates[HID + j]);
            float gg = tanhe(g_gates[2 * HID + j]);
            float go = sigm(g_gates[3 * HID + j]);
            float c = gf * cold[j] + gi * gg;
            g_h[j] = go * tanhe(c);
            cnew[j] = c;
        }
    }
    // every block redundantly computes the 16 h values of its own k-chunk
    if (tid < 16) {
        int j = kb + tid;
        float gi = sigm(g_gates[j]);
        float gf = sigm(g_gates[HID + j]);
        float gg = tanhe(g_gates[2 * HID + j]);
        float go = sigm(g_gates[3 * HID + j]);
        float c = gf * cold[j] + gi * gg;
        sh[tid] = go * tanhe(c);
    }
    __syncthreads();

    float a0 = 0.f, a1 = 0.f;
#pragma unroll
    for (int kk = 0; kk < 16; kk++) {
        float hv = sh[kk];
        const float* wr = hop_wq + (size_t)(kb + kk) * HID;
        a0 += hv * wr[tid];
        a1 += hv * wr[tid + 256];
    }
    atomicAdd(&g_qh[tid], a0);
    atomicAdd(&g_qh[tid + 256], a1);
}

// ---------------- K3: hop pass — fused score + online-softmax weighted sum ----------------
__global__ void __launch_bounds__(256) k_hop(const float* __restrict__ hop_v) {
    int tid = threadIdx.x, wz = tid >> 5, lane = tid & 31;
    if (blockIdx.x == 0) { g_ba[tid] = 0.f; g_ba[tid + 256] = 0.f; }  // for k_bias atomics
    int gw = blockIdx.x * 8 + wz;
    const int tot = NBP * 8;

    float q0[16], v0[16];
#pragma unroll
    for (int r = 0; r < 4; r++) {
        float4 qq = *(const float4*)&g_qh[r * 128 + lane * 4];
        float4 vv = *(const float4*)&hop_v[r * 128 + lane * 4];
        q0[r*4+0]=qq.x; q0[r*4+1]=qq.y; q0[r*4+2]=qq.z; q0[r*4+3]=qq.w;
        v0[r*4+0]=vv.x; v0[r*4+1]=vv.y; v0[r*4+2]=vv.z; v0[r*4+3]=vv.w;
    }
    float mx = NEGINF, sw = 0.f, acc[16];
#pragma unroll
    for (int i = 0; i < 16; i++) acc[i] = 0.f;

    for (int m = gw; m < MPTS; m += tot) {
        const float4* rp = (const float4*)(g_hf + (size_t)m * DIM);
        float vals[16]; float sp = 0.f;
#pragma unroll
        for (int r = 0; r < 4; r++) {
            float4 f4 = rp[r * 32 + lane];
            vals[r*4+0]=f4.x; vals[r*4+1]=f4.y; vals[r*4+2]=f4.z; vals[r*4+3]=f4.w;
            sp += tanhe(f4.x + q0[r*4+0]) * v0[r*4+0];
            sp += tanhe(f4.y + q0[r*4+1]) * v0[r*4+1];
            sp += tanhe(f4.z + q0[r*4+2]) * v0[r*4+2];
            sp += tanhe(f4.w + q0[r*4+3]) * v0[r*4+3];
        }
#pragma unroll
        for (int o = 16; o; o >>= 1) sp += __shfl_xor_sync(0xffffffffu, sp, o);
        if (sp > mx) {
            float f = __expf(mx - sp);
            sw *= f;
#pragma unroll
            for (int i = 0; i < 16; i++) acc[i] *= f;
            mx = sp;
        }
        float wgt = __expf(sp - mx);
        sw += wgt;
#pragma unroll
        for (int i = 0; i < 16; i++) acc[i] += wgt * vals[i];
    }
    __shared__ float smx[8], ssw[8], sacc[8][512];
#pragma unroll
    for (int r = 0; r < 4; r++)
#pragma unroll
        for (int s = 0; s < 4; s++) sacc[wz][r * 128 + lane * 4 + s] = acc[r * 4 + s];
    if (!lane) { smx[wz] = mx; ssw[wz] = sw; }
    __syncthreads();

    float M = smx[0];
#pragma unroll
    for (int w = 1; w < 8; w++) M = fmaxf(M, smx[w]);
    for (int c = tid; c < 512; c += 256) {
        float a = 0.f;
#pragma unroll
        for (int w = 0; w < 8; w++) a += sacc[w][c] * __expf(smx[w] - M);
        g_hpart[blockIdx.x][2 + c] = a;
    }
    if (tid == 0) {
        float W = 0.f;
#pragma unroll
        for (int w = 0; w < 8; w++) W += ssw[w] * __expf(smx[w] - M);
        g_hpart[blockIdx.x][0] = M;
        g_hpart[blockIdx.x][1] = W;
    }
}

// ---------------- K4: reduce hop partials + bias = q @ attn_wq (wide, atomic acc) ----------------
// 32 blocks x 256 threads; each block redundantly reduces the softmax partials
// it needs (L2-resident), computes q for its 16-k chunk, then a GEMV partial.
__global__ void __launch_bounds__(256) k_bias(const float* __restrict__ attn_wq) {
    __shared__ float red[256];
    __shared__ float qn[16];
    int tid = threadIdx.x;
    int kb = blockIdx.x * 16;

    // global max over 444 block maxima
    float m = NEGINF;
    for (int b = tid; b < NBP; b += 256) m = fmaxf(m, g_hpart[b][0]);
    red[tid] = m; __syncthreads();
    for (int o = 128; o; o >>= 1) { if (tid < o) red[tid] = fmaxf(red[tid], red[tid + o]); __syncthreads(); }
    float M = red[0]; __syncthreads();

    // total softmax weight
    float wsum = 0.f;
    for (int b = tid; b < NBP; b += 256) wsum += __expf(g_hpart[b][0] - M) * g_hpart[b][1];
    red[tid] = wsum; __syncthreads();
    for (int o = 128; o; o >>= 1) { if (tid < o) red[tid] += red[tid + o]; __syncthreads(); }
    float W = red[0]; __syncthreads();

    // q values for this block's 16 k's: 16 groups of 16 lanes split the 444 partials
    {
        int g = tid >> 4, l = tid & 15;
        int k = kb + g;
        float a = 0.f;
#pragma unroll 4
        for (int b = l; b < NBP; b += 16)
            a += __expf(g_hpart[b][0] - M) * g_hpart[b][2 + k];
        a += __shfl_xor_sync(0xffffffffu, a, 8);
        a += __shfl_xor_sync(0xffffffffu, a, 4);
        a += __shfl_xor_sync(0xffffffffu, a, 2);
        a += __shfl_xor_sync(0xffffffffu, a, 1);
        if (l == 0) qn[g] = __fdividef(a, W);
    }
    __syncthreads();

    float a0 = 0.f, a1 = 0.f;
#pragma unroll
    for (int kk = 0; kk < 16; kk++) {
        float q = qn[kk];
        const float* wr = attn_wq + (size_t)(kb + kk) * HID;
        a0 += q * wr[tid];
        a1 += q * wr[tid + 256];
    }
    atomicAdd(&g_ba[tid], a0);
    atomicAdd(&g_ba[tid + 256], a1);
}

// ---------------- K5: attn pass — masked score, argmax(score+g), online LSE ----------------
__global__ void __launch_bounds__(256) k_attn(const float* __restrict__ attn_v,
                                              const float* __restrict__ gumbel, int t) {
    int tid = threadIdx.x, wz = tid >> 5, lane = tid & 31;
    int gw = blockIdx.x * 8 + wz;
    const int tot = NBP * 8;
    const float* gum = gumbel + (size_t)t * MPTS;

    float b0[16], v0[16];
#pragma unroll
    for (int r = 0; r < 4; r++) {
        float4 bb = *(const float4*)&g_ba[r * 128 + lane * 4];
        float4 vv = *(const float4*)&attn_v[r * 128 + lane * 4];
        b0[r*4+0]=bb.x; b0[r*4+1]=bb.y; b0[r*4+2]=bb.z; b0[r*4+3]=bb.w;
        v0[r*4+0]=vv.x; v0[r*4+1]=vv.y; v0[r*4+2]=vv.z; v0[r*4+3]=vv.w;
    }
    float mxs = NEGINF, ssum = 0.f, best = NEGINF;
    int bidx = 0x7fffffff;

    for (int m = gw; m < MPTS; m += tot) {
        const float4* rp = (const float4*)(g_af + (size_t)m * DIM);
        float sp = 0.f;
#pragma unroll
        for (int r = 0; r < 4; r++) {
            float4 f4 = rp[r * 32 + lane];
            sp += tanhe(f4.x + b0[r*4+0]) * v0[r*4+0];
            sp += tanhe(f4.y + b0[r*4+1]) * v0[r*4+1];
            sp += tanhe(f4.z + b0[r*4+2]) * v0[r*4+2];
            sp += tanhe(f4.w + b0[r*4+3]) * v0[r*4+3];
        }
#pragma unroll
        for (int o = 16; o; o >>= 1) sp += __shfl_xor_sync(0xffffffffu, sp, o);
        float sc = g_sel[m] ? -1e18f : sp;
        if (sc > mxs) { ssum *= __expf(mxs - sc); mxs = sc; }
        ssum += __expf(sc - mxs);
        float tv = sc + gum[m];
        if (tv > best || (tv == best && m < bidx)) { best = tv; bidx = m; }
    }
    __shared__ float sb[8]; __shared__ int si[8];
    __shared__ float sm[8]; __shared__ float ss[8];
    if (!lane) { sb[wz] = best; si[wz] = bidx; sm[wz] = mxs; ss[wz] = ssum; }
    __syncthreads();
    if (tid == 0) {
        float B = sb[0]; int I = si[0];
        float M2 = sm[0], S = ss[0];
#pragma unroll
        for (int w = 1; w < 8; w++) {
            if (sb[w] > B || (sb[w] == B && si[w] < I)) { B = sb[w]; I = si[w]; }
            float m2 = sm[w], s2 = ss[w];
            if (m2 > M2) { S = S * __expf(M2 - m2) + s2; M2 = m2; }
            else S += s2 * __expf(m2 - M2);
        }
        g_apart[blockIdx.x][0] = B; g_apart[blockIdx.x][1] = M2;
        g_apart[blockIdx.x][2] = S; g_aidx[blockIdx.x] = I;
    }
}

// ---------------- K6: final select + state update + outputs ----------------
__global__ void k_final(const float* __restrict__ attn_mem, const float* __restrict__ stop,
                        const float* __restrict__ gumbel, float* __restrict__ out, int t) {
    __shared__ float sb[512]; __shared__ int si[512];
    __shared__ float sm[512]; __shared__ float ss[512];
    __shared__ int s_out, s_nd;
    int tid = threadIdx.x;
    float B = NEGINF; int I = 0x7fffffff; float M = NEGINF; float S = 0.f;
    if (tid < NBP) { B = g_apart[tid][0]; M = g_apart[tid][1]; S = g_apart[tid][2]; I = g_aidx[tid]; }
    sb[tid] = B; si[tid] = I; sm[tid] = M; ss[tid] = S;
    __syncthreads();
    for (int o = 256; o; o >>= 1) {
        if (tid < o) {
            if (sb[tid + o] > sb[tid] || (sb[tid + o] == sb[tid] && si[tid + o] < si[tid])) {
                sb[tid] = sb[tid + o]; si[tid] = si[tid + o];
            }
            float m1 = sm[tid], s1 = ss[tid];
            float m2 = sm[tid + o], s2 = ss[tid + o];
            float Mn = fmaxf(m1, m2);
            float Sn = 0.f;
            if (s1 > 0.f) Sn += s1 * __expf(m1 - Mn);
            if (s2 > 0.f) Sn += s2 * __expf(m2 - Mn);
            sm[tid] = Mn; ss[tid] = Sn;
        }
        __syncthreads();
    }
    if (tid == 0) {
        int done = g_done;
        int o_ = si[0];
        float sc = sb[0] - gumbel[(size_t)t * MPTS + o_];
        float lse = sm[0] + logf(ss[0]);
        float logp = sc - lse;
        out[t]          = done ? (float)NPTS : (float)o_;
        out[TSTEPS + t] = done ? 0.f : logp;
        if (!done) g_sel[o_] = 1;
        int nd = done || (o_ == NPTS);
        g_done = nd;
        s_out = o_; s_nd = nd;
    }
    __syncthreads();
    if (!s_nd && tid < DIM) {
        int o_ = s_out;
        const float* src = (o_ == NPTS) ? stop : attn_mem + (size_t)o_ * DIM;
        g_x[tid] = src[tid];
    }
}

// ---------------- launch ----------------
extern "C" void kernel_launch(void* const* d_in, const int* in_sizes, int n_in,
                              void* d_out, int out_size) {
    const float* attn_mem = (const float*)d_in[0];
    const float* stop     = (const float*)d_in[1];
    const float* init_h   = (const float*)d_in[2];
    const float* init_c   = (const float*)d_in[3];
    const float* init_i   = (const float*)d_in[4];
    const float* attn_wm  = (const float*)d_in[5];
    const float* attn_wq  = (const float*)d_in[6];
    const float* attn_v   = (const float*)d_in[7];
    const float* hop_wm   = (const float*)d_in[8];
    const float* hop_wq   = (const float*)d_in[9];
    const float* hop_v    = (const float*)d_in[10];
    const float* w_ih     = (const float*)d_in[11];
    const float* w_hh     = (const float*)d_in[12];
    const float* b_ih     = (const float*)d_in[13];
    const float* b_hh     = (const float*)d_in[14];
    const float* gumbel   = (const float*)d_in[15];
    float* out = (float*)d_out;

    k_init<<<(MPTS + 255) / 256, 256>>>(init_h, init_c, init_i);

    dim3 gg(16, (MPTS + 127) / 128);
    k_feat<<<gg, 256>>>(attn_mem, stop, attn_wm, hop_wm);

    for (int t = 0; t < TSTEPS; t++) {
        k_gates<<<256, 256>>>(w_ih, w_hh, b_ih, b_hh);
        k_qh<<<32, 256>>>(hop_wq, t);
        k_hop<<<NBP, 256>>>(hop_v);
        k_bias<<<32, 256>>>(attn_wq);
        k_attn<<<NBP, 256>>>(attn_v, gumbel, t);
        k_final<<<1, 512>>>(attn_mem, stop, gumbel, out, t);
    }
}

// round 5
// speedup vs baseline: 2.5191x; 1.4043x over previous
#include <cuda_runtime.h>
#include <cuda_bf16.h>
#include <cstdint>

#define NPTS   50000
#define MPTS   50001
#define DIM    512
#define HID    512
#define TSTEPS 16
#define NBP    444
#define NEGINF (__int_as_float(0xff800000))

#define PADM   50048           // 391 * 128
#define ROWT   391
#define KP     1536            // K' = 3 * 512
#define NCH    48              // K' / 32

// ---------------- device scratch ----------------
__device__ float g_af[(size_t)MPTS * DIM];
__device__ float g_hf[(size_t)MPTS * DIM];
__device__ __nv_bfloat16 g_ahi[(size_t)PADM * DIM];
__device__ __nv_bfloat16 g_alo[(size_t)PADM * DIM];
__device__ __nv_bfloat16 g_bt[2][512][KP];     // [mat][n][k'] = [Bhi|Blo|Bhi]
__device__ float g_gates[4 * HID];
__device__ float g_h[HID];
__device__ float g_cbuf[2][HID];
__device__ float g_x[DIM];
__device__ float g_qh[HID];
__device__ float g_ba[HID];
__device__ unsigned char g_sel[MPTS];
__device__ int   g_done;
__device__ float g_hpart[NBP][514];
__device__ float g_apart[NBP][3];
__device__ int   g_aidx[NBP];

// ---------------- helpers ----------------
__device__ __forceinline__ float tanhe(float x) {          // accurate
    float e = __expf(2.f * x);
    return 1.f - __fdividef(2.f, e + 1.f);
}
__device__ __forceinline__ float tanha(float x) {          // HW tanh (1 MUFU)
    float y; asm("tanh.approx.f32 %0, %1;" : "=f"(y) : "f"(x)); return y;
}
__device__ __forceinline__ float sigm(float x) {
    return __fdividef(1.f, 1.f + __expf(-x));
}
__device__ __forceinline__ uint32_t s2u(const void* p) {
    uint32_t a;
    asm("{ .reg .u64 t; cvta.to.shared.u64 t, %1; cvt.u32.u64 %0, t; }" : "=r"(a) : "l"(p));
    return a;
}
__device__ __forceinline__ void cp16(uint32_t dst, const void* src) {
    asm volatile("cp.async.cg.shared.global [%0], [%1], 16;" :: "r"(dst), "l"(src));
}
__device__ __forceinline__ void ldm4(uint32_t& r0, uint32_t& r1, uint32_t& r2, uint32_t& r3,
                                     uint32_t addr) {
    asm volatile("ldmatrix.sync.aligned.m8n8.x4.shared.b16 {%0,%1,%2,%3}, [%4];"
                 : "=r"(r0), "=r"(r1), "=r"(r2), "=r"(r3) : "r"(addr));
}
__device__ __forceinline__ void mma16816(float* c, uint32_t a0, uint32_t a1, uint32_t a2,
                                         uint32_t a3, uint32_t b0, uint32_t b1) {
    asm volatile(
        "mma.sync.aligned.m16n8k16.row.col.f32.bf16.bf16.f32 "
        "{%0,%1,%2,%3},{%4,%5,%6,%7},{%8,%9},{%0,%1,%2,%3};"
        : "+f"(c[0]), "+f"(c[1]), "+f"(c[2]), "+f"(c[3])
        : "r"(a0), "r"(a1), "r"(a2), "r"(a3), "r"(b0), "r"(b1));
}
__device__ __forceinline__ unsigned pk2(float a, float b) {
    unsigned lo = __bfloat16_as_ushort(__float2bfloat16(a));
    unsigned hi = __bfloat16_as_ushort(__float2bfloat16(b));
    return lo | (hi << 16);
}

// ---------------- K0: state init ----------------
__global__ void k_init(const float* __restrict__ ih, const float* __restrict__ ic,
                       const float* __restrict__ ii) {
    int i = blockIdx.x * blockDim.x + threadIdx.x;
    if (i < MPTS) g_sel[i] = 0;
    if (i < HID) { g_h[i] = ih[i]; g_cbuf[0][i] = ic[i]; g_x[i] = ii[i]; }
    if (i == 0) g_done = 0;
}

// ---------------- convert A: mem(+stop,+pad) -> bf16 hi/lo ----------------
__global__ void k_convA(const float* __restrict__ mem, const float* __restrict__ stop) {
    const int total4 = PADM * DIM / 4;
    for (int i = blockIdx.x * blockDim.x + threadIdx.x; i < total4;
         i += gridDim.x * blockDim.x) {
        int row = i >> 7;
        int c4 = (i & 127) * 4;
        float4 v;
        if (row < NPTS)       v = *(const float4*)&mem[(size_t)row * DIM + c4];
        else if (row == NPTS) v = *(const float4*)&stop[c4];
        else                  v = make_float4(0.f, 0.f, 0.f, 0.f);
        float h0 = __bfloat162float(__float2bfloat16(v.x));
        float h1 = __bfloat162float(__float2bfloat16(v.y));
        float h2 = __bfloat162float(__float2bfloat16(v.z));
        float h3 = __bfloat162float(__float2bfloat16(v.w));
        uint2 ph, pl;
        ph.x = pk2(v.x, v.y); ph.y = pk2(v.z, v.w);
        pl.x = pk2(v.x - h0, v.y - h1); pl.y = pk2(v.z - h2, v.w - h3);
        ((uint2*)g_ahi)[i] = ph;
        ((uint2*)g_alo)[i] = pl;
    }
}

// ---------------- convert B: wm[k][n] -> g_bt[mat][n][k'] ----------------
__global__ void k_convB(const float* __restrict__ attn_wm, const float* __restrict__ hop_wm) {
    int id = blockIdx.x * blockDim.x + threadIdx.x;
    if (id >= 2 * 512 * 512) return;
    int w = id >> 18;
    int r = id & 262143;
    int n = r >> 9;
    int k = r & 511;
    const float* src = w ? hop_wm : attn_wm;
    float x = src[(size_t)k * 512 + n];
    __nv_bfloat16 hi = __float2bfloat16(x);
    __nv_bfloat16 lo = __float2bfloat16(x - __bfloat162float(hi));
    g_bt[w][n][k]        = hi;
    g_bt[w][n][512 + k]  = lo;
    g_bt[w][n][1024 + k] = hi;
}

// ---------------- GEMM: bf16-split mma.sync, CTA 128x128, K'=1536 ----------------
// 8 warps: 4(m) x 2(n); warp tile 32x64. K-chunk 32, cp.async double buffer.
// smem rows padded to 40 bf16 (80B) -> ldmatrix conflict-free.
__global__ void __launch_bounds__(256, 2) k_feat_mma() {
    __shared__ __align__(16) __nv_bfloat16 sA[2][128 * 40];
    __shared__ __align__(16) __nv_bfloat16 sB[2][128 * 40];
    int tid = threadIdx.x, wid = tid >> 5, lane = tid & 31;
    int rowBase = blockIdx.x * 128;
    int colBase = blockIdx.y * 128;
    int mat = blockIdx.z;
    const __nv_bfloat16* bsrc = &g_bt[mat][colBase][0];
    float* outp = mat ? g_hf : g_af;
    const __nv_bfloat16* ahi = g_ahi + (size_t)rowBase * DIM;
    const __nv_bfloat16* alo = g_alo + (size_t)rowBase * DIM;
    int wm = wid >> 1, wn = wid & 1;

    float acc[2][8][4];
#pragma unroll
    for (int mt = 0; mt < 2; mt++)
#pragma unroll
        for (int j = 0; j < 8; j++)
#pragma unroll
            for (int e = 0; e < 4; e++) acc[mt][j][e] = 0.f;

    uint32_t uA0 = s2u(&sA[0][0]), uB0 = s2u(&sB[0][0]);
    const uint32_t bufStride = 128 * 40 * 2;

    auto load = [&](int c, int buf) {
        int seg = c >> 4, kof = (c & 15) * 32;
        const __nv_bfloat16* A = (seg == 2 ? alo : ahi) + kof;
        const __nv_bfloat16* B = bsrc + c * 32;
        uint32_t dA = uA0 + buf * bufStride;
        uint32_t dB = uB0 + buf * bufStride;
#pragma unroll
        for (int i = 0; i < 2; i++) {
            int idx = i * 256 + tid;
            int r = idx >> 2, ch = idx & 3;
            cp16(dA + r * 80 + ch * 16, (const char*)(A + (size_t)r * DIM) + ch * 16);
            cp16(dB + r * 80 + ch * 16, (const char*)(B + (size_t)r * KP) + ch * 16);
        }
        asm volatile("cp.async.commit_group;" ::: "memory");
    };

    load(0, 0);
    for (int c = 0; c < NCH; c++) {
        int buf = c & 1;
        if (c + 1 < NCH) load(c + 1, buf ^ 1);
        if (c + 1 < NCH)
            asm volatile("cp.async.wait_group 1;" ::: "memory");
        else
            asm volatile("cp.async.wait_group 0;" ::: "memory");
        __syncthreads();

        uint32_t bA = uA0 + buf * bufStride;
        uint32_t bB = uB0 + buf * bufStride;
#pragma unroll
        for (int ks = 0; ks < 2; ks++) {
            uint32_t a[2][4];
#pragma unroll
            for (int mt = 0; mt < 2; mt++) {
                int row = wm * 32 + mt * 16 + (lane & 15);
                int col = ks * 16 + (lane >> 4) * 8;
                ldm4(a[mt][0], a[mt][1], a[mt][2], a[mt][3], bA + (row * 40 + col) * 2);
            }
            uint32_t b[4][4];
#pragma unroll
            for (int p = 0; p < 4; p++) {
                int q = lane >> 3, rr = lane & 7;
                int n = wn * 64 + p * 16 + (q >> 1) * 8 + rr;
                int col = ks * 16 + (q & 1) * 8;
                ldm4(b[p][0], b[p][1], b[p][2], b[p][3], bB + (n * 40 + col) * 2);
            }
#pragma unroll
            for (int mt = 0; mt < 2; mt++)
#pragma unroll
                for (int j = 0; j < 8; j++)
                    mma16816(acc[mt][j], a[mt][0], a[mt][1], a[mt][2], a[mt][3],
                             b[j >> 1][(j & 1) * 2], b[j >> 1][(j & 1) * 2 + 1]);
        }
        __syncthreads();
    }

    // epilogue: C fragments straight to global (float2, full 32B sectors)
    int g = lane >> 2, tq = lane & 3;
#pragma unroll
    for (int mt = 0; mt < 2; mt++) {
        int r0 = rowBase + wm * 32 + mt * 16 + g;
#pragma unroll
        for (int j = 0; j < 8; j++) {
            int cc = colBase + wn * 64 + j * 8 + tq * 2;
            if (r0 < MPTS)
                *(float2*)&outp[(size_t)r0 * DIM + cc] =
                    make_float2(acc[mt][j][0], acc[mt][j][1]);
            if (r0 + 8 < MPTS)
                *(float2*)&outp[(size_t)(r0 + 8) * DIM + cc] =
                    make_float2(acc[mt][j][2], acc[mt][j][3]);
        }
    }
}

// ---------------- K1: LSTM gates ----------------
__global__ void k_gates(const float* __restrict__ w_ih, const float* __restrict__ w_hh,
                        const float* __restrict__ b_ih, const float* __restrict__ b_hh) {
    int tid = threadIdx.x;
    if (blockIdx.x == 0) { g_qh[tid] = 0.f; g_qh[tid + 256] = 0.f; }
    int w = blockIdx.x * 8 + (tid >> 5);
    int lane = tid & 31;
    const float* wi = w_ih + (size_t)w * DIM;
    const float* wh = w_hh + (size_t)w * HID;
    float s = 0.f;
#pragma unroll 4
    for (int k = lane; k < DIM; k += 32) s += wi[k] * g_x[k] + wh[k] * g_h[k];
#pragma unroll
    for (int o = 16; o; o >>= 1) s += __shfl_xor_sync(0xffffffffu, s, o);
    if (!lane) g_gates[w] = s + b_ih[w] + b_hh[w];
}

// ---------------- K2: h,c update + qh = h @ hop_wq (64 blocks) ----------------
__global__ void __launch_bounds__(256) k_qh(const float* __restrict__ hop_wq, int t) {
    __shared__ float sh[8];
    int tid = threadIdx.x;
    int kb = blockIdx.x * 8;
    const float* cold = g_cbuf[t & 1];
    float* cnew = g_cbuf[(t + 1) & 1];
    if (blockIdx.x == 0) {
        for (int j = tid; j < HID; j += 256) {
            float gi = sigm(g_gates[j]);
            float gf = sigm(g_gates[HID + j]);
            float gg = tanhe(g_gates[2 * HID + j]);
            float go = sigm(g_gates[3 * HID + j]);
            float c = gf * cold[j] + gi * gg;
            g_h[j] = go * tanhe(c);
            cnew[j] = c;
        }
    }
    if (tid < 8) {
        int j = kb + tid;
        float gi = sigm(g_gates[j]);
        float gf = sigm(g_gates[HID + j]);
        float gg = tanhe(g_gates[2 * HID + j]);
        float go = sigm(g_gates[3 * HID + j]);
        float c = gf * cold[j] + gi * gg;
        sh[tid] = go * tanhe(c);
    }
    __syncthreads();
    float a0 = 0.f, a1 = 0.f;
#pragma unroll
    for (int kk = 0; kk < 8; kk++) {
        float hv = sh[kk];
        const float* wr = hop_wq + (size_t)(kb + kk) * HID;
        a0 += hv * wr[tid];
        a1 += hv * wr[tid + 256];
    }
    atomicAdd(&g_qh[tid], a0);
    atomicAdd(&g_qh[tid + 256], a1);
}

// ---------------- K3: hop pass ----------------
__global__ void __launch_bounds__(256) k_hop(const float* __restrict__ hop_v) {
    int tid = threadIdx.x, wz = tid >> 5, lane = tid & 31;
    if (blockIdx.x == 0) { g_ba[tid] = 0.f; g_ba[tid + 256] = 0.f; }
    int gw = blockIdx.x * 8 + wz;
    const int tot = NBP * 8;

    float q0[16], v0[16];
#pragma unroll
    for (int r = 0; r < 4; r++) {
        float4 qq = *(const float4*)&g_qh[r * 128 + lane * 4];
        float4 vv = *(const float4*)&hop_v[r * 128 + lane * 4];
        q0[r*4+0]=qq.x; q0[r*4+1]=qq.y; q0[r*4+2]=qq.z; q0[r*4+3]=qq.w;
        v0[r*4+0]=vv.x; v0[r*4+1]=vv.y; v0[r*4+2]=vv.z; v0[r*4+3]=vv.w;
    }
    float mx = NEGINF, sw = 0.f, acc[16];
#pragma unroll
    for (int i = 0; i < 16; i++) acc[i] = 0.f;

    for (int m = gw; m < MPTS; m += tot) {
        const float4* rp = (const float4*)(g_hf + (size_t)m * DIM);
        float vals[16]; float sp = 0.f;
#pragma unroll
        for (int r = 0; r < 4; r++) {
            float4 f4 = rp[r * 32 + lane];
            vals[r*4+0]=f4.x; vals[r*4+1]=f4.y; vals[r*4+2]=f4.z; vals[r*4+3]=f4.w;
            sp += tanha(f4.x + q0[r*4+0]) * v0[r*4+0];
            sp += tanha(f4.y + q0[r*4+1]) * v0[r*4+1];
            sp += tanha(f4.z + q0[r*4+2]) * v0[r*4+2];
            sp += tanha(f4.w + q0[r*4+3]) * v0[r*4+3];
        }
#pragma unroll
        for (int o = 16; o; o >>= 1) sp += __shfl_xor_sync(0xffffffffu, sp, o);
        if (sp > mx) {
            float f = __expf(mx - sp);
            sw *= f;
#pragma unroll
            for (int i = 0; i < 16; i++) acc[i] *= f;
            mx = sp;
        }
        float wgt = __expf(sp - mx);
        sw += wgt;
#pragma unroll
        for (int i = 0; i < 16; i++) acc[i] += wgt * vals[i];
    }
    __shared__ float smx[8], ssw[8], sacc[8][512];
#pragma unroll
    for (int r = 0; r < 4; r++)
#pragma unroll
        for (int s = 0; s < 4; s++) sacc[wz][r * 128 + lane * 4 + s] = acc[r * 4 + s];
    if (!lane) { smx[wz] = mx; ssw[wz] = sw; }
    __syncthreads();

    float M = smx[0];
#pragma unroll
    for (int w = 1; w < 8; w++) M = fmaxf(M, smx[w]);
    for (int c = tid; c < 512; c += 256) {
        float a = 0.f;
#pragma unroll
        for (int w = 0; w < 8; w++) a += sacc[w][c] * __expf(smx[w] - M);
        g_hpart[blockIdx.x][2 + c] = a;
    }
    if (tid == 0) {
        float W = 0.f;
#pragma unroll
        for (int w = 0; w < 8; w++) W += ssw[w] * __expf(smx[w] - M);
        g_hpart[blockIdx.x][0] = M;
        g_hpart[blockIdx.x][1] = W;
    }
}

// ---------------- K4: reduce hop partials + bias GEMV (64 blocks) ----------------
__global__ void __launch_bounds__(256) k_bias(const float* __restrict__ attn_wq) {
    __shared__ float red[256];
    __shared__ float qn[8];
    int tid = threadIdx.x;
    int kb = blockIdx.x * 8;

    float m = NEGINF;
    for (int b = tid; b < NBP; b += 256) m = fmaxf(m, g_hpart[b][0]);
    red[tid] = m; __syncthreads();
    for (int o = 128; o; o >>= 1) { if (tid < o) red[tid] = fmaxf(red[tid], red[tid + o]); __syncthreads(); }
    float M = red[0]; __syncthreads();

    float wsum = 0.f;
    for (int b = tid; b < NBP; b += 256) wsum += __expf(g_hpart[b][0] - M) * g_hpart[b][1];
    red[tid] = wsum; __syncthreads();
    for (int o = 128; o; o >>= 1) { if (tid < o) red[tid] += red[tid + o]; __syncthreads(); }
    float W = red[0]; __syncthreads();

    {
        int g = tid >> 5, l = tid & 31;
        int k = kb + g;
        float a = 0.f;
        for (int b = l; b < NBP; b += 32)
            a += __expf(g_hpart[b][0] - M) * g_hpart[b][2 + k];
#pragma unroll
        for (int o = 16; o; o >>= 1) a += __shfl_xor_sync(0xffffffffu, a, o);
        if (l == 0) qn[g] = __fdividef(a, W);
    }
    __syncthreads();

    float a0 = 0.f, a1 = 0.f;
#pragma unroll
    for (int kk = 0; kk < 8; kk++) {
        float q = qn[kk];
        const float* wr = attn_wq + (size_t)(kb + kk) * HID;
        a0 += q * wr[tid];
        a1 += q * wr[tid + 256];
    }
    atomicAdd(&g_ba[tid], a0);
    atomicAdd(&g_ba[tid + 256], a1);
}

// ---------------- K5: attn pass ----------------
__global__ void __launch_bounds__(256) k_attn(const float* __restrict__ attn_v,
                                              const float* __restrict__ gumbel, int t) {
    int tid = threadIdx.x, wz = tid >> 5, lane = tid & 31;
    int gw = blockIdx.x * 8 + wz;
    const int tot = NBP * 8;
    const float* gum = gumbel + (size_t)t * MPTS;

    float b0[16], v0[16];
#pragma unroll
    for (int r = 0; r < 4; r++) {
        float4 bb = *(const float4*)&g_ba[r * 128 + lane * 4];
        float4 vv = *(const float4*)&attn_v[r * 128 + lane * 4];
        b0[r*4+0]=bb.x; b0[r*4+1]=bb.y; b0[r*4+2]=bb.z; b0[r*4+3]=bb.w;
        v0[r*4+0]=vv.x; v0[r*4+1]=vv.y; v0[r*4+2]=vv.z; v0[r*4+3]=vv.w;
    }
    float mxs = NEGINF, ssum = 0.f, best = NEGINF;
    int bidx = 0x7fffffff;

    for (int m = gw; m < MPTS; m += tot) {
        const float4* rp = (const float4*)(g_af + (size_t)m * DIM);
        float sp = 0.f;
#pragma unroll
        for (int r = 0; r < 4; r++) {
            float4 f4 = rp[r * 32 + lane];
            sp += tanha(f4.x + b0[r*4+0]) * v0[r*4+0];
            sp += tanha(f4.y + b0[r*4+1]) * v0[r*4+1];
            sp += tanha(f4.z + b0[r*4+2]) * v0[r*4+2];
            sp += tanha(f4.w + b0[r*4+3]) * v0[r*4+3];
        }
#pragma unroll
        for (int o = 16; o; o >>= 1) sp += __shfl_xor_sync(0xffffffffu, sp, o);
        float sc = g_sel[m] ? -1e18f : sp;
        if (sc > mxs) { ssum *= __expf(mxs - sc); mxs = sc; }
        ssum += __expf(sc - mxs);
        float tv = sc + gum[m];
        if (tv > best || (tv == best && m < bidx)) { best = tv; bidx = m; }
    }
    __shared__ float sb[8]; __shared__ int si[8];
    __shared__ float sm[8]; __shared__ float ss[8];
    if (!lane) { sb[wz] = best; si[wz] = bidx; sm[wz] = mxs; ss[wz] = ssum; }
    __syncthreads();
    if (tid == 0) {
        float B = sb[0]; int I = si[0];
        float M2 = sm[0], S = ss[0];
#pragma unroll
        for (int w = 1; w < 8; w++) {
            if (sb[w] > B || (sb[w] == B && si[w] < I)) { B = sb[w]; I = si[w]; }
            float m2 = sm[w], s2 = ss[w];
            if (m2 > M2) { S = S * __expf(M2 - m2) + s2; M2 = m2; }
            else S += s2 * __expf(m2 - M2);
        }
        g_apart[blockIdx.x][0] = B; g_apart[blockIdx.x][1] = M2;
        g_apart[blockIdx.x][2] = S; g_aidx[blockIdx.x] = I;
    }
}

// ---------------- K6: final select + state update ----------------
__global__ void k_final(const float* __restrict__ attn_mem, const float* __restrict__ stop,
                        const float* __restrict__ gumbel, float* __restrict__ out, int t) {
    __shared__ float sb[512]; __shared__ int si[512];
    __shared__ float sm[512]; __shared__ float ss[512];
    __shared__ int s_out, s_nd;
    int tid = threadIdx.x;
    float B = NEGINF; int I = 0x7fffffff; float M = NEGINF; float S = 0.f;
    if (tid < NBP) { B = g_apart[tid][0]; M = g_apart[tid][1]; S = g_apart[tid][2]; I = g_aidx[tid]; }
    sb[tid] = B; si[tid] = I; sm[tid] = M; ss[tid] = S;
    __syncthreads();
    for (int o = 256; o; o >>= 1) {
        if (tid < o) {
            if (sb[tid + o] > sb[tid] || (sb[tid + o] == sb[tid] && si[tid + o] < si[tid])) {
                sb[tid] = sb[tid + o]; si[tid] = si[tid + o];
            }
            float m1 = sm[tid], s1 = ss[tid];
            float m2 = sm[tid + o], s2 = ss[tid + o];
            float Mn = fmaxf(m1, m2);
            float Sn = 0.f;
            if (s1 > 0.f) Sn += s1 * __expf(m1 - Mn);
            if (s2 > 0.f) Sn += s2 * __expf(m2 - Mn);
            sm[tid] = Mn; ss[tid] = Sn;
        }
        __syncthreads();
    }
    if (tid == 0) {
        int done = g_done;
        int o_ = si[0];
        float sc = sb[0] - gumbel[(size_t)t * MPTS + o_];
        float lse = sm[0] + logf(ss[0]);
        float logp = sc - lse;
        out[t]          = done ? (float)NPTS : (float)o_;
        out[TSTEPS + t] = done ? 0.f : logp;
        if (!done) g_sel[o_] = 1;
        int nd = done || (o_ == NPTS);
        g_done = nd;
        s_out = o_; s_nd = nd;
    }
    __syncthreads();
    if (!s_nd && tid < DIM) {
        int o_ = s_out;
        const float* src = (o_ == NPTS) ? stop : attn_mem + (size_t)o_ * DIM;
        g_x[tid] = src[tid];
    }
}

// ---------------- launch ----------------
extern "C" void kernel_launch(void* const* d_in, const int* in_sizes, int n_in,
                              void* d_out, int out_size) {
    const float* attn_mem = (const float*)d_in[0];
    const float* stop     = (const float*)d_in[1];
    const float* init_h   = (const float*)d_in[2];
    const float* init_c   = (const float*)d_in[3];
    const float* init_i   = (const float*)d_in[4];
    const float* attn_wm  = (const float*)d_in[5];
    const float* attn_wq  = (const float*)d_in[6];
    const float* attn_v   = (const float*)d_in[7];
    const float* hop_wm   = (const float*)d_in[8];
    const float* hop_wq   = (const float*)d_in[9];
    const float* hop_v    = (const float*)d_in[10];
    const float* w_ih     = (const float*)d_in[11];
    const float* w_hh     = (const float*)d_in[12];
    const float* b_ih     = (const float*)d_in[13];
    const float* b_hh     = (const float*)d_in[14];
    const float* gumbel   = (const float*)d_in[15];
    float* out = (float*)d_out;

    k_init<<<(MPTS + 255) / 256, 256>>>(init_h, init_c, init_i);
    k_convA<<<8192, 256>>>(attn_mem, stop);
    k_convB<<<2048, 256>>>(attn_wm, hop_wm);

    dim3 gg(ROWT, 4, 2);
    k_feat_mma<<<gg, 256>>>();

    for (int t = 0; t < TSTEPS; t++) {
        k_gates<<<256, 256>>>(w_ih, w_hh, b_ih, b_hh);
        k_qh<<<64, 256>>>(hop_wq, t);
        k_hop<<<NBP, 256>>>(hop_v);
        k_bias<<<64, 256>>>(attn_wq);
        k_attn<<<NBP, 256>>>(attn_v, gumbel, t);
        k_final<<<1, 512>>>(attn_mem, stop, gumbel, out, t);
    }
}

// round 6
// speedup vs baseline: 2.7030x; 1.0730x over previous
#include <cuda_runtime.h>
#include <cuda_bf16.h>
#include <cuda_fp16.h>
#include <cstdint>

#define NPTS   50000
#define MPTS   50001
#define DIM    512
#define HID    512
#define TSTEPS 16
#define NBP    444
#define NEGINF (__int_as_float(0xff800000))

#define PADM   50048           // 391 * 128
#define ROWT   391
#define KP     1536            // K' = 3 * 512
#define NCH    48              // K' / 32

// ---------------- device scratch ----------------
__device__ __half g_af16[(size_t)MPTS * DIM];      // attn_feat fp16 (51MB)
__device__ __half g_hf16[(size_t)MPTS * DIM];      // hop_feat fp16
__device__ __nv_bfloat16 g_ahi[(size_t)PADM * DIM];
__device__ __nv_bfloat16 g_alo[(size_t)PADM * DIM];
__device__ __nv_bfloat16 g_bt[2][512][KP];         // [mat][n][k'] = [Bhi|Blo|Bhi]
__device__ float g_gates[4 * HID];
__device__ float g_h[HID];
__device__ float g_cbuf[2][HID];
__device__ float g_x[DIM];
__device__ float g_qh[HID];
__device__ float g_ba[HID];
__device__ unsigned char g_sel[MPTS];
__device__ int   g_done;
__device__ int   g_ticket;
__device__ float g_hpart[NBP][514];
__device__ float g_apart[NBP][3];
__device__ int   g_aidx[NBP];

// ---------------- helpers ----------------
__device__ __forceinline__ float tanhe(float x) {
    float e = __expf(2.f * x);
    return 1.f - __fdividef(2.f, e + 1.f);
}
__device__ __forceinline__ float tanha(float x) {
    float y; asm("tanh.approx.f32 %0, %1;" : "=f"(y) : "f"(x)); return y;
}
__device__ __forceinline__ float sigm(float x) {
    return __fdividef(1.f, 1.f + __expf(-x));
}
__device__ __forceinline__ uint32_t s2u(const void* p) {
    uint32_t a;
    asm("{ .reg .u64 t; cvta.to.shared.u64 t, %1; cvt.u32.u64 %0, t; }" : "=r"(a) : "l"(p));
    return a;
}
__device__ __forceinline__ void cp16(uint32_t dst, const void* src) {
    asm volatile("cp.async.cg.shared.global [%0], [%1], 16;" :: "r"(dst), "l"(src));
}
__device__ __forceinline__ void ldm4(uint32_t& r0, uint32_t& r1, uint32_t& r2, uint32_t& r3,
                                     uint32_t addr) {
    asm volatile("ldmatrix.sync.aligned.m8n8.x4.shared.b16 {%0,%1,%2,%3}, [%4];"
                 : "=r"(r0), "=r"(r1), "=r"(r2), "=r"(r3) : "r"(addr));
}
__device__ __forceinline__ void mma16816(float* c, uint32_t a0, uint32_t a1, uint32_t a2,
                                         uint32_t a3, uint32_t b0, uint32_t b1) {
    asm volatile(
        "mma.sync.aligned.m16n8k16.row.col.f32.bf16.bf16.f32 "
        "{%0,%1,%2,%3},{%4,%5,%6,%7},{%8,%9},{%0,%1,%2,%3};"
        : "+f"(c[0]), "+f"(c[1]), "+f"(c[2]), "+f"(c[3])
        : "r"(a0), "r"(a1), "r"(a2), "r"(a3), "r"(b0), "r"(b1));
}
__device__ __forceinline__ unsigned pk2(float a, float b) {
    unsigned lo = __bfloat16_as_ushort(__float2bfloat16(a));
    unsigned hi = __bfloat16_as_ushort(__float2bfloat16(b));
    return lo | (hi << 16);
}

// ---------------- K0: state init ----------------
__global__ void k_init(const float* __restrict__ ih, const float* __restrict__ ic,
                       const float* __restrict__ ii) {
    int i = blockIdx.x * blockDim.x + threadIdx.x;
    if (i < MPTS) g_sel[i] = 0;
    if (i < HID) { g_h[i] = ih[i]; g_cbuf[0][i] = ic[i]; g_x[i] = ii[i]; }
    if (i == 0) { g_done = 0; g_ticket = 0; }
}

// ---------------- convert A: mem(+stop,+pad) -> bf16 hi/lo ----------------
__global__ void k_convA(const float* __restrict__ mem, const float* __restrict__ stop) {
    const int total4 = PADM * DIM / 4;
    for (int i = blockIdx.x * blockDim.x + threadIdx.x; i < total4;
         i += gridDim.x * blockDim.x) {
        int row = i >> 7;
        int c4 = (i & 127) * 4;
        float4 v;
        if (row < NPTS)       v = *(const float4*)&mem[(size_t)row * DIM + c4];
        else if (row == NPTS) v = *(const float4*)&stop[c4];
        else                  v = make_float4(0.f, 0.f, 0.f, 0.f);
        float h0 = __bfloat162float(__float2bfloat16(v.x));
        float h1 = __bfloat162float(__float2bfloat16(v.y));
        float h2 = __bfloat162float(__float2bfloat16(v.z));
        float h3 = __bfloat162float(__float2bfloat16(v.w));
        uint2 ph, pl;
        ph.x = pk2(v.x, v.y); ph.y = pk2(v.z, v.w);
        pl.x = pk2(v.x - h0, v.y - h1); pl.y = pk2(v.z - h2, v.w - h3);
        ((uint2*)g_ahi)[i] = ph;
        ((uint2*)g_alo)[i] = pl;
    }
}

// ---------------- convert B: wm[k][n] -> g_bt[mat][n][k'] ----------------
__global__ void k_convB(const float* __restrict__ attn_wm, const float* __restrict__ hop_wm) {
    int id = blockIdx.x * blockDim.x + threadIdx.x;
    if (id >= 2 * 512 * 512) return;
    int w = id >> 18;
    int r = id & 262143;
    int n = r >> 9;
    int k = r & 511;
    const float* src = w ? hop_wm : attn_wm;
    float x = src[(size_t)k * 512 + n];
    __nv_bfloat16 hi = __float2bfloat16(x);
    __nv_bfloat16 lo = __float2bfloat16(x - __bfloat162float(hi));
    g_bt[w][n][k]        = hi;
    g_bt[w][n][512 + k]  = lo;
    g_bt[w][n][1024 + k] = hi;
}

// ---------------- GEMM: bf16-split mma.sync, 3-stage pipeline, fp16 out ----------------
// CTA 128x128, 8 warps 4m x 2n, warp tile 32x64, K-chunk 32, smem rows 40 bf16.
#define STG_B   20480          // bytes per stage (A 10240 + B 10240)
__global__ void __launch_bounds__(256, 2) k_feat_mma() {
    extern __shared__ __align__(16) char dsm[];
    uint32_t u0 = s2u(dsm);
    int tid = threadIdx.x, wid = tid >> 5, lane = tid & 31;
    int rowBase = blockIdx.x * 128;
    int colBase = blockIdx.y * 128;
    int mat = blockIdx.z;
    const __nv_bfloat16* bsrc = &g_bt[mat][colBase][0];
    __half* outp = mat ? g_hf16 : g_af16;
    const __nv_bfloat16* ahi = g_ahi + (size_t)rowBase * DIM;
    const __nv_bfloat16* alo = g_alo + (size_t)rowBase * DIM;
    int wm = wid >> 1, wn = wid & 1;

    float acc[2][8][4];
#pragma unroll
    for (int mt = 0; mt < 2; mt++)
#pragma unroll
        for (int j = 0; j < 8; j++)
#pragma unroll
            for (int e = 0; e < 4; e++) acc[mt][j][e] = 0.f;

    auto load = [&](int c, int s) {
        int seg = c >> 4, kof = (c & 15) * 32;
        const __nv_bfloat16* A = (seg == 2 ? alo : ahi) + kof;
        const __nv_bfloat16* B = bsrc + c * 32;
        uint32_t dA = u0 + s * STG_B;
        uint32_t dB = dA + 10240;
#pragma unroll
        for (int i = 0; i < 2; i++) {
            int idx = i * 256 + tid;
            int r = idx >> 2, ch = idx & 3;
            cp16(dA + r * 80 + ch * 16, (const char*)(A + (size_t)r * DIM) + ch * 16);
            cp16(dB + r * 80 + ch * 16, (const char*)(B + (size_t)r * KP) + ch * 16);
        }
        asm volatile("cp.async.commit_group;" ::: "memory");
    };

    load(0, 0);
    load(1, 1);
    for (int c = 0; c < NCH; c++) {
        if (c == NCH - 1)
            asm volatile("cp.async.wait_group 0;" ::: "memory");
        else
            asm volatile("cp.async.wait_group 1;" ::: "memory");
        __syncthreads();
        if (c + 2 < NCH) load(c + 2, (c + 2) % 3);

        uint32_t bA = u0 + (c % 3) * STG_B;
        uint32_t bB = bA + 10240;
#pragma unroll
        for (int ks = 0; ks < 2; ks++) {
            uint32_t a[2][4];
#pragma unroll
            for (int mt = 0; mt < 2; mt++) {
                int row = wm * 32 + mt * 16 + (lane & 15);
                int col = ks * 16 + (lane >> 4) * 8;
                ldm4(a[mt][0], a[mt][1], a[mt][2], a[mt][3], bA + (row * 40 + col) * 2);
            }
            uint32_t b[4][4];
#pragma unroll
            for (int p = 0; p < 4; p++) {
                int q = lane >> 3, rr = lane & 7;
                int n = wn * 64 + p * 16 + (q >> 1) * 8 + rr;
                int col = ks * 16 + (q & 1) * 8;
                ldm4(b[p][0], b[p][1], b[p][2], b[p][3], bB + (n * 40 + col) * 2);
            }
#pragma unroll
            for (int mt = 0; mt < 2; mt++)
#pragma unroll
                for (int j = 0; j < 8; j++)
                    mma16816(acc[mt][j], a[mt][0], a[mt][1], a[mt][2], a[mt][3],
                             b[j >> 1][(j & 1) * 2], b[j >> 1][(j & 1) * 2 + 1]);
        }
    }

    // epilogue: fp32 acc -> half2 -> global
    int g = lane >> 2, tq = lane & 3;
#pragma unroll
    for (int mt = 0; mt < 2; mt++) {
        int r0 = rowBase + wm * 32 + mt * 16 + g;
#pragma unroll
        for (int j = 0; j < 8; j++) {
            int cc = colBase + wn * 64 + j * 8 + tq * 2;
            if (r0 < MPTS)
                *(__half2*)&outp[(size_t)r0 * DIM + cc] =
                    __floats2half2_rn(acc[mt][j][0], acc[mt][j][1]);
            if (r0 + 8 < MPTS)
                *(__half2*)&outp[(size_t)(r0 + 8) * DIM + cc] =
                    __floats2half2_rn(acc[mt][j][2], acc[mt][j][3]);
        }
    }
}

// ---------------- K1: LSTM gates ----------------
__global__ void k_gates(const float* __restrict__ w_ih, const float* __restrict__ w_hh,
                        const float* __restrict__ b_ih, const float* __restrict__ b_hh) {
    int tid = threadIdx.x;
    if (blockIdx.x == 0) { g_qh[tid] = 0.f; g_qh[tid + 256] = 0.f; }
    int w = blockIdx.x * 8 + (tid >> 5);
    int lane = tid & 31;
    const float* wi = w_ih + (size_t)w * DIM;
    const float* wh = w_hh + (size_t)w * HID;
    float s = 0.f;
#pragma unroll 4
    for (int k = lane; k < DIM; k += 32) s += wi[k] * g_x[k] + wh[k] * g_h[k];
#pragma unroll
    for (int o = 16; o; o >>= 1) s += __shfl_xor_sync(0xffffffffu, s, o);
    if (!lane) g_gates[w] = s + b_ih[w] + b_hh[w];
}

// ---------------- K2: h,c update + qh = h @ hop_wq (64 blocks) ----------------
__global__ void __launch_bounds__(256) k_qh(const float* __restrict__ hop_wq, int t) {
    __shared__ float sh[8];
    int tid = threadIdx.x;
    int kb = blockIdx.x * 8;
    const float* cold = g_cbuf[t & 1];
    float* cnew = g_cbuf[(t + 1) & 1];
    if (blockIdx.x == 0) {
        for (int j = tid; j < HID; j += 256) {
            float gi = sigm(g_gates[j]);
            float gf = sigm(g_gates[HID + j]);
            float gg = tanhe(g_gates[2 * HID + j]);
            float go = sigm(g_gates[3 * HID + j]);
            float c = gf * cold[j] + gi * gg;
            g_h[j] = go * tanhe(c);
            cnew[j] = c;
        }
    }
    if (tid < 8) {
        int j = kb + tid;
        float gi = sigm(g_gates[j]);
        float gf = sigm(g_gates[HID + j]);
        float gg = tanhe(g_gates[2 * HID + j]);
        float go = sigm(g_gates[3 * HID + j]);
        float c = gf * cold[j] + gi * gg;
        sh[tid] = go * tanhe(c);
    }
    __syncthreads();
    float a0 = 0.f, a1 = 0.f;
#pragma unroll
    for (int kk = 0; kk < 8; kk++) {
        float hv = sh[kk];
        const float* wr = hop_wq + (size_t)(kb + kk) * HID;
        a0 += hv * wr[tid];
        a1 += hv * wr[tid + 256];
    }
    atomicAdd(&g_qh[tid], a0);
    atomicAdd(&g_qh[tid + 256], a1);
}

// ---------------- K3: hop pass (fp16 features) ----------------
// lane covers cols [lane*8, lane*8+8) and [256+lane*8, 256+lane*8+8)
__global__ void __launch_bounds__(256) k_hop(const float* __restrict__ hop_v) {
    int tid = threadIdx.x, wz = tid >> 5, lane = tid & 31;
    if (blockIdx.x == 0) { g_ba[tid] = 0.f; g_ba[tid + 256] = 0.f; }
    int gw = blockIdx.x * 8 + wz;
    const int tot = NBP * 8;

    float q0[16], v0[16];
    {
        float4 a = *(const float4*)&g_qh[lane * 8];
        float4 b = *(const float4*)&g_qh[lane * 8 + 4];
        float4 c = *(const float4*)&g_qh[256 + lane * 8];
        float4 d = *(const float4*)&g_qh[256 + lane * 8 + 4];
        q0[0]=a.x;q0[1]=a.y;q0[2]=a.z;q0[3]=a.w; q0[4]=b.x;q0[5]=b.y;q0[6]=b.z;q0[7]=b.w;
        q0[8]=c.x;q0[9]=c.y;q0[10]=c.z;q0[11]=c.w; q0[12]=d.x;q0[13]=d.y;q0[14]=d.z;q0[15]=d.w;
        a = *(const float4*)&hop_v[lane * 8];
        b = *(const float4*)&hop_v[lane * 8 + 4];
        c = *(const float4*)&hop_v[256 + lane * 8];
        d = *(const float4*)&hop_v[256 + lane * 8 + 4];
        v0[0]=a.x;v0[1]=a.y;v0[2]=a.z;v0[3]=a.w; v0[4]=b.x;v0[5]=b.y;v0[6]=b.z;v0[7]=b.w;
        v0[8]=c.x;v0[9]=c.y;v0[10]=c.z;v0[11]=c.w; v0[12]=d.x;v0[13]=d.y;v0[14]=d.z;v0[15]=d.w;
    }
    float mx = NEGINF, sw = 0.f, acc[16];
#pragma unroll
    for (int i = 0; i < 16; i++) acc[i] = 0.f;

    for (int m = gw; m < MPTS; m += tot) {
        const uint4* rp = (const uint4*)(g_hf16 + (size_t)m * DIM);
        uint4 p0 = rp[lane];
        uint4 p1 = rp[32 + lane];
        float vals[16];
#pragma unroll
        for (int k = 0; k < 4; k++) {
            float2 f0 = __half22float2(((const __half2*)&p0)[k]);
            float2 f1 = __half22float2(((const __half2*)&p1)[k]);
            vals[2*k] = f0.x; vals[2*k+1] = f0.y;
            vals[8+2*k] = f1.x; vals[8+2*k+1] = f1.y;
        }
        float sp = 0.f;
#pragma unroll
        for (int i = 0; i < 16; i++) sp += tanha(vals[i] + q0[i]) * v0[i];
#pragma unroll
        for (int o = 16; o; o >>= 1) sp += __shfl_xor_sync(0xffffffffu, sp, o);
        if (sp > mx) {
            float f = __expf(mx - sp);
            sw *= f;
#pragma unroll
            for (int i = 0; i < 16; i++) acc[i] *= f;
            mx = sp;
        }
        float wgt = __expf(sp - mx);
        sw += wgt;
#pragma unroll
        for (int i = 0; i < 16; i++) acc[i] += wgt * vals[i];
    }
    __shared__ float smx[8], ssw[8], sacc[8][512];
#pragma unroll
    for (int s = 0; s < 8; s++) {
        sacc[wz][lane * 8 + s] = acc[s];
        sacc[wz][256 + lane * 8 + s] = acc[8 + s];
    }
    if (!lane) { smx[wz] = mx; ssw[wz] = sw; }
    __syncthreads();

    float M = smx[0];
#pragma unroll
    for (int w = 1; w < 8; w++) M = fmaxf(M, smx[w]);
    for (int c = tid; c < 512; c += 256) {
        float a = 0.f;
#pragma unroll
        for (int w = 0; w < 8; w++) a += sacc[w][c] * __expf(smx[w] - M);
        g_hpart[blockIdx.x][2 + c] = a;
    }
    if (tid == 0) {
        float W = 0.f;
#pragma unroll
        for (int w = 0; w < 8; w++) W += ssw[w] * __expf(smx[w] - M);
        g_hpart[blockIdx.x][0] = M;
        g_hpart[blockIdx.x][1] = W;
    }
}

// ---------------- K4: reduce hop partials + bias GEMV (64 blocks) ----------------
__global__ void __launch_bounds__(256) k_bias(const float* __restrict__ attn_wq) {
    __shared__ float red[256];
    __shared__ float qn[8];
    int tid = threadIdx.x;
    int kb = blockIdx.x * 8;

    float m = NEGINF;
    for (int b = tid; b < NBP; b += 256) m = fmaxf(m, g_hpart[b][0]);
    red[tid] = m; __syncthreads();
    for (int o = 128; o; o >>= 1) { if (tid < o) red[tid] = fmaxf(red[tid], red[tid + o]); __syncthreads(); }
    float M = red[0]; __syncthreads();

    float wsum = 0.f;
    for (int b = tid; b < NBP; b += 256) wsum += __expf(g_hpart[b][0] - M) * g_hpart[b][1];
    red[tid] = wsum; __syncthreads();
    for (int o = 128; o; o >>= 1) { if (tid < o) red[tid] += red[tid + o]; __syncthreads(); }
    float W = red[0]; __syncthreads();

    {
        int g = tid >> 5, l = tid & 31;
        int k = kb + g;
        float a = 0.f;
        for (int b = l; b < NBP; b += 32)
            a += __expf(g_hpart[b][0] - M) * g_hpart[b][2 + k];
#pragma unroll
        for (int o = 16; o; o >>= 1) a += __shfl_xor_sync(0xffffffffu, a, o);
        if (l == 0) qn[g] = __fdividef(a, W);
    }
    __syncthreads();

    float a0 = 0.f, a1 = 0.f;
#pragma unroll
    for (int kk = 0; kk < 8; kk++) {
        float q = qn[kk];
        const float* wr = attn_wq + (size_t)(kb + kk) * HID;
        a0 += q * wr[tid];
        a1 += q * wr[tid + 256];
    }
    atomicAdd(&g_ba[tid], a0);
    atomicAdd(&g_ba[tid + 256], a1);
}

// ---------------- K5: attn pass + fused final (ticket) ----------------
__global__ void __launch_bounds__(256) k_attn(const float* __restrict__ attn_v,
                                              const float* __restrict__ gumbel,
                                              const float* __restrict__ attn_mem,
                                              const float* __restrict__ stop,
                                              float* __restrict__ out, int t) {
    int tid = threadIdx.x, wz = tid >> 5, lane = tid & 31;
    int gw = blockIdx.x * 8 + wz;
    const int tot = NBP * 8;
    const float* gum = gumbel + (size_t)t * MPTS;

    float b0[16], v0[16];
    {
        float4 a = *(const float4*)&g_ba[lane * 8];
        float4 b = *(const float4*)&g_ba[lane * 8 + 4];
        float4 c = *(const float4*)&g_ba[256 + lane * 8];
        float4 d = *(const float4*)&g_ba[256 + lane * 8 + 4];
        b0[0]=a.x;b0[1]=a.y;b0[2]=a.z;b0[3]=a.w; b0[4]=b.x;b0[5]=b.y;b0[6]=b.z;b0[7]=b.w;
        b0[8]=c.x;b0[9]=c.y;b0[10]=c.z;b0[11]=c.w; b0[12]=d.x;b0[13]=d.y;b0[14]=d.z;b0[15]=d.w;
        a = *(const float4*)&attn_v[lane * 8];
        b = *(const float4*)&attn_v[lane * 8 + 4];
        c = *(const float4*)&attn_v[256 + lane * 8];
        d = *(const float4*)&attn_v[256 + lane * 8 + 4];
        v0[0]=a.x;v0[1]=a.y;v0[2]=a.z;v0[3]=a.w; v0[4]=b.x;v0[5]=b.y;v0[6]=b.z;v0[7]=b.w;
        v0[8]=c.x;v0[9]=c.y;v0[10]=c.z;v0[11]=c.w; v0[12]=d.x;v0[13]=d.y;v0[14]=d.z;v0[15]=d.w;
    }
    float mxs = NEGINF, ssum = 0.f, best = NEGINF;
    int bidx = 0x7fffffff;

    for (int m = gw; m < MPTS; m += tot) {
        const uint4* rp = (const uint4*)(g_af16 + (size_t)m * DIM);
        uint4 p0 = rp[lane];
        uint4 p1 = rp[32 + lane];
        float sp = 0.f;
#pragma unroll
        for (int k = 0; k < 4; k++) {
            float2 f0 = __half22float2(((const __half2*)&p0)[k]);
            float2 f1 = __half22float2(((const __half2*)&p1)[k]);
            sp += tanha(f0.x + b0[2*k])     * v0[2*k];
            sp += tanha(f0.y + b0[2*k+1])   * v0[2*k+1];
            sp += tanha(f1.x + b0[8+2*k])   * v0[8+2*k];
            sp += tanha(f1.y + b0[8+2*k+1]) * v0[8+2*k+1];
        }
#pragma unroll
        for (int o = 16; o; o >>= 1) sp += __shfl_xor_sync(0xffffffffu, sp, o);
        float sc = g_sel[m] ? -1e18f : sp;
        if (sc > mxs) { ssum *= __expf(mxs - sc); mxs = sc; }
        ssum += __expf(sc - mxs);
        float tv = sc + gum[m];
        if (tv > best || (tv == best && m < bidx)) { best = tv; bidx = m; }
    }
    __shared__ float sb[8]; __shared__ int si[8];
    __shared__ float sm[8]; __shared__ float ss[8];
    if (!lane) { sb[wz] = best; si[wz] = bidx; sm[wz] = mxs; ss[wz] = ssum; }
    __syncthreads();
    if (tid == 0) {
        float B = sb[0]; int I = si[0];
        float M2 = sm[0], S = ss[0];
#pragma unroll
        for (int w = 1; w < 8; w++) {
            if (sb[w] > B || (sb[w] == B && si[w] < I)) { B = sb[w]; I = si[w]; }
            float m2 = sm[w], s2 = ss[w];
            if (m2 > M2) { S = S * __expf(M2 - m2) + s2; M2 = m2; }
            else S += s2 * __expf(m2 - M2);
        }
        g_apart[blockIdx.x][0] = B; g_apart[blockIdx.x][1] = M2;
        g_apart[blockIdx.x][2] = S; g_aidx[blockIdx.x] = I;
    }

    // ---- fused final: last block to finish does the global select ----
    __threadfence();
    __shared__ int islast;
    if (tid == 0) {
        int v = atomicAdd(&g_ticket, 1);
        islast = ((v % NBP) == NBP - 1);
    }
    __syncthreads();
    if (!islast) return;

    __shared__ float fb[256]; __shared__ int fi[256];
    __shared__ float fm[256]; __shared__ float fs[256];
    __shared__ int s_out, s_nd;
    float B = NEGINF; int I = 0x7fffffff; float M = NEGINF; float S = 0.f;
    for (int b = tid; b < NBP; b += 256) {
        float bb = g_apart[b][0]; int ii = g_aidx[b];
        if (bb > B || (bb == B && ii < I)) { B = bb; I = ii; }
        float m2 = g_apart[b][1], s2 = g_apart[b][2];
        if (m2 > M) { S = S * __expf(M - m2) + s2; M = m2; }
        else S += s2 * __expf(m2 - M);
    }
    fb[tid] = B; fi[tid] = I; fm[tid] = M; fs[tid] = S;
    __syncthreads();
    for (int o = 128; o; o >>= 1) {
        if (tid < o) {
            if (fb[tid + o] > fb[tid] || (fb[tid + o] == fb[tid] && fi[tid + o] < fi[tid])) {
                fb[tid] = fb[tid + o]; fi[tid] = fi[tid + o];
            }
            float m1 = fm[tid], s1 = fs[tid];
            float m2 = fm[tid + o], s2 = fs[tid + o];
            float Mn = fmaxf(m1, m2);
            float Sn = 0.f;
            if (s1 > 0.f) Sn += s1 * __expf(m1 - Mn);
            if (s2 > 0.f) Sn += s2 * __expf(m2 - Mn);
            fm[tid] = Mn; fs[tid] = Sn;
        }
        __syncthreads();
    }
    if (tid == 0) {
        int done = g_done;
        int o_ = fi[0];
        float sc = fb[0] - gum[o_];
        float lse = fm[0] + logf(fs[0]);
        float logp = sc - lse;
        out[t]          = done ? (float)NPTS : (float)o_;
        out[TSTEPS + t] = done ? 0.f : logp;
        if (!done) g_sel[o_] = 1;
        int nd = done || (o_ == NPTS);
        g_done = nd;
        s_out = o_; s_nd = nd;
    }
    __syncthreads();
    if (!s_nd) {
        int o_ = s_out;
        const float* src = (o_ == NPTS) ? stop : attn_mem + (size_t)o_ * DIM;
        g_x[tid] = src[tid];
        g_x[tid + 256] = src[tid + 256];
    }
}

// ---------------- launch ----------------
extern "C" void kernel_launch(void* const* d_in, const int* in_sizes, int n_in,
                              void* d_out, int out_size) {
    const float* attn_mem = (const float*)d_in[0];
    const float* stop     = (const float*)d_in[1];
    const float* init_h   = (const float*)d_in[2];
    const float* init_c   = (const float*)d_in[3];
    const float* init_i   = (const float*)d_in[4];
    const float* attn_wm  = (const float*)d_in[5];
    const float* attn_wq  = (const float*)d_in[6];
    const float* attn_v   = (const float*)d_in[7];
    const float* hop_wm   = (const float*)d_in[8];
    const float* hop_wq   = (const float*)d_in[9];
    const float* hop_v    = (const float*)d_in[10];
    const float* w_ih     = (const float*)d_in[11];
    const float* w_hh     = (const float*)d_in[12];
    const float* b_ih     = (const float*)d_in[13];
    const float* b_hh     = (const float*)d_in[14];
    const float* gumbel   = (const float*)d_in[15];
    float* out = (float*)d_out;

    const int FEAT_SMEM = 3 * STG_B;   // 61440
    cudaFuncSetAttribute(k_feat_mma, cudaFuncAttributeMaxDynamicSharedMemorySize, FEAT_SMEM);

    k_init<<<(MPTS + 255) / 256, 256>>>(init_h, init_c, init_i);
    k_convA<<<8192, 256>>>(attn_mem, stop);
    k_convB<<<2048, 256>>>(attn_wm, hop_wm);

    dim3 gg(ROWT, 4, 2);
    k_feat_mma<<<gg, 256, FEAT_SMEM>>>();

    for (int t = 0; t < TSTEPS; t++) {
        k_gates<<<256, 256>>>(w_ih, w_hh, b_ih, b_hh);
        k_qh<<<64, 256>>>(hop_wq, t);
        k_hop<<<NBP, 256>>>(hop_v);
        k_bias<<<64, 256>>>(attn_wq);
        k_attn<<<NBP, 256>>>(attn_v, gumbel, attn_mem, stop, out, t);
    }
}

// round 7
// speedup vs baseline: 3.1106x; 1.1508x over previous
#include <cuda_runtime.h>
#include <cuda_fp16.h>
#include <cstdint>

#define NPTS   50000
#define MPTS   50001
#define DIM    512
#define HID    512
#define TSTEPS 16
#define NBP    444
#define NEGINF (__int_as_float(0xff800000))

#define PADM   50048           // 391 * 128
#define ROWT   391
#define NCH    32              // K' = 1024, 32-wide chunks

// ---------------- device scratch ----------------
__device__ __half g_af16[(size_t)MPTS * DIM];      // attn_feat fp16
__device__ __half g_hf16[(size_t)MPTS * DIM];      // hop_feat fp16
__device__ __half g_ahi[(size_t)PADM * DIM];       // A hi (fp16)
__device__ __half g_alo[(size_t)PADM * DIM];       // A residual (fp16)
__device__ __half g_bt[2][512][512];               // [mat][n][k] = Bh (1MB, L2-resident)
__device__ float g_gates[4 * HID];
__device__ float g_h[HID];
__device__ float g_cbuf[2][HID];
__device__ float g_x[DIM];
__device__ float g_qh[HID];
__device__ float g_ba[HID];
__device__ unsigned char g_sel[MPTS];
__device__ int   g_done;
__device__ int   g_ticket;
__device__ float g_hpart[NBP][514];
__device__ float g_apart[NBP][3];
__device__ int   g_aidx[NBP];

// ---------------- helpers ----------------
__device__ __forceinline__ float tanhe(float x) {
    float e = __expf(2.f * x);
    return 1.f - __fdividef(2.f, e + 1.f);
}
__device__ __forceinline__ float tanha(float x) {
    float y; asm("tanh.approx.f32 %0, %1;" : "=f"(y) : "f"(x)); return y;
}
__device__ __forceinline__ float sigm(float x) {
    return __fdividef(1.f, 1.f + __expf(-x));
}
__device__ __forceinline__ uint32_t s2u(const void* p) {
    uint32_t a;
    asm("{ .reg .u64 t; cvta.to.shared.u64 t, %1; cvt.u32.u64 %0, t; }" : "=r"(a) : "l"(p));
    return a;
}
__device__ __forceinline__ void cp16(uint32_t dst, const void* src) {
    asm volatile("cp.async.cg.shared.global [%0], [%1], 16;" :: "r"(dst), "l"(src));
}
__device__ __forceinline__ void ldm4(uint32_t& r0, uint32_t& r1, uint32_t& r2, uint32_t& r3,
                                     uint32_t addr) {
    asm volatile("ldmatrix.sync.aligned.m8n8.x4.shared.b16 {%0,%1,%2,%3}, [%4];"
                 : "=r"(r0), "=r"(r1), "=r"(r2), "=r"(r3) : "r"(addr));
}
__device__ __forceinline__ void mma16816(float* c, uint32_t a0, uint32_t a1, uint32_t a2,
                                         uint32_t a3, uint32_t b0, uint32_t b1) {
    asm volatile(
        "mma.sync.aligned.m16n8k16.row.col.f32.f16.f16.f32 "
        "{%0,%1,%2,%3},{%4,%5,%6,%7},{%8,%9},{%0,%1,%2,%3};"
        : "+f"(c[0]), "+f"(c[1]), "+f"(c[2]), "+f"(c[3])
        : "r"(a0), "r"(a1), "r"(a2), "r"(a3), "r"(b0), "r"(b1));
}
__device__ __forceinline__ unsigned pkh2(float a, float b) {
    __half2 h = __floats2half2_rn(a, b);
    return *(unsigned*)&h;
}

// ---------------- K0: state init ----------------
__global__ void k_init(const float* __restrict__ ih, const float* __restrict__ ic,
                       const float* __restrict__ ii) {
    int i = blockIdx.x * blockDim.x + threadIdx.x;
    if (i < MPTS) g_sel[i] = 0;
    if (i < HID) { g_h[i] = ih[i]; g_cbuf[0][i] = ic[i]; g_x[i] = ii[i]; }
    if (i == 0) { g_done = 0; g_ticket = 0; }
}

// ---------------- convert A: mem(+stop,+pad) -> fp16 hi/lo ----------------
__global__ void k_convA(const float* __restrict__ mem, const float* __restrict__ stop) {
    const int total4 = PADM * DIM / 4;
    for (int i = blockIdx.x * blockDim.x + threadIdx.x; i < total4;
         i += gridDim.x * blockDim.x) {
        int row = i >> 7;
        int c4 = (i & 127) * 4;
        float4 v;
        if (row < NPTS)       v = *(const float4*)&mem[(size_t)row * DIM + c4];
        else if (row == NPTS) v = *(const float4*)&stop[c4];
        else                  v = make_float4(0.f, 0.f, 0.f, 0.f);
        float h0 = __half2float(__float2half_rn(v.x));
        float h1 = __half2float(__float2half_rn(v.y));
        float h2 = __half2float(__float2half_rn(v.z));
        float h3 = __half2float(__float2half_rn(v.w));
        uint2 ph, pl;
        ph.x = pkh2(v.x, v.y); ph.y = pkh2(v.z, v.w);
        pl.x = pkh2(v.x - h0, v.y - h1); pl.y = pkh2(v.z - h2, v.w - h3);
        ((uint2*)g_ahi)[i] = ph;
        ((uint2*)g_alo)[i] = pl;
    }
}

// ---------------- convert B: wm[k][n] -> g_bt[mat][n][k] (fp16) ----------------
__global__ void k_convB(const float* __restrict__ attn_wm, const float* __restrict__ hop_wm) {
    int id = blockIdx.x * blockDim.x + threadIdx.x;
    if (id >= 2 * 512 * 512) return;
    int w = id >> 18;
    int r = id & 262143;
    int n = r >> 9;
    int k = r & 511;
    const float* src = w ? hop_wm : attn_wm;
    g_bt[w][n][k] = __float2half_rn(src[(size_t)k * 512 + n]);
}

// ---------------- GEMM: fp16-split mma.sync, CTA 128x128, K'=1024 ----------------
// grid (8 = colblock*2+mat, 391 = rowtile): x fastest -> 8 CTAs share A stripe (L2).
// 8 warps 4m x 2n, warp tile 32x64, K-chunk 32, 2-stage cp.async, smem rows 40 half.
__global__ void __launch_bounds__(256, 2) k_feat_mma() {
    __shared__ __align__(16) __half sA[2][128 * 40];
    __shared__ __align__(16) __half sB[2][128 * 40];
    int tid = threadIdx.x, wid = tid >> 5, lane = tid & 31;
    int rowBase = blockIdx.y * 128;
    int colBase = (blockIdx.x >> 1) * 128;
    int mat = blockIdx.x & 1;
    const __half* bsrc = &g_bt[mat][colBase][0];
    __half* outp = mat ? g_hf16 : g_af16;
    const __half* ahi = g_ahi + (size_t)rowBase * DIM;
    const __half* alo = g_alo + (size_t)rowBase * DIM;
    int wm = wid >> 1, wn = wid & 1;

    float acc[2][8][4];
#pragma unroll
    for (int mt = 0; mt < 2; mt++)
#pragma unroll
        for (int j = 0; j < 8; j++)
#pragma unroll
            for (int e = 0; e < 4; e++) acc[mt][j][e] = 0.f;

    uint32_t uA0 = s2u(&sA[0][0]), uB0 = s2u(&sB[0][0]);
    const uint32_t bufStride = 128 * 40 * 2;

    auto load = [&](int c, int buf) {
        const __half* A = ((c >> 4) ? alo : ahi) + (c & 15) * 32;
        const __half* B = bsrc + (c & 15) * 32;
        uint32_t dA = uA0 + buf * bufStride;
        uint32_t dB = uB0 + buf * bufStride;
#pragma unroll
        for (int i = 0; i < 2; i++) {
            int idx = i * 256 + tid;
            int r = idx >> 2, ch = idx & 3;
            cp16(dA + r * 80 + ch * 16, (const char*)(A + (size_t)r * DIM) + ch * 16);
            cp16(dB + r * 80 + ch * 16, (const char*)(B + (size_t)r * 512) + ch * 16);
        }
        asm volatile("cp.async.commit_group;" ::: "memory");
    };

    load(0, 0);
    for (int c = 0; c < NCH; c++) {
        int buf = c & 1;
        if (c + 1 < NCH) load(c + 1, buf ^ 1);
        if (c + 1 < NCH)
            asm volatile("cp.async.wait_group 1;" ::: "memory");
        else
            asm volatile("cp.async.wait_group 0;" ::: "memory");
        __syncthreads();

        uint32_t bA = uA0 + buf * bufStride;
        uint32_t bB = uB0 + buf * bufStride;
#pragma unroll
        for (int ks = 0; ks < 2; ks++) {
            uint32_t a[2][4];
#pragma unroll
            for (int mt = 0; mt < 2; mt++) {
                int row = wm * 32 + mt * 16 + (lane & 15);
                int col = ks * 16 + (lane >> 4) * 8;
                ldm4(a[mt][0], a[mt][1], a[mt][2], a[mt][3], bA + (row * 40 + col) * 2);
            }
            uint32_t b[4][4];
#pragma unroll
            for (int p = 0; p < 4; p++) {
                int q = lane >> 3, rr = lane & 7;
                int n = wn * 64 + p * 16 + (q >> 1) * 8 + rr;
                int col = ks * 16 + (q & 1) * 8;
                ldm4(b[p][0], b[p][1], b[p][2], b[p][3], bB + (n * 40 + col) * 2);
            }
#pragma unroll
            for (int mt = 0; mt < 2; mt++)
#pragma unroll
                for (int j = 0; j < 8; j++)
                    mma16816(acc[mt][j], a[mt][0], a[mt][1], a[mt][2], a[mt][3],
                             b[j >> 1][(j & 1) * 2], b[j >> 1][(j & 1) * 2 + 1]);
        }
        __syncthreads();
    }

    // epilogue: fp32 acc -> half2 -> global
    int g = lane >> 2, tq = lane & 3;
#pragma unroll
    for (int mt = 0; mt < 2; mt++) {
        int r0 = rowBase + wm * 32 + mt * 16 + g;
#pragma unroll
        for (int j = 0; j < 8; j++) {
            int cc = colBase + wn * 64 + j * 8 + tq * 2;
            if (r0 < MPTS)
                *(__half2*)&outp[(size_t)r0 * DIM + cc] =
                    __floats2half2_rn(acc[mt][j][0], acc[mt][j][1]);
            if (r0 + 8 < MPTS)
                *(__half2*)&outp[(size_t)(r0 + 8) * DIM + cc] =
                    __floats2half2_rn(acc[mt][j][2], acc[mt][j][3]);
        }
    }
}

// ---------------- K1: LSTM gates ----------------
__global__ void k_gates(const float* __restrict__ w_ih, const float* __restrict__ w_hh,
                        const float* __restrict__ b_ih, const float* __restrict__ b_hh) {
    int tid = threadIdx.x;
    if (blockIdx.x == 0) { g_qh[tid] = 0.f; g_qh[tid + 256] = 0.f; }
    int w = blockIdx.x * 8 + (tid >> 5);
    int lane = tid & 31;
    const float* wi = w_ih + (size_t)w * DIM;
    const float* wh = w_hh + (size_t)w * HID;
    float s = 0.f;
#pragma unroll 4
    for (int k = lane; k < DIM; k += 32) s += wi[k] * g_x[k] + wh[k] * g_h[k];
#pragma unroll
    for (int o = 16; o; o >>= 1) s += __shfl_xor_sync(0xffffffffu, s, o);
    if (!lane) g_gates[w] = s + b_ih[w] + b_hh[w];
}

// ---------------- K2: h,c update + qh = h @ hop_wq (64 blocks) ----------------
__global__ void __launch_bounds__(256) k_qh(const float* __restrict__ hop_wq, int t) {
    __shared__ float sh[8];
    int tid = threadIdx.x;
    int kb = blockIdx.x * 8;
    const float* cold = g_cbuf[t & 1];
    float* cnew = g_cbuf[(t + 1) & 1];
    if (blockIdx.x == 0) {
        for (int j = tid; j < HID; j += 256) {
            float gi = sigm(g_gates[j]);
            float gf = sigm(g_gates[HID + j]);
            float gg = tanhe(g_gates[2 * HID + j]);
            float go = sigm(g_gates[3 * HID + j]);
            float c = gf * cold[j] + gi * gg;
            g_h[j] = go * tanhe(c);
            cnew[j] = c;
        }
    }
    if (tid < 8) {
        int j = kb + tid;
        float gi = sigm(g_gates[j]);
        float gf = sigm(g_gates[HID + j]);
        float gg = tanhe(g_gates[2 * HID + j]);
        float go = sigm(g_gates[3 * HID + j]);
        float c = gf * cold[j] + gi * gg;
        sh[tid] = go * tanhe(c);
    }
    __syncthreads();
    float a0 = 0.f, a1 = 0.f;
#pragma unroll
    for (int kk = 0; kk < 8; kk++) {
        float hv = sh[kk];
        const float* wr = hop_wq + (size_t)(kb + kk) * HID;
        a0 += hv * wr[tid];
        a1 += hv * wr[tid + 256];
    }
    atomicAdd(&g_qh[tid], a0);
    atomicAdd(&g_qh[tid + 256], a1);
}

// ---------------- K3: hop pass (fp16 features) ----------------
__global__ void __launch_bounds__(256) k_hop(const float* __restrict__ hop_v) {
    int tid = threadIdx.x, wz = tid >> 5, lane = tid & 31;
    if (blockIdx.x == 0) { g_ba[tid] = 0.f; g_ba[tid + 256] = 0.f; }
    int gw = blockIdx.x * 8 + wz;
    const int tot = NBP * 8;

    float q0[16], v0[16];
    {
        float4 a = *(const float4*)&g_qh[lane * 8];
        float4 b = *(const float4*)&g_qh[lane * 8 + 4];
        float4 c = *(const float4*)&g_qh[256 + lane * 8];
        float4 d = *(const float4*)&g_qh[256 + lane * 8 + 4];
        q0[0]=a.x;q0[1]=a.y;q0[2]=a.z;q0[3]=a.w; q0[4]=b.x;q0[5]=b.y;q0[6]=b.z;q0[7]=b.w;
        q0[8]=c.x;q0[9]=c.y;q0[10]=c.z;q0[11]=c.w; q0[12]=d.x;q0[13]=d.y;q0[14]=d.z;q0[15]=d.w;
        a = *(const float4*)&hop_v[lane * 8];
        b = *(const float4*)&hop_v[lane * 8 + 4];
        c = *(const float4*)&hop_v[256 + lane * 8];
        d = *(const float4*)&hop_v[256 + lane * 8 + 4];
        v0[0]=a.x;v0[1]=a.y;v0[2]=a.z;v0[3]=a.w; v0[4]=b.x;v0[5]=b.y;v0[6]=b.z;v0[7]=b.w;
        v0[8]=c.x;v0[9]=c.y;v0[10]=c.z;v0[11]=c.w; v0[12]=d.x;v0[13]=d.y;v0[14]=d.z;v0[15]=d.w;
    }
    float mx = NEGINF, sw = 0.f, acc[16];
#pragma unroll
    for (int i = 0; i < 16; i++) acc[i] = 0.f;

    for (int m = gw; m < MPTS; m += tot) {
        const uint4* rp = (const uint4*)(g_hf16 + (size_t)m * DIM);
        uint4 p0 = rp[lane];
        uint4 p1 = rp[32 + lane];
        float vals[16];
#pragma unroll
        for (int k = 0; k < 4; k++) {
            float2 f0 = __half22float2(((const __half2*)&p0)[k]);
            float2 f1 = __half22float2(((const __half2*)&p1)[k]);
            vals[2*k] = f0.x; vals[2*k+1] = f0.y;
            vals[8+2*k] = f1.x; vals[8+2*k+1] = f1.y;
        }
        float sp = 0.f;
#pragma unroll
        for (int i = 0; i < 16; i++) sp += tanha(vals[i] + q0[i]) * v0[i];
#pragma unroll
        for (int o = 16; o; o >>= 1) sp += __shfl_xor_sync(0xffffffffu, sp, o);
        if (sp > mx) {
            float f = __expf(mx - sp);
            sw *= f;
#pragma unroll
            for (int i = 0; i < 16; i++) acc[i] *= f;
            mx = sp;
        }
        float wgt = __expf(sp - mx);
        sw += wgt;
#pragma unroll
        for (int i = 0; i < 16; i++) acc[i] += wgt * vals[i];
    }
    __shared__ float smx[8], ssw[8], sacc[8][512];
#pragma unroll
    for (int s = 0; s < 8; s++) {
        sacc[wz][lane * 8 + s] = acc[s];
        sacc[wz][256 + lane * 8 + s] = acc[8 + s];
    }
    if (!lane) { smx[wz] = mx; ssw[wz] = sw; }
    __syncthreads();

    float M = smx[0];
#pragma unroll
    for (int w = 1; w < 8; w++) M = fmaxf(M, smx[w]);
    for (int c = tid; c < 512; c += 256) {
        float a = 0.f;
#pragma unroll
        for (int w = 0; w < 8; w++) a += sacc[w][c] * __expf(smx[w] - M);
        g_hpart[blockIdx.x][2 + c] = a;
    }
    if (tid == 0) {
        float W = 0.f;
#pragma unroll
        for (int w = 0; w < 8; w++) W += ssw[w] * __expf(smx[w] - M);
        g_hpart[blockIdx.x][0] = M;
        g_hpart[blockIdx.x][1] = W;
    }
}

// ---------------- K4: reduce hop partials + bias GEMV (64 blocks) ----------------
__global__ void __launch_bounds__(256) k_bias(const float* __restrict__ attn_wq) {
    __shared__ float red[256];
    __shared__ float qn[8];
    int tid = threadIdx.x;
    int kb = blockIdx.x * 8;

    float m = NEGINF;
    for (int b = tid; b < NBP; b += 256) m = fmaxf(m, g_hpart[b][0]);
    red[tid] = m; __syncthreads();
    for (int o = 128; o; o >>= 1) { if (tid < o) red[tid] = fmaxf(red[tid], red[tid + o]); __syncthreads(); }
    float M = red[0]; __syncthreads();

    float wsum = 0.f;
    for (int b = tid; b < NBP; b += 256) wsum += __expf(g_hpart[b][0] - M) * g_hpart[b][1];
    red[tid] = wsum; __syncthreads();
    for (int o = 128; o; o >>= 1) { if (tid < o) red[tid] += red[tid + o]; __syncthreads(); }
    float W = red[0]; __syncthreads();

    {
        int g = tid >> 5, l = tid & 31;
        int k = kb + g;
        float a = 0.f;
        for (int b = l; b < NBP; b += 32)
            a += __expf(g_hpart[b][0] - M) * g_hpart[b][2 + k];
#pragma unroll
        for (int o = 16; o; o >>= 1) a += __shfl_xor_sync(0xffffffffu, a, o);
        if (l == 0) qn[g] = __fdividef(a, W);
    }
    __syncthreads();

    float a0 = 0.f, a1 = 0.f;
#pragma unroll
    for (int kk = 0; kk < 8; kk++) {
        float q = qn[kk];
        const float* wr = attn_wq + (size_t)(kb + kk) * HID;
        a0 += q * wr[tid];
        a1 += q * wr[tid + 256];
    }
    atomicAdd(&g_ba[tid], a0);
    atomicAdd(&g_ba[tid + 256], a1);
}

// ---------------- K5: attn pass + fused final (ticket) ----------------
__global__ void __launch_bounds__(256) k_attn(const float* __restrict__ attn_v,
                                              const float* __restrict__ gumbel,
                                              const float* __restrict__ attn_mem,
                                              const float* __restrict__ stop,
                                              float* __restrict__ out, int t) {
    int tid = threadIdx.x, wz = tid >> 5, lane = tid & 31;
    int gw = blockIdx.x * 8 + wz;
    const int tot = NBP * 8;
    const float* gum = gumbel + (size_t)t * MPTS;

    float b0[16], v0[16];
    {
        float4 a = *(const float4*)&g_ba[lane * 8];
        float4 b = *(const float4*)&g_ba[lane * 8 + 4];
        float4 c = *(const float4*)&g_ba[256 + lane * 8];
        float4 d = *(const float4*)&g_ba[256 + lane * 8 + 4];
        b0[0]=a.x;b0[1]=a.y;b0[2]=a.z;b0[3]=a.w; b0[4]=b.x;b0[5]=b.y;b0[6]=b.z;b0[7]=b.w;
        b0[8]=c.x;b0[9]=c.y;b0[10]=c.z;b0[11]=c.w; b0[12]=d.x;b0[13]=d.y;b0[14]=d.z;b0[15]=d.w;
        a = *(const float4*)&attn_v[lane * 8];
        b = *(const float4*)&attn_v[lane * 8 + 4];
        c = *(const float4*)&attn_v[256 + lane * 8];
        d = *(const float4*)&attn_v[256 + lane * 8 + 4];
        v0[0]=a.x;v0[1]=a.y;v0[2]=a.z;v0[3]=a.w; v0[4]=b.x;v0[5]=b.y;v0[6]=b.z;v0[7]=b.w;
        v0[8]=c.x;v0[9]=c.y;v0[10]=c.z;v0[11]=c.w; v0[12]=d.x;v0[13]=d.y;v0[14]=d.z;v0[15]=d.w;
    }
    float mxs = NEGINF, ssum = 0.f, best = NEGINF;
    int bidx = 0x7fffffff;

    for (int m = gw; m < MPTS; m += tot) {
        const uint4* rp = (const uint4*)(g_af16 + (size_t)m * DIM);
        uint4 p0 = rp[lane];
        uint4 p1 = rp[32 + lane];
        float sp = 0.f;
#pragma unroll
        for (int k = 0; k < 4; k++) {
            float2 f0 = __half22float2(((const __half2*)&p0)[k]);
            float2 f1 = __half22float2(((const __half2*)&p1)[k]);
            sp += tanha(f0.x + b0[2*k])     * v0[2*k];
            sp += tanha(f0.y + b0[2*k+1])   * v0[2*k+1];
            sp += tanha(f1.x + b0[8+2*k])   * v0[8+2*k];
            sp += tanha(f1.y + b0[8+2*k+1]) * v0[8+2*k+1];
        }
#pragma unroll
        for (int o = 16; o; o >>= 1) sp += __shfl_xor_sync(0xffffffffu, sp, o);
        float sc = g_sel[m] ? -1e18f : sp;
        if (sc > mxs) { ssum *= __expf(mxs - sc); mxs = sc; }
        ssum += __expf(sc - mxs);
        float tv = sc + gum[m];
        if (tv > best || (tv == best && m < bidx)) { best = tv; bidx = m; }
    }
    __shared__ float sb[8]; __shared__ int si[8];
    __shared__ float sm[8]; __shared__ float ss[8];
    if (!lane) { sb[wz] = best; si[wz] = bidx; sm[wz] = mxs; ss[wz] = ssum; }
    __syncthreads();
    if (tid == 0) {
        float B = sb[0]; int I = si[0];
        float M2 = sm[0], S = ss[0];
#pragma unroll
        for (int w = 1; w < 8; w++) {
            if (sb[w] > B || (sb[w] == B && si[w] < I)) { B = sb[w]; I = si[w]; }
            float m2 = sm[w], s2 = ss[w];
            if (m2 > M2) { S = S * __expf(M2 - m2) + s2; M2 = m2; }
            else S += s2 * __expf(m2 - M2);
        }
        g_apart[blockIdx.x][0] = B; g_apart[blockIdx.x][1] = M2;
        g_apart[blockIdx.x][2] = S; g_aidx[blockIdx.x] = I;
    }

    // ---- fused final: last block to finish does the global select ----
    __threadfence();
    __shared__ int islast;
    if (tid == 0) {
        int v = atomicAdd(&g_ticket, 1);
        islast = ((v % NBP) == NBP - 1);
    }
    __syncthreads();
    if (!islast) return;

    __shared__ float fb[256]; __shared__ int fi[256];
    __shared__ float fm[256]; __shared__ float fs[256];
    __shared__ int s_out, s_nd;
    float B = NEGINF; int I = 0x7fffffff; float M = NEGINF; float S = 0.f;
    for (int b = tid; b < NBP; b += 256) {
        float bb = g_apart[b][0]; int ii = g_aidx[b];
        if (bb > B || (bb == B && ii < I)) { B = bb; I = ii; }
        float m2 = g_apart[b][1], s2 = g_apart[b][2];
        if (m2 > M) { S = S * __expf(M - m2) + s2; M = m2; }
        else S += s2 * __expf(m2 - M);
    }
    fb[tid] = B; fi[tid] = I; fm[tid] = M; fs[tid] = S;
    __syncthreads();
    for (int o = 128; o; o >>= 1) {
        if (tid < o) {
            if (fb[tid + o] > fb[tid] || (fb[tid + o] == fb[tid] && fi[tid + o] < fi[tid])) {
                fb[tid] = fb[tid + o]; fi[tid] = fi[tid + o];
            }
            float m1 = fm[tid], s1 = fs[tid];
            float m2 = fm[tid + o], s2 = fs[tid + o];
            float Mn = fmaxf(m1, m2);
            float Sn = 0.f;
            if (s1 > 0.f) Sn += s1 * __expf(m1 - Mn);
            if (s2 > 0.f) Sn += s2 * __expf(m2 - Mn);
            fm[tid] = Mn; fs[tid] = Sn;
        }
        __syncthreads();
    }
    if (tid == 0) {
        int done = g_done;
        int o_ = fi[0];
        float sc = fb[0] - gum[o_];
        float lse = fm[0] + logf(fs[0]);
        float logp = sc - lse;
        out[t]          = done ? (float)NPTS : (float)o_;
        out[TSTEPS + t] = done ? 0.f : logp;
        if (!done) g_sel[o_] = 1;
        int nd = done || (o_ == NPTS);
        g_done = nd;
        s_out = o_; s_nd = nd;
    }
    __syncthreads();
    if (!s_nd) {
        int o_ = s_out;
        const float* src = (o_ == NPTS) ? stop : attn_mem + (size_t)o_ * DIM;
        g_x[tid] = src[tid];
        g_x[tid + 256] = src[tid + 256];
    }
}

// ---------------- launch ----------------
extern "C" void kernel_launch(void* const* d_in, const int* in_sizes, int n_in,
                              void* d_out, int out_size) {
    const float* attn_mem = (const float*)d_in[0];
    const float* stop     = (const float*)d_in[1];
    const float* init_h   = (const float*)d_in[2];
    const float* init_c   = (const float*)d_in[3];
    const float* init_i   = (const float*)d_in[4];
    const float* attn_wm  = (const float*)d_in[5];
    const float* attn_wq  = (const float*)d_in[6];
    const float* attn_v   = (const float*)d_in[7];
    const float* hop_wm   = (const float*)d_in[8];
    const float* hop_wq   = (const float*)d_in[9];
    const float* hop_v    = (const float*)d_in[10];
    const float* w_ih     = (const float*)d_in[11];
    const float* w_hh     = (const float*)d_in[12];
    const float* b_ih     = (const float*)d_in[13];
    const float* b_hh     = (const float*)d_in[14];
    const float* gumbel   = (const float*)d_in[15];
    float* out = (float*)d_out;

    k_init<<<(MPTS + 255) / 256, 256>>>(init_h, init_c, init_i);
    k_convA<<<8192, 256>>>(attn_mem, stop);
    k_convB<<<2048, 256>>>(attn_wm, hop_wm);

    dim3 gg(8, ROWT);
    k_feat_mma<<<gg, 256>>>();

    for (int t = 0; t < TSTEPS; t++) {
        k_gates<<<256, 256>>>(w_ih, w_hh, b_ih, b_hh);
        k_qh<<<64, 256>>>(hop_wq, t);
        k_hop<<<NBP, 256>>>(hop_v);
        k_bias<<<64, 256>>>(attn_wq);
        k_attn<<<NBP, 256>>>(attn_v, gumbel, attn_mem, stop, out, t);
    }
}

// round 8
// speedup vs baseline: 3.2838x; 1.0557x over previous
#include <cuda_runtime.h>
#include <cuda_fp16.h>
#include <cstdint>

#define NPTS   50000
#define MPTS   50001
#define DIM    512
#define HID    512
#define TSTEPS 16
#define NBP    444
#define NEGINF (__int_as_float(0xff800000))

#define PADM   50048           // 391 * 128
#define ROWT   391
#define NCH    16              // K = 512, 32-wide chunks

// ---------------- device scratch ----------------
__device__ __half g_af16[(size_t)MPTS * DIM];      // attn_feat fp16
__device__ __half g_hf16[(size_t)MPTS * DIM];      // hop_feat fp16
__device__ __half g_a16[(size_t)PADM * DIM];       // A (fp16)
__device__ __half g_bt[2][512][512];               // [mat][n][k] (1MB, L2-resident)
__device__ float g_hbuf[2][HID];                   // double buffered h
__device__ float g_cbuf[2][HID];                   // double buffered c
__device__ float g_x[DIM];
__device__ float g_qh[HID];
__device__ float g_ba[HID];
__device__ unsigned char g_sel[MPTS];
__device__ int   g_done;
__device__ int   g_ticket;
__device__ float g_hpart[NBP][514];
__device__ float g_apart[NBP][3];
__device__ int   g_aidx[NBP];

// ---------------- helpers ----------------
__device__ __forceinline__ float tanhe(float x) {
    float e = __expf(2.f * x);
    return 1.f - __fdividef(2.f, e + 1.f);
}
__device__ __forceinline__ float tanha(float x) {
    float y; asm("tanh.approx.f32 %0, %1;" : "=f"(y) : "f"(x)); return y;
}
__device__ __forceinline__ float sigm(float x) {
    return __fdividef(1.f, 1.f + __expf(-x));
}
__device__ __forceinline__ uint32_t s2u(const void* p) {
    uint32_t a;
    asm("{ .reg .u64 t; cvta.to.shared.u64 t, %1; cvt.u32.u64 %0, t; }" : "=r"(a) : "l"(p));
    return a;
}
__device__ __forceinline__ void cp16(uint32_t dst, const void* src) {
    asm volatile("cp.async.cg.shared.global [%0], [%1], 16;" :: "r"(dst), "l"(src));
}
__device__ __forceinline__ void ldm4(uint32_t& r0, uint32_t& r1, uint32_t& r2, uint32_t& r3,
                                     uint32_t addr) {
    asm volatile("ldmatrix.sync.aligned.m8n8.x4.shared.b16 {%0,%1,%2,%3}, [%4];"
                 : "=r"(r0), "=r"(r1), "=r"(r2), "=r"(r3) : "r"(addr));
}
__device__ __forceinline__ void mma16816(float* c, uint32_t a0, uint32_t a1, uint32_t a2,
                                         uint32_t a3, uint32_t b0, uint32_t b1) {
    asm volatile(
        "mma.sync.aligned.m16n8k16.row.col.f32.f16.f16.f32 "
        "{%0,%1,%2,%3},{%4,%5,%6,%7},{%8,%9},{%0,%1,%2,%3};"
        : "+f"(c[0]), "+f"(c[1]), "+f"(c[2]), "+f"(c[3])
        : "r"(a0), "r"(a1), "r"(a2), "r"(a3), "r"(b0), "r"(b1));
}
__device__ __forceinline__ unsigned pkh2(float a, float b) {
    __half2 h = __floats2half2_rn(a, b);
    return *(unsigned*)&h;
}

// ---------------- K0: state init ----------------
__global__ void k_init(const float* __restrict__ ih, const float* __restrict__ ic,
                       const float* __restrict__ ii) {
    int i = blockIdx.x * blockDim.x + threadIdx.x;
    if (i < MPTS) g_sel[i] = 0;
    if (i < HID) { g_hbuf[0][i] = ih[i]; g_cbuf[0][i] = ic[i]; g_x[i] = ii[i]; g_qh[i] = 0.f; }
    if (i == 0) { g_done = 0; g_ticket = 0; }
}

// ---------------- convert A: mem(+stop,+pad) -> fp16 ----------------
__global__ void k_convA(const float* __restrict__ mem, const float* __restrict__ stop) {
    const int total4 = PADM * DIM / 4;
    for (int i = blockIdx.x * blockDim.x + threadIdx.x; i < total4;
         i += gridDim.x * blockDim.x) {
        int row = i >> 7;
        int c4 = (i & 127) * 4;
        float4 v;
        if (row < NPTS)       v = *(const float4*)&mem[(size_t)row * DIM + c4];
        else if (row == NPTS) v = *(const float4*)&stop[c4];
        else                  v = make_float4(0.f, 0.f, 0.f, 0.f);
        uint2 ph;
        ph.x = pkh2(v.x, v.y); ph.y = pkh2(v.z, v.w);
        ((uint2*)g_a16)[i] = ph;
    }
}

// ---------------- convert B: wm[k][n] -> g_bt[mat][n][k] (fp16) ----------------
__global__ void k_convB(const float* __restrict__ attn_wm, const float* __restrict__ hop_wm) {
    int id = blockIdx.x * blockDim.x + threadIdx.x;
    if (id >= 2 * 512 * 512) return;
    int w = id >> 18;
    int r = id & 262143;
    int n = r >> 9;
    int k = r & 511;
    const float* src = w ? hop_wm : attn_wm;
    g_bt[w][n][k] = __float2half_rn(src[(size_t)k * 512 + n]);
}

// ---------------- GEMM: fp16 mma.sync, CTA 128x128, K=512 ----------------
// grid (8 = colblock*2+mat, 391 = rowtile): x fastest -> B L2-resident, A stripe shared.
__global__ void __launch_bounds__(256, 2) k_feat_mma() {
    __shared__ __align__(16) __half sA[2][128 * 40];
    __shared__ __align__(16) __half sB[2][128 * 40];
    int tid = threadIdx.x, wid = tid >> 5, lane = tid & 31;
    int rowBase = blockIdx.y * 128;
    int colBase = (blockIdx.x >> 1) * 128;
    int mat = blockIdx.x & 1;
    const __half* bsrc = &g_bt[mat][colBase][0];
    __half* outp = mat ? g_hf16 : g_af16;
    const __half* asrc = g_a16 + (size_t)rowBase * DIM;
    int wm = wid >> 1, wn = wid & 1;

    float acc[2][8][4];
#pragma unroll
    for (int mt = 0; mt < 2; mt++)
#pragma unroll
        for (int j = 0; j < 8; j++)
#pragma unroll
            for (int e = 0; e < 4; e++) acc[mt][j][e] = 0.f;

    uint32_t uA0 = s2u(&sA[0][0]), uB0 = s2u(&sB[0][0]);
    const uint32_t bufStride = 128 * 40 * 2;

    auto load = [&](int c, int buf) {
        const __half* A = asrc + c * 32;
        const __half* B = bsrc + c * 32;
        uint32_t dA = uA0 + buf * bufStride;
        uint32_t dB = uB0 + buf * bufStride;
#pragma unroll
        for (int i = 0; i < 2; i++) {
            int idx = i * 256 + tid;
            int r = idx >> 2, ch = idx & 3;
            cp16(dA + r * 80 + ch * 16, (const char*)(A + (size_t)r * 512) + ch * 16);
            cp16(dB + r * 80 + ch * 16, (const char*)(B + (size_t)r * 512) + ch * 16);
        }
        asm volatile("cp.async.commit_group;" ::: "memory");
    };

    load(0, 0);
    for (int c = 0; c < NCH; c++) {
        int buf = c & 1;
        if (c + 1 < NCH) load(c + 1, buf ^ 1);
        if (c + 1 < NCH)
            asm volatile("cp.async.wait_group 1;" ::: "memory");
        else
            asm volatile("cp.async.wait_group 0;" ::: "memory");
        __syncthreads();

        uint32_t bA = uA0 + buf * bufStride;
        uint32_t bB = uB0 + buf * bufStride;
#pragma unroll
        for (int ks = 0; ks < 2; ks++) {
            uint32_t a[2][4];
#pragma unroll
            for (int mt = 0; mt < 2; mt++) {
                int row = wm * 32 + mt * 16 + (lane & 15);
                int col = ks * 16 + (lane >> 4) * 8;
                ldm4(a[mt][0], a[mt][1], a[mt][2], a[mt][3], bA + (row * 40 + col) * 2);
            }
            uint32_t b[4][4];
#pragma unroll
            for (int p = 0; p < 4; p++) {
                int q = lane >> 3, rr = lane & 7;
                int n = wn * 64 + p * 16 + (q >> 1) * 8 + rr;
                int col = ks * 16 + (q & 1) * 8;
                ldm4(b[p][0], b[p][1], b[p][2], b[p][3], bB + (n * 40 + col) * 2);
            }
#pragma unroll
            for (int mt = 0; mt < 2; mt++)
#pragma unroll
                for (int j = 0; j < 8; j++)
                    mma16816(acc[mt][j], a[mt][0], a[mt][1], a[mt][2], a[mt][3],
                             b[j >> 1][(j & 1) * 2], b[j >> 1][(j & 1) * 2 + 1]);
        }
        __syncthreads();
    }

    // epilogue: fp32 acc -> half2 -> global
    int g = lane >> 2, tq = lane & 3;
#pragma unroll
    for (int mt = 0; mt < 2; mt++) {
        int r0 = rowBase + wm * 32 + mt * 16 + g;
#pragma unroll
        for (int j = 0; j < 8; j++) {
            int cc = colBase + wn * 64 + j * 8 + tq * 2;
            if (r0 < MPTS)
                *(__half2*)&outp[(size_t)r0 * DIM + cc] =
                    __floats2half2_rn(acc[mt][j][0], acc[mt][j][1]);
            if (r0 + 8 < MPTS)
                *(__half2*)&outp[(size_t)(r0 + 8) * DIM + cc] =
                    __floats2half2_rn(acc[mt][j][2], acc[mt][j][3]);
        }
    }
}

// ---------------- K2: fused gates + h,c update + qh GEMV (64 blocks) ----------------
// Block b owns hidden slice [8b, 8b+8). Warp w computes the 4 gate dots for j=8b+w,
// then tid<8 forms h/c, writes the global slice, and the block does its GEMV partial.
__global__ void __launch_bounds__(256) k_qh(const float* __restrict__ w_ih,
                                            const float* __restrict__ w_hh,
                                            const float* __restrict__ b_ih,
                                            const float* __restrict__ b_hh,
                                            const float* __restrict__ hop_wq, int t) {
    __shared__ float sg[8][4];
    __shared__ float sh[8];
    int tid = threadIdx.x, wid = tid >> 5, lane = tid & 31;
    int kb = blockIdx.x * 8;
    const float* hold = g_hbuf[t & 1];
    float* hnew = g_hbuf[(t + 1) & 1];
    const float* cold = g_cbuf[t & 1];
    float* cnew = g_cbuf[(t + 1) & 1];

    int j = kb + wid;
    const float* wi0 = w_ih + (size_t)j * DIM;
    const float* wi1 = w_ih + (size_t)(HID + j) * DIM;
    const float* wi2 = w_ih + (size_t)(2 * HID + j) * DIM;
    const float* wi3 = w_ih + (size_t)(3 * HID + j) * DIM;
    const float* wh0 = w_hh + (size_t)j * HID;
    const float* wh1 = w_hh + (size_t)(HID + j) * HID;
    const float* wh2 = w_hh + (size_t)(2 * HID + j) * HID;
    const float* wh3 = w_hh + (size_t)(3 * HID + j) * HID;
    float s0 = 0.f, s1 = 0.f, s2 = 0.f, s3 = 0.f;
#pragma unroll 4
    for (int k = lane; k < DIM; k += 32) {
        float xv = g_x[k], hv = hold[k];
        s0 += wi0[k] * xv + wh0[k] * hv;
        s1 += wi1[k] * xv + wh1[k] * hv;
        s2 += wi2[k] * xv + wh2[k] * hv;
        s3 += wi3[k] * xv + wh3[k] * hv;
    }
#pragma unroll
    for (int o = 16; o; o >>= 1) {
        s0 += __shfl_xor_sync(0xffffffffu, s0, o);
        s1 += __shfl_xor_sync(0xffffffffu, s1, o);
        s2 += __shfl_xor_sync(0xffffffffu, s2, o);
        s3 += __shfl_xor_sync(0xffffffffu, s3, o);
    }
    if (!lane) {
        sg[wid][0] = s0 + b_ih[j] + b_hh[j];
        sg[wid][1] = s1 + b_ih[HID + j] + b_hh[HID + j];
        sg[wid][2] = s2 + b_ih[2 * HID + j] + b_hh[2 * HID + j];
        sg[wid][3] = s3 + b_ih[3 * HID + j] + b_hh[3 * HID + j];
    }
    __syncthreads();
    if (tid < 8) {
        int jj = kb + tid;
        float gi = sigm(sg[tid][0]);
        float gf = sigm(sg[tid][1]);
        float gg = tanhe(sg[tid][2]);
        float go = sigm(sg[tid][3]);
        float c = gf * cold[jj] + gi * gg;
        float h = go * tanhe(c);
        cnew[jj] = c;
        hnew[jj] = h;
        sh[tid] = h;
    }
    __syncthreads();
    float a0 = 0.f, a1 = 0.f;
#pragma unroll
    for (int kk = 0; kk < 8; kk++) {
        float hv = sh[kk];
        const float* wr = hop_wq + (size_t)(kb + kk) * HID;
        a0 += hv * wr[tid];
        a1 += hv * wr[tid + 256];
    }
    atomicAdd(&g_qh[tid], a0);
    atomicAdd(&g_qh[tid + 256], a1);
}

// ---------------- K3: hop pass (fp16 features) ----------------
__global__ void __launch_bounds__(256) k_hop(const float* __restrict__ hop_v) {
    int tid = threadIdx.x, wz = tid >> 5, lane = tid & 31;
    if (blockIdx.x == 0) { g_ba[tid] = 0.f; g_ba[tid + 256] = 0.f; }
    int gw = blockIdx.x * 8 + wz;
    const int tot = NBP * 8;

    float q0[16], v0[16];
    {
        float4 a = *(const float4*)&g_qh[lane * 8];
        float4 b = *(const float4*)&g_qh[lane * 8 + 4];
        float4 c = *(const float4*)&g_qh[256 + lane * 8];
        float4 d = *(const float4*)&g_qh[256 + lane * 8 + 4];
        q0[0]=a.x;q0[1]=a.y;q0[2]=a.z;q0[3]=a.w; q0[4]=b.x;q0[5]=b.y;q0[6]=b.z;q0[7]=b.w;
        q0[8]=c.x;q0[9]=c.y;q0[10]=c.z;q0[11]=c.w; q0[12]=d.x;q0[13]=d.y;q0[14]=d.z;q0[15]=d.w;
        a = *(const float4*)&hop_v[lane * 8];
        b = *(const float4*)&hop_v[lane * 8 + 4];
        c = *(const float4*)&hop_v[256 + lane * 8];
        d = *(const float4*)&hop_v[256 + lane * 8 + 4];
        v0[0]=a.x;v0[1]=a.y;v0[2]=a.z;v0[3]=a.w; v0[4]=b.x;v0[5]=b.y;v0[6]=b.z;v0[7]=b.w;
        v0[8]=c.x;v0[9]=c.y;v0[10]=c.z;v0[11]=c.w; v0[12]=d.x;v0[13]=d.y;v0[14]=d.z;v0[15]=d.w;
    }
    float mx = NEGINF, sw = 0.f, acc[16];
#pragma unroll
    for (int i = 0; i < 16; i++) acc[i] = 0.f;

    for (int m = gw; m < MPTS; m += tot) {
        const uint4* rp = (const uint4*)(g_hf16 + (size_t)m * DIM);
        uint4 p0 = rp[lane];
        uint4 p1 = rp[32 + lane];
        float vals[16];
#pragma unroll
        for (int k = 0; k < 4; k++) {
            float2 f0 = __half22float2(((const __half2*)&p0)[k]);
            float2 f1 = __half22float2(((const __half2*)&p1)[k]);
            vals[2*k] = f0.x; vals[2*k+1] = f0.y;
            vals[8+2*k] = f1.x; vals[8+2*k+1] = f1.y;
        }
        float sp = 0.f;
#pragma unroll
        for (int i = 0; i < 16; i++) sp += tanha(vals[i] + q0[i]) * v0[i];
#pragma unroll
        for (int o = 16; o; o >>= 1) sp += __shfl_xor_sync(0xffffffffu, sp, o);
        if (sp > mx) {
            float f = __expf(mx - sp);
            sw *= f;
#pragma unroll
            for (int i = 0; i < 16; i++) acc[i] *= f;
            mx = sp;
        }
        float wgt = __expf(sp - mx);
        sw += wgt;
#pragma unroll
        for (int i = 0; i < 16; i++) acc[i] += wgt * vals[i];
    }
    __shared__ float smx[8], ssw[8], sacc[8][512];
#pragma unroll
    for (int s = 0; s < 8; s++) {
        sacc[wz][lane * 8 + s] = acc[s];
        sacc[wz][256 + lane * 8 + s] = acc[8 + s];
    }
    if (!lane) { smx[wz] = mx; ssw[wz] = sw; }
    __syncthreads();

    float M = smx[0];
#pragma unroll
    for (int w = 1; w < 8; w++) M = fmaxf(M, smx[w]);
    for (int c = tid; c < 512; c += 256) {
        float a = 0.f;
#pragma unroll
        for (int w = 0; w < 8; w++) a += sacc[w][c] * __expf(smx[w] - M);
        g_hpart[blockIdx.x][2 + c] = a;
    }
    if (tid == 0) {
        float W = 0.f;
#pragma unroll
        for (int w = 0; w < 8; w++) W += ssw[w] * __expf(smx[w] - M);
        g_hpart[blockIdx.x][0] = M;
        g_hpart[blockIdx.x][1] = W;
    }
}

// ---------------- K4: reduce hop partials + bias GEMV (64 blocks) ----------------
__global__ void __launch_bounds__(256) k_bias(const float* __restrict__ attn_wq) {
    __shared__ float red[256];
    __shared__ float qn[8];
    int tid = threadIdx.x;
    int kb = blockIdx.x * 8;

    float m = NEGINF;
    for (int b = tid; b < NBP; b += 256) m = fmaxf(m, g_hpart[b][0]);
    red[tid] = m; __syncthreads();
    for (int o = 128; o; o >>= 1) { if (tid < o) red[tid] = fmaxf(red[tid], red[tid + o]); __syncthreads(); }
    float M = red[0]; __syncthreads();

    float wsum = 0.f;
    for (int b = tid; b < NBP; b += 256) wsum += __expf(g_hpart[b][0] - M) * g_hpart[b][1];
    red[tid] = wsum; __syncthreads();
    for (int o = 128; o; o >>= 1) { if (tid < o) red[tid] += red[tid + o]; __syncthreads(); }
    float W = red[0]; __syncthreads();

    {
        int g = tid >> 5, l = tid & 31;
        int k = kb + g;
        float a = 0.f;
        for (int b = l; b < NBP; b += 32)
            a += __expf(g_hpart[b][0] - M) * g_hpart[b][2 + k];
#pragma unroll
        for (int o = 16; o; o >>= 1) a += __shfl_xor_sync(0xffffffffu, a, o);
        if (l == 0) qn[g] = __fdividef(a, W);
    }
    __syncthreads();

    float a0 = 0.f, a1 = 0.f;
#pragma unroll
    for (int kk = 0; kk < 8; kk++) {
        float q = qn[kk];
        const float* wr = attn_wq + (size_t)(kb + kk) * HID;
        a0 += q * wr[tid];
        a1 += q * wr[tid + 256];
    }
    atomicAdd(&g_ba[tid], a0);
    atomicAdd(&g_ba[tid + 256], a1);
}

// ---------------- K5: attn pass + fused final (ticket) ----------------
__global__ void __launch_bounds__(256) k_attn(const float* __restrict__ attn_v,
                                              const float* __restrict__ gumbel,
                                              const float* __restrict__ attn_mem,
                                              const float* __restrict__ stop,
                                              float* __restrict__ out, int t) {
    int tid = threadIdx.x, wz = tid >> 5, lane = tid & 31;
    int gw = blockIdx.x * 8 + wz;
    const int tot = NBP * 8;
    const float* gum = gumbel + (size_t)t * MPTS;

    float b0[16], v0[16];
    {
        float4 a = *(const float4*)&g_ba[lane * 8];
        float4 b = *(const float4*)&g_ba[lane * 8 + 4];
        float4 c = *(const float4*)&g_ba[256 + lane * 8];
        float4 d = *(const float4*)&g_ba[256 + lane * 8 + 4];
        b0[0]=a.x;b0[1]=a.y;b0[2]=a.z;b0[3]=a.w; b0[4]=b.x;b0[5]=b.y;b0[6]=b.z;b0[7]=b.w;
        b0[8]=c.x;b0[9]=c.y;b0[10]=c.z;b0[11]=c.w; b0[12]=d.x;b0[13]=d.y;b0[14]=d.z;b0[15]=d.w;
        a = *(const float4*)&attn_v[lane * 8];
        b = *(const float4*)&attn_v[lane * 8 + 4];
        c = *(const float4*)&attn_v[256 + lane * 8];
        d = *(const float4*)&attn_v[256 + lane * 8 + 4];
        v0[0]=a.x;v0[1]=a.y;v0[2]=a.z;v0[3]=a.w; v0[4]=b.x;v0[5]=b.y;v0[6]=b.z;v0[7]=b.w;
        v0[8]=c.x;v0[9]=c.y;v0[10]=c.z;v0[11]=c.w; v0[12]=d.x;v0[13]=d.y;v0[14]=d.z;v0[15]=d.w;
    }
    float mxs = NEGINF, ssum = 0.f, best = NEGINF;
    int bidx = 0x7fffffff;

    for (int m = gw; m < MPTS; m += tot) {
        const uint4* rp = (const uint4*)(g_af16 + (size_t)m * DIM);
        uint4 p0 = rp[lane];
        uint4 p1 = rp[32 + lane];
        float sp = 0.f;
#pragma unroll
        for (int k = 0; k < 4; k++) {
            float2 f0 = __half22float2(((const __half2*)&p0)[k]);
            float2 f1 = __half22float2(((const __half2*)&p1)[k]);
            sp += tanha(f0.x + b0[2*k])     * v0[2*k];
            sp += tanha(f0.y + b0[2*k+1])   * v0[2*k+1];
            sp += tanha(f1.x + b0[8+2*k])   * v0[8+2*k];
            sp += tanha(f1.y + b0[8+2*k+1]) * v0[8+2*k+1];
        }
#pragma unroll
        for (int o = 16; o; o >>= 1) sp += __shfl_xor_sync(0xffffffffu, sp, o);
        float sc = g_sel[m] ? -1e18f : sp;
        if (sc > mxs) { ssum *= __expf(mxs - sc); mxs = sc; }
        ssum += __expf(sc - mxs);
        float tv = sc + gum[m];
        if (tv > best || (tv == best && m < bidx)) { best = tv; bidx = m; }
    }
    __shared__ float sb[8]; __shared__ int si[8];
    __shared__ float sm[8]; __shared__ float ss[8];
    if (!lane) { sb[wz] = best; si[wz] = bidx; sm[wz] = mxs; ss[wz] = ssum; }
    __syncthreads();
    if (tid == 0) {
        float B = sb[0]; int I = si[0];
        float M2 = sm[0], S = ss[0];
#pragma unroll
        for (int w = 1; w < 8; w++) {
            if (sb[w] > B || (sb[w] == B && si[w] < I)) { B = sb[w]; I = si[w]; }
            float m2 = sm[w], s2 = ss[w];
            if (m2 > M2) { S = S * __expf(M2 - m2) + s2; M2 = m2; }
            else S += s2 * __expf(m2 - M2);
        }
        g_apart[blockIdx.x][0] = B; g_apart[blockIdx.x][1] = M2;
        g_apart[blockIdx.x][2] = S; g_aidx[blockIdx.x] = I;
    }

    // ---- fused final: last block to finish does the global select ----
    __threadfence();
    __shared__ int islast;
    if (tid == 0) {
        int v = atomicAdd(&g_ticket, 1);
        islast = ((v % NBP) == NBP - 1);
    }
    __syncthreads();
    if (!islast) return;

    // zero qh accumulator for next step's k_qh atomics
    g_qh[tid] = 0.f; g_qh[tid + 256] = 0.f;

    __shared__ float fb[256]; __shared__ int fi[256];
    __shared__ float fm[256]; __shared__ float fs[256];
    __shared__ int s_out, s_nd;
    float B = NEGINF; int I = 0x7fffffff; float M = NEGINF; float S = 0.f;
    for (int b = tid; b < NBP; b += 256) {
        float bb = g_apart[b][0]; int ii = g_aidx[b];
        if (bb > B || (bb == B && ii < I)) { B = bb; I = ii; }
        float m2 = g_apart[b][1], s2 = g_apart[b][2];
        if (m2 > M) { S = S * __expf(M - m2) + s2; M = m2; }
        else S += s2 * __expf(m2 - M);
    }
    fb[tid] = B; fi[tid] = I; fm[tid] = M; fs[tid] = S;
    __syncthreads();
    for (int o = 128; o; o >>= 1) {
        if (tid < o) {
            if (fb[tid + o] > fb[tid] || (fb[tid + o] == fb[tid] && fi[tid + o] < fi[tid])) {
                fb[tid] = fb[tid + o]; fi[tid] = fi[tid + o];
            }
            float m1 = fm[tid], s1 = fs[tid];
            float m2 = fm[tid + o], s2 = fs[tid + o];
            float Mn = fmaxf(m1, m2);
            float Sn = 0.f;
            if (s1 > 0.f) Sn += s1 * __expf(m1 - Mn);
            if (s2 > 0.f) Sn += s2 * __expf(m2 - Mn);
            fm[tid] = Mn; fs[tid] = Sn;
        }
        __syncthreads();
    }
    if (tid == 0) {
        int done = g_done;
        int o_ = fi[0];
        float sc = fb[0] - gum[o_];
        float lse = fm[0] + logf(fs[0]);
        float logp = sc - lse;
        out[t]          = done ? (float)NPTS : (float)o_;
        out[TSTEPS + t] = done ? 0.f : logp;
        if (!done) g_sel[o_] = 1;
        int nd = done || (o_ == NPTS);
        g_done = nd;
        s_out = o_; s_nd = nd;
    }
    __syncthreads();
    if (!s_nd) {
        int o_ = s_out;
        const float* src = (o_ == NPTS) ? stop : attn_mem + (size_t)o_ * DIM;
        g_x[tid] = src[tid];
        g_x[tid + 256] = src[tid + 256];
    }
}

// ---------------- launch ----------------
extern "C" void kernel_launch(void* const* d_in, const int* in_sizes, int n_in,
                              void* d_out, int out_size) {
    const float* attn_mem = (const float*)d_in[0];
    const float* stop     = (const float*)d_in[1];
    const float* init_h   = (const float*)d_in[2];
    const float* init_c   = (const float*)d_in[3];
    const float* init_i   = (const float*)d_in[4];
    const float* attn_wm  = (const float*)d_in[5];
    const float* attn_wq  = (const float*)d_in[6];
    const float* attn_v   = (const float*)d_in[7];
    const float* hop_wm   = (const float*)d_in[8];
    const float* hop_wq   = (const float*)d_in[9];
    const float* hop_v    = (const float*)d_in[10];
    const float* w_ih     = (const float*)d_in[11];
    const float* w_hh     = (const float*)d_in[12];
    const float* b_ih     = (const float*)d_in[13];
    const float* b_hh     = (const float*)d_in[14];
    const float* gumbel   = (const float*)d_in[15];
    float* out = (float*)d_out;

    k_init<<<(MPTS + 255) / 256, 256>>>(init_h, init_c, init_i);
    k_convA<<<8192, 256>>>(attn_mem, stop);
    k_convB<<<2048, 256>>>(attn_wm, hop_wm);

    dim3 gg(8, ROWT);
    k_feat_mma<<<gg, 256>>>();

    for (int t = 0; t < TSTEPS; t++) {
        k_qh<<<64, 256>>>(w_ih, w_hh, b_ih, b_hh, hop_wq, t);
        k_hop<<<NBP, 256>>>(hop_v);
        k_bias<<<64, 256>>>(attn_wq);
        k_attn<<<NBP, 256>>>(attn_v, gumbel, attn_mem, stop, out, t);
    }
}

// round 9
// speedup vs baseline: 3.3440x; 1.0183x over previous
#include <cuda_runtime.h>
#include <cuda_fp16.h>
#include <cstdint>

#define NPTS   50000
#define MPTS   50001
#define DIM    512
#define HID    512
#define TSTEPS 16
#define NBMAX  320
#define NEGINF (__int_as_float(0xff800000))

#define PADM   50048           // 391 * 128
#define ROWT   391
#define NCH    16              // K = 512, 32-wide chunks

// ---------------- device scratch ----------------
__device__ __half g_af16[(size_t)MPTS * DIM];
__device__ __half g_hf16[(size_t)MPTS * DIM];
__device__ __half g_a16[(size_t)PADM * DIM];
__device__ __half g_bt[2][512][512];
__device__ float g_hbuf[2][HID];
__device__ float g_cbuf[2][HID];
__device__ float g_x[DIM];
__device__ float g_qh[HID];
__device__ float g_ba[HID];
__device__ unsigned char g_sel[MPTS];
__device__ int   g_done;
__device__ int   g_ticket;
__device__ volatile unsigned g_gen;
__device__ unsigned g_cnt;
__device__ float g_hpart[NBMAX][514];
__device__ float g_apart[NBMAX][3];
__device__ int   g_aidx[NBMAX];

// ---------------- helpers ----------------
__device__ __forceinline__ float tanhe(float x) {
    float e = __expf(2.f * x);
    return 1.f - __fdividef(2.f, e + 1.f);
}
__device__ __forceinline__ float tanha(float x) {
    float y; asm("tanh.approx.f32 %0, %1;" : "=f"(y) : "f"(x)); return y;
}
__device__ __forceinline__ float sigm(float x) {
    return __fdividef(1.f, 1.f + __expf(-x));
}
__device__ __forceinline__ uint32_t s2u(const void* p) {
    uint32_t a;
    asm("{ .reg .u64 t; cvta.to.shared.u64 t, %1; cvt.u32.u64 %0, t; }" : "=r"(a) : "l"(p));
    return a;
}
__device__ __forceinline__ void cp16(uint32_t dst, const void* src) {
    asm volatile("cp.async.cg.shared.global [%0], [%1], 16;" :: "r"(dst), "l"(src));
}
__device__ __forceinline__ void ldm4(uint32_t& r0, uint32_t& r1, uint32_t& r2, uint32_t& r3,
                                     uint32_t addr) {
    asm volatile("ldmatrix.sync.aligned.m8n8.x4.shared.b16 {%0,%1,%2,%3}, [%4];"
                 : "=r"(r0), "=r"(r1), "=r"(r2), "=r"(r3) : "r"(addr));
}
__device__ __forceinline__ void mma16816(float* c, uint32_t a0, uint32_t a1, uint32_t a2,
                                         uint32_t a3, uint32_t b0, uint32_t b1) {
    asm volatile(
        "mma.sync.aligned.m16n8k16.row.col.f32.f16.f16.f32 "
        "{%0,%1,%2,%3},{%4,%5,%6,%7},{%8,%9},{%0,%1,%2,%3};"
        : "+f"(c[0]), "+f"(c[1]), "+f"(c[2]), "+f"(c[3])
        : "r"(a0), "r"(a1), "r"(a2), "r"(a3), "r"(b0), "r"(b1));
}
__device__ __forceinline__ unsigned pkh2(float a, float b) {
    __half2 h = __floats2half2_rn(a, b);
    return *(unsigned*)&h;
}

// grid barrier: counting + generation spin (all nb blocks resident by construction)
__device__ __forceinline__ void gridbar(int nb) {
    __threadfence();
    __syncthreads();
    if (threadIdx.x == 0) {
        unsigned gen = g_gen;
        unsigned v = atomicAdd(&g_cnt, 1);
        if (v == (unsigned)(nb - 1)) {
            g_cnt = 0;
            __threadfence();
            g_gen = gen + 1;
        } else {
            while (g_gen == gen) __nanosleep(64);
        }
    }
    __syncthreads();
}

// ---------------- K0: state init ----------------
__global__ void k_init(const float* __restrict__ ih, const float* __restrict__ ic,
                       const float* __restrict__ ii) {
    int i = blockIdx.x * blockDim.x + threadIdx.x;
    if (i < MPTS) g_sel[i] = 0;
    if (i < HID) { g_hbuf[0][i] = ih[i]; g_cbuf[0][i] = ic[i]; g_x[i] = ii[i]; g_qh[i] = 0.f; }
    if (i == 0) { g_done = 0; g_ticket = 0; g_gen = 0; g_cnt = 0; }
}

// ---------------- convert A ----------------
__global__ void k_convA(const float* __restrict__ mem, const float* __restrict__ stop) {
    const int total4 = PADM * DIM / 4;
    for (int i = blockIdx.x * blockDim.x + threadIdx.x; i < total4;
         i += gridDim.x * blockDim.x) {
        int row = i >> 7;
        int c4 = (i & 127) * 4;
        float4 v;
        if (row < NPTS)       v = *(const float4*)&mem[(size_t)row * DIM + c4];
        else if (row == NPTS) v = *(const float4*)&stop[c4];
        else                  v = make_float4(0.f, 0.f, 0.f, 0.f);
        uint2 ph;
        ph.x = pkh2(v.x, v.y); ph.y = pkh2(v.z, v.w);
        ((uint2*)g_a16)[i] = ph;
    }
}

// ---------------- convert B ----------------
__global__ void k_convB(const float* __restrict__ attn_wm, const float* __restrict__ hop_wm) {
    int id = blockIdx.x * blockDim.x + threadIdx.x;
    if (id >= 2 * 512 * 512) return;
    int w = id >> 18;
    int r = id & 262143;
    int n = r >> 9;
    int k = r & 511;
    const float* src = w ? hop_wm : attn_wm;
    g_bt[w][n][k] = __float2half_rn(src[(size_t)k * 512 + n]);
}

// ---------------- GEMM: fp16 mma.sync, CTA 128x128, K=512 (unchanged) ----------------
__global__ void __launch_bounds__(256, 2) k_feat_mma() {
    __shared__ __align__(16) __half sA[2][128 * 40];
    __shared__ __align__(16) __half sB[2][128 * 40];
    int tid = threadIdx.x, wid = tid >> 5, lane = tid & 31;
    int rowBase = blockIdx.y * 128;
    int colBase = (blockIdx.x >> 1) * 128;
    int mat = blockIdx.x & 1;
    const __half* bsrc = &g_bt[mat][colBase][0];
    __half* outp = mat ? g_hf16 : g_af16;
    const __half* asrc = g_a16 + (size_t)rowBase * DIM;
    int wm = wid >> 1, wn = wid & 1;

    float acc[2][8][4];
#pragma unroll
    for (int mt = 0; mt < 2; mt++)
#pragma unroll
        for (int j = 0; j < 8; j++)
#pragma unroll
            for (int e = 0; e < 4; e++) acc[mt][j][e] = 0.f;

    uint32_t uA0 = s2u(&sA[0][0]), uB0 = s2u(&sB[0][0]);
    const uint32_t bufStride = 128 * 40 * 2;

    auto load = [&](int c, int buf) {
        const __half* A = asrc + c * 32;
        const __half* B = bsrc + c * 32;
        uint32_t dA = uA0 + buf * bufStride;
        uint32_t dB = uB0 + buf * bufStride;
#pragma unroll
        for (int i = 0; i < 2; i++) {
            int idx = i * 256 + tid;
            int r = idx >> 2, ch = idx & 3;
            cp16(dA + r * 80 + ch * 16, (const char*)(A + (size_t)r * 512) + ch * 16);
            cp16(dB + r * 80 + ch * 16, (const char*)(B + (size_t)r * 512) + ch * 16);
        }
        asm volatile("cp.async.commit_group;" ::: "memory");
    };

    load(0, 0);
    for (int c = 0; c < NCH; c++) {
        int buf = c & 1;
        if (c + 1 < NCH) load(c + 1, buf ^ 1);
        if (c + 1 < NCH)
            asm volatile("cp.async.wait_group 1;" ::: "memory");
        else
            asm volatile("cp.async.wait_group 0;" ::: "memory");
        __syncthreads();

        uint32_t bA = uA0 + buf * bufStride;
        uint32_t bB = uB0 + buf * bufStride;
#pragma unroll
        for (int ks = 0; ks < 2; ks++) {
            uint32_t a[2][4];
#pragma unroll
            for (int mt = 0; mt < 2; mt++) {
                int row = wm * 32 + mt * 16 + (lane & 15);
                int col = ks * 16 + (lane >> 4) * 8;
                ldm4(a[mt][0], a[mt][1], a[mt][2], a[mt][3], bA + (row * 40 + col) * 2);
            }
            uint32_t b[4][4];
#pragma unroll
            for (int p = 0; p < 4; p++) {
                int q = lane >> 3, rr = lane & 7;
                int n = wn * 64 + p * 16 + (q >> 1) * 8 + rr;
                int col = ks * 16 + (q & 1) * 8;
                ldm4(b[p][0], b[p][1], b[p][2], b[p][3], bB + (n * 40 + col) * 2);
            }
#pragma unroll
            for (int mt = 0; mt < 2; mt++)
#pragma unroll
                for (int j = 0; j < 8; j++)
                    mma16816(acc[mt][j], a[mt][0], a[mt][1], a[mt][2], a[mt][3],
                             b[j >> 1][(j & 1) * 2], b[j >> 1][(j & 1) * 2 + 1]);
        }
        __syncthreads();
    }

    int g = lane >> 2, tq = lane & 3;
#pragma unroll
    for (int mt = 0; mt < 2; mt++) {
        int r0 = rowBase + wm * 32 + mt * 16 + g;
#pragma unroll
        for (int j = 0; j < 8; j++) {
            int cc = colBase + wn * 64 + j * 8 + tq * 2;
            if (r0 < MPTS)
                *(__half2*)&outp[(size_t)r0 * DIM + cc] =
                    __floats2half2_rn(acc[mt][j][0], acc[mt][j][1]);
            if (r0 + 8 < MPTS)
                *(__half2*)&outp[(size_t)(r0 + 8) * DIM + cc] =
                    __floats2half2_rn(acc[mt][j][2], acc[mt][j][3]);
        }
    }
}

// ================= persistent step megakernel =================
__global__ void __launch_bounds__(256, 2) k_step(
    const float* __restrict__ w_ih, const float* __restrict__ w_hh,
    const float* __restrict__ b_ih, const float* __restrict__ b_hh,
    const float* __restrict__ hop_wq, const float* __restrict__ hop_v,
    const float* __restrict__ attn_wq, const float* __restrict__ attn_v,
    const float* __restrict__ gumbel, const float* __restrict__ attn_mem,
    const float* __restrict__ stop, float* __restrict__ out, int nb)
{
    // shared (summed across phases; ~21KB)
    __shared__ float sg[8][4];
    __shared__ float shh[8];
    __shared__ float smx[8], ssw[8], sacc[8][512];
    __shared__ float red[256];
    __shared__ float qn[8];
    __shared__ float sb[8]; __shared__ int si[8];
    __shared__ float sm[8]; __shared__ float ss[8];
    __shared__ float fb[256]; __shared__ int fi[256];
    __shared__ float fm[256]; __shared__ float fs[256];
    __shared__ int s_out, s_nd, islast;

    int bid = blockIdx.x;
    int tid = threadIdx.x, wid = tid >> 5, lane = tid & 31;
    const int tot = nb * 8;

    for (int t = 0; t < TSTEPS; t++) {
        // ---- phase A: gates + h,c + qh GEMV (blocks 0..63) ----
        if (bid < 64) {
            int kb = bid * 8;
            const float* hold = g_hbuf[t & 1];
            float* hnew = g_hbuf[(t + 1) & 1];
            const float* cold = g_cbuf[t & 1];
            float* cnew = g_cbuf[(t + 1) & 1];
            int j = kb + wid;
            const float* wi0 = w_ih + (size_t)j * DIM;
            const float* wi1 = w_ih + (size_t)(HID + j) * DIM;
            const float* wi2 = w_ih + (size_t)(2 * HID + j) * DIM;
            const float* wi3 = w_ih + (size_t)(3 * HID + j) * DIM;
            const float* wh0 = w_hh + (size_t)j * HID;
            const float* wh1 = w_hh + (size_t)(HID + j) * HID;
            const float* wh2 = w_hh + (size_t)(2 * HID + j) * HID;
            const float* wh3 = w_hh + (size_t)(3 * HID + j) * HID;
            float s0 = 0.f, s1 = 0.f, s2 = 0.f, s3 = 0.f;
#pragma unroll 4
            for (int k = lane; k < DIM; k += 32) {
                float xv = g_x[k], hv = hold[k];
                s0 += wi0[k] * xv + wh0[k] * hv;
                s1 += wi1[k] * xv + wh1[k] * hv;
                s2 += wi2[k] * xv + wh2[k] * hv;
                s3 += wi3[k] * xv + wh3[k] * hv;
            }
#pragma unroll
            for (int o = 16; o; o >>= 1) {
                s0 += __shfl_xor_sync(0xffffffffu, s0, o);
                s1 += __shfl_xor_sync(0xffffffffu, s1, o);
                s2 += __shfl_xor_sync(0xffffffffu, s2, o);
                s3 += __shfl_xor_sync(0xffffffffu, s3, o);
            }
            if (!lane) {
                sg[wid][0] = s0 + b_ih[j] + b_hh[j];
                sg[wid][1] = s1 + b_ih[HID + j] + b_hh[HID + j];
                sg[wid][2] = s2 + b_ih[2 * HID + j] + b_hh[2 * HID + j];
                sg[wid][3] = s3 + b_ih[3 * HID + j] + b_hh[3 * HID + j];
            }
            __syncthreads();
            if (tid < 8) {
                int jj = kb + tid;
                float gi = sigm(sg[tid][0]);
                float gf = sigm(sg[tid][1]);
                float gg = tanhe(sg[tid][2]);
                float go = sigm(sg[tid][3]);
                float c = gf * cold[jj] + gi * gg;
                float h = go * tanhe(c);
                cnew[jj] = c;
                hnew[jj] = h;
                shh[tid] = h;
            }
            __syncthreads();
            float a0 = 0.f, a1 = 0.f;
#pragma unroll
            for (int kk = 0; kk < 8; kk++) {
                float hv = shh[kk];
                const float* wr = hop_wq + (size_t)(kb + kk) * HID;
                a0 += hv * wr[tid];
                a1 += hv * wr[tid + 256];
            }
            atomicAdd(&g_qh[tid], a0);
            atomicAdd(&g_qh[tid + 256], a1);
        }
        gridbar(nb);

        // ---- phase B: hop pass ----
        {
            if (bid == 0) { g_ba[tid] = 0.f; g_ba[tid + 256] = 0.f; }
            int gw = bid * 8 + wid;
            float q0[16], v0[16];
            {
                float4 a = *(const float4*)&g_qh[lane * 8];
                float4 b = *(const float4*)&g_qh[lane * 8 + 4];
                float4 c = *(const float4*)&g_qh[256 + lane * 8];
                float4 d = *(const float4*)&g_qh[256 + lane * 8 + 4];
                q0[0]=a.x;q0[1]=a.y;q0[2]=a.z;q0[3]=a.w; q0[4]=b.x;q0[5]=b.y;q0[6]=b.z;q0[7]=b.w;
                q0[8]=c.x;q0[9]=c.y;q0[10]=c.z;q0[11]=c.w; q0[12]=d.x;q0[13]=d.y;q0[14]=d.z;q0[15]=d.w;
                a = *(const float4*)&hop_v[lane * 8];
                b = *(const float4*)&hop_v[lane * 8 + 4];
                c = *(const float4*)&hop_v[256 + lane * 8];
                d = *(const float4*)&hop_v[256 + lane * 8 + 4];
                v0[0]=a.x;v0[1]=a.y;v0[2]=a.z;v0[3]=a.w; v0[4]=b.x;v0[5]=b.y;v0[6]=b.z;v0[7]=b.w;
                v0[8]=c.x;v0[9]=c.y;v0[10]=c.z;v0[11]=c.w; v0[12]=d.x;v0[13]=d.y;v0[14]=d.z;v0[15]=d.w;
            }
            float mx = NEGINF, sw = 0.f, acc[16];
#pragma unroll
            for (int i = 0; i < 16; i++) acc[i] = 0.f;

            for (int m = gw; m < MPTS; m += tot) {
                const uint4* rp = (const uint4*)(g_hf16 + (size_t)m * DIM);
                uint4 p0 = rp[lane];
                uint4 p1 = rp[32 + lane];
                float vals[16];
#pragma unroll
                for (int k = 0; k < 4; k++) {
                    float2 f0 = __half22float2(((const __half2*)&p0)[k]);
                    float2 f1 = __half22float2(((const __half2*)&p1)[k]);
                    vals[2*k] = f0.x; vals[2*k+1] = f0.y;
                    vals[8+2*k] = f1.x; vals[8+2*k+1] = f1.y;
                }
                float sp = 0.f;
#pragma unroll
                for (int i = 0; i < 16; i++) sp += tanha(vals[i] + q0[i]) * v0[i];
#pragma unroll
                for (int o = 16; o; o >>= 1) sp += __shfl_xor_sync(0xffffffffu, sp, o);
                if (sp > mx) {
                    float f = __expf(mx - sp);
                    sw *= f;
#pragma unroll
                    for (int i = 0; i < 16; i++) acc[i] *= f;
                    mx = sp;
                }
                float wgt = __expf(sp - mx);
                sw += wgt;
#pragma unroll
                for (int i = 0; i < 16; i++) acc[i] += wgt * vals[i];
            }
#pragma unroll
            for (int s = 0; s < 8; s++) {
                sacc[wid][lane * 8 + s] = acc[s];
                sacc[wid][256 + lane * 8 + s] = acc[8 + s];
            }
            if (!lane) { smx[wid] = mx; ssw[wid] = sw; }
            __syncthreads();

            float M = smx[0];
#pragma unroll
            for (int w = 1; w < 8; w++) M = fmaxf(M, smx[w]);
            for (int c = tid; c < 512; c += 256) {
                float a = 0.f;
#pragma unroll
                for (int w = 0; w < 8; w++) a += sacc[w][c] * __expf(smx[w] - M);
                g_hpart[bid][2 + c] = a;
            }
            if (tid == 0) {
                float W = 0.f;
#pragma unroll
                for (int w = 0; w < 8; w++) W += ssw[w] * __expf(smx[w] - M);
                g_hpart[bid][0] = M;
                g_hpart[bid][1] = W;
            }
            __syncthreads();
        }
        gridbar(nb);

        // ---- phase C: reduce hop partials + bias GEMV (blocks 0..63) ----
        if (bid < 64) {
            int kb = bid * 8;
            float m = NEGINF;
            for (int b = tid; b < nb; b += 256) m = fmaxf(m, g_hpart[b][0]);
            red[tid] = m; __syncthreads();
            for (int o = 128; o; o >>= 1) { if (tid < o) red[tid] = fmaxf(red[tid], red[tid + o]); __syncthreads(); }
            float M = red[0]; __syncthreads();

            float wsum = 0.f;
            for (int b = tid; b < nb; b += 256) wsum += __expf(g_hpart[b][0] - M) * g_hpart[b][1];
            red[tid] = wsum; __syncthreads();
            for (int o = 128; o; o >>= 1) { if (tid < o) red[tid] += red[tid + o]; __syncthreads(); }
            float W = red[0]; __syncthreads();

            {
                int g = tid >> 5, l = tid & 31;
                int k = kb + g;
                float a = 0.f;
                for (int b = l; b < nb; b += 32)
                    a += __expf(g_hpart[b][0] - M) * g_hpart[b][2 + k];
#pragma unroll
                for (int o = 16; o; o >>= 1) a += __shfl_xor_sync(0xffffffffu, a, o);
                if (l == 0) qn[g] = __fdividef(a, W);
            }
            __syncthreads();

            float a0 = 0.f, a1 = 0.f;
#pragma unroll
            for (int kk = 0; kk < 8; kk++) {
                float q = qn[kk];
                const float* wr = attn_wq + (size_t)(kb + kk) * HID;
                a0 += q * wr[tid];
                a1 += q * wr[tid + 256];
            }
            atomicAdd(&g_ba[tid], a0);
            atomicAdd(&g_ba[tid + 256], a1);
        }
        gridbar(nb);

        // ---- phase D: attn pass + ticket-fused final ----
        {
            int gw = bid * 8 + wid;
            const float* gum = gumbel + (size_t)t * MPTS;
            float b0[16], v0[16];
            {
                float4 a = *(const float4*)&g_ba[lane * 8];
                float4 b = *(const float4*)&g_ba[lane * 8 + 4];
                float4 c = *(const float4*)&g_ba[256 + lane * 8];
                float4 d = *(const float4*)&g_ba[256 + lane * 8 + 4];
                b0[0]=a.x;b0[1]=a.y;b0[2]=a.z;b0[3]=a.w; b0[4]=b.x;b0[5]=b.y;b0[6]=b.z;b0[7]=b.w;
                b0[8]=c.x;b0[9]=c.y;b0[10]=c.z;b0[11]=c.w; b0[12]=d.x;b0[13]=d.y;b0[14]=d.z;b0[15]=d.w;
                a = *(const float4*)&attn_v[lane * 8];
                b = *(const float4*)&attn_v[lane * 8 + 4];
                c = *(const float4*)&attn_v[256 + lane * 8];
                d = *(const float4*)&attn_v[256 + lane * 8 + 4];
                v0[0]=a.x;v0[1]=a.y;v0[2]=a.z;v0[3]=a.w; v0[4]=b.x;v0[5]=b.y;v0[6]=b.z;v0[7]=b.w;
                v0[8]=c.x;v0[9]=c.y;v0[10]=c.z;v0[11]=c.w; v0[12]=d.x;v0[13]=d.y;v0[14]=d.z;v0[15]=d.w;
            }
            float mxs = NEGINF, ssum = 0.f, best = NEGINF;
            int bidx = 0x7fffffff;

            for (int m = gw; m < MPTS; m += tot) {
                const uint4* rp = (const uint4*)(g_af16 + (size_t)m * DIM);
                uint4 p0 = rp[lane];
                uint4 p1 = rp[32 + lane];
                float sp = 0.f;
#pragma unroll
                for (int k = 0; k < 4; k++) {
                    float2 f0 = __half22float2(((const __half2*)&p0)[k]);
                    float2 f1 = __half22float2(((const __half2*)&p1)[k]);
                    sp += tanha(f0.x + b0[2*k])     * v0[2*k];
                    sp += tanha(f0.y + b0[2*k+1])   * v0[2*k+1];
                    sp += tanha(f1.x + b0[8+2*k])   * v0[8+2*k];
                    sp += tanha(f1.y + b0[8+2*k+1]) * v0[8+2*k+1];
                }
#pragma unroll
                for (int o = 16; o; o >>= 1) sp += __shfl_xor_sync(0xffffffffu, sp, o);
                float sc = g_sel[m] ? -1e18f : sp;
                if (sc > mxs) { ssum *= __expf(mxs - sc); mxs = sc; }
                ssum += __expf(sc - mxs);
                float tv = sc + gum[m];
                if (tv > best || (tv == best && m < bidx)) { best = tv; bidx = m; }
            }
            if (!lane) { sb[wid] = best; si[wid] = bidx; sm[wid] = mxs; ss[wid] = ssum; }
            __syncthreads();
            if (tid == 0) {
                float B = sb[0]; int I = si[0];
                float M2 = sm[0], S = ss[0];
#pragma unroll
                for (int w = 1; w < 8; w++) {
                    if (sb[w] > B || (sb[w] == B && si[w] < I)) { B = sb[w]; I = si[w]; }
                    float m2 = sm[w], s2 = ss[w];
                    if (m2 > M2) { S = S * __expf(M2 - m2) + s2; M2 = m2; }
                    else S += s2 * __expf(m2 - M2);
                }
                g_apart[bid][0] = B; g_apart[bid][1] = M2;
                g_apart[bid][2] = S; g_aidx[bid] = I;
            }

            __threadfence();
            __syncthreads();
            if (tid == 0) {
                int v = atomicAdd(&g_ticket, 1);
                islast = ((v % nb) == nb - 1);
            }
            __syncthreads();
            if (islast) {
                g_qh[tid] = 0.f; g_qh[tid + 256] = 0.f;   // for next step's atomics
                float B = NEGINF; int I = 0x7fffffff; float M = NEGINF; float S = 0.f;
                for (int b = tid; b < nb; b += 256) {
                    float bb = g_apart[b][0]; int ii = g_aidx[b];
                    if (bb > B || (bb == B && ii < I)) { B = bb; I = ii; }
                    float m2 = g_apart[b][1], s2 = g_apart[b][2];
                    if (m2 > M) { S = S * __expf(M - m2) + s2; M = m2; }
                    else S += s2 * __expf(m2 - M);
                }
                fb[tid] = B; fi[tid] = I; fm[tid] = M; fs[tid] = S;
                __syncthreads();
                for (int o = 128; o; o >>= 1) {
                    if (tid < o) {
                        if (fb[tid + o] > fb[tid] || (fb[tid + o] == fb[tid] && fi[tid + o] < fi[tid])) {
                            fb[tid] = fb[tid + o]; fi[tid] = fi[tid + o];
                        }
                        float m1 = fm[tid], s1 = fs[tid];
                        float m2 = fm[tid + o], s2 = fs[tid + o];
                        float Mn = fmaxf(m1, m2);
                        float Sn = 0.f;
                        if (s1 > 0.f) Sn += s1 * __expf(m1 - Mn);
                        if (s2 > 0.f) Sn += s2 * __expf(m2 - Mn);
                        fm[tid] = Mn; fs[tid] = Sn;
                    }
                    __syncthreads();
                }
                if (tid == 0) {
                    int done = g_done;
                    int o_ = fi[0];
                    float sc = fb[0] - gum[o_];
                    float lse = fm[0] + logf(fs[0]);
                    float logp = sc - lse;
                    out[t]          = done ? (float)NPTS : (float)o_;
                    out[TSTEPS + t] = done ? 0.f : logp;
                    if (!done) g_sel[o_] = 1;
                    int nd = done || (o_ == NPTS);
                    g_done = nd;
                    s_out = o_; s_nd = nd;
                }
                __syncthreads();
                if (!s_nd) {
                    int o_ = s_out;
                    const float* src = (o_ == NPTS) ? stop : attn_mem + (size_t)o_ * DIM;
                    g_x[tid] = src[tid];
                    g_x[tid + 256] = src[tid + 256];
                }
            }
        }
        gridbar(nb);
    }
}

// ---------------- launch ----------------
extern "C" void kernel_launch(void* const* d_in, const int* in_sizes, int n_in,
                              void* d_out, int out_size) {
    const float* attn_mem = (const float*)d_in[0];
    const float* stop     = (const float*)d_in[1];
    const float* init_h   = (const float*)d_in[2];
    const float* init_c   = (const float*)d_in[3];
    const float* init_i   = (const float*)d_in[4];
    const float* attn_wm  = (const float*)d_in[5];
    const float* attn_wq  = (const float*)d_in[6];
    const float* attn_v   = (const float*)d_in[7];
    const float* hop_wm   = (const float*)d_in[8];
    const float* hop_wq   = (const float*)d_in[9];
    const float* hop_v    = (const float*)d_in[10];
    const float* w_ih     = (const float*)d_in[11];
    const float* w_hh     = (const float*)d_in[12];
    const float* b_ih     = (const float*)d_in[13];
    const float* b_hh     = (const float*)d_in[14];
    const float* gumbel   = (const float*)d_in[15];
    float* out = (float*)d_out;

    static int nb = 0;
    if (nb == 0) {
        int sms = 0;
        cudaDeviceGetAttribute(&sms, cudaDevAttrMultiProcessorCount, 0);
        nb = 2 * sms;
        if (nb > NBMAX) nb = NBMAX;
        if (nb < 64) nb = 64;
    }

    k_init<<<(MPTS + 255) / 256, 256>>>(init_h, init_c, init_i);
    k_convA<<<8192, 256>>>(attn_mem, stop);
    k_convB<<<2048, 256>>>(attn_wm, hop_wm);

    dim3 gg(8, ROWT);
    k_feat_mma<<<gg, 256>>>();

    k_step<<<nb, 256>>>(w_ih, w_hh, b_ih, b_hh, hop_wq, hop_v,
                        attn_wq, attn_v, gumbel, attn_mem, stop, out, nb);
}

// round 10
// speedup vs baseline: 3.9739x; 1.1883x over previous
#include <cuda_runtime.h>
#include <cuda_fp16.h>
#include <cstdint>

#define NPTS   50000
#define MPTS   50001
#define DIM    512
#define HID    512
#define TSTEPS 16
#define NBMAX  320
#define NEGINF (__int_as_float(0xff800000))

#define PADM   50048           // 391 * 128
#define ROWT   391
#define NCH    16              // K = 512, 32-wide chunks

// ---------------- device scratch ----------------
__device__ __half g_af16[(size_t)MPTS * DIM];
__device__ __half g_hf16[(size_t)MPTS * DIM];
__device__ __half g_a16[(size_t)PADM * DIM];
__device__ __half g_bt[2][512][512];
__device__ float g_hbuf[2][HID];
__device__ float g_cbuf[2][HID];
__device__ float g_x[DIM];
__device__ float g_qh[HID];
__device__ float g_ba[HID];
__device__ unsigned char g_sel[MPTS];
__device__ int   g_done;
__device__ int   g_ticket;
__device__ volatile unsigned g_gen;
__device__ unsigned g_cnt;
__device__ float g_hpart[NBMAX][514];
__device__ float g_apart[NBMAX][3];
__device__ int   g_aidx[NBMAX];

// ---------------- helpers ----------------
__device__ __forceinline__ float tanhe(float x) {
    float e = __expf(2.f * x);
    return 1.f - __fdividef(2.f, e + 1.f);
}
__device__ __forceinline__ float tanha(float x) {
    float y; asm("tanh.approx.f32 %0, %1;" : "=f"(y) : "f"(x)); return y;
}
__device__ __forceinline__ float sigm(float x) {
    return __fdividef(1.f, 1.f + __expf(-x));
}
__device__ __forceinline__ uint32_t s2u(const void* p) {
    uint32_t a;
    asm("{ .reg .u64 t; cvta.to.shared.u64 t, %1; cvt.u32.u64 %0, t; }" : "=r"(a) : "l"(p));
    return a;
}
__device__ __forceinline__ void cp16(uint32_t dst, const void* src) {
    asm volatile("cp.async.cg.shared.global [%0], [%1], 16;" :: "r"(dst), "l"(src));
}
__device__ __forceinline__ void ldm4(uint32_t& r0, uint32_t& r1, uint32_t& r2, uint32_t& r3,
                                     uint32_t addr) {
    asm volatile("ldmatrix.sync.aligned.m8n8.x4.shared.b16 {%0,%1,%2,%3}, [%4];"
                 : "=r"(r0), "=r"(r1), "=r"(r2), "=r"(r3) : "r"(addr));
}
__device__ __forceinline__ void mma16816(float* c, uint32_t a0, uint32_t a1, uint32_t a2,
                                         uint32_t a3, uint32_t b0, uint32_t b1) {
    asm volatile(
        "mma.sync.aligned.m16n8k16.row.col.f32.f16.f16.f32 "
        "{%0,%1,%2,%3},{%4,%5,%6,%7},{%8,%9},{%0,%1,%2,%3};"
        : "+f"(c[0]), "+f"(c[1]), "+f"(c[2]), "+f"(c[3])
        : "r"(a0), "r"(a1), "r"(a2), "r"(a3), "r"(b0), "r"(b1));
}
__device__ __forceinline__ unsigned pkh2(float a, float b) {
    __half2 h = __floats2half2_rn(a, b);
    return *(unsigned*)&h;
}

// grid barrier
__device__ __forceinline__ void gridbar(int nb) {
    __threadfence();
    __syncthreads();
    if (threadIdx.x == 0) {
        unsigned gen = g_gen;
        unsigned v = atomicAdd(&g_cnt, 1);
        if (v == (unsigned)(nb - 1)) {
            g_cnt = 0;
            __threadfence();
            g_gen = gen + 1;
        } else {
            while (g_gen == gen) __nanosleep(64);
        }
    }
    __syncthreads();
}

// ---------------- K0: state init ----------------
__global__ void k_init(const float* __restrict__ ih, const float* __restrict__ ic,
                       const float* __restrict__ ii) {
    int i = blockIdx.x * blockDim.x + threadIdx.x;
    if (i < MPTS) g_sel[i] = 0;
    if (i < HID) { g_hbuf[0][i] = ih[i]; g_cbuf[0][i] = ic[i]; g_x[i] = ii[i]; g_qh[i] = 0.f; }
    if (i == 0) { g_done = 0; g_ticket = 0; g_gen = 0; g_cnt = 0; }
}

// ---------------- convert A ----------------
__global__ void k_convA(const float* __restrict__ mem, const float* __restrict__ stop) {
    const int total4 = PADM * DIM / 4;
    for (int i = blockIdx.x * blockDim.x + threadIdx.x; i < total4;
         i += gridDim.x * blockDim.x) {
        int row = i >> 7;
        int c4 = (i & 127) * 4;
        float4 v;
        if (row < NPTS)       v = *(const float4*)&mem[(size_t)row * DIM + c4];
        else if (row == NPTS) v = *(const float4*)&stop[c4];
        else                  v = make_float4(0.f, 0.f, 0.f, 0.f);
        uint2 ph;
        ph.x = pkh2(v.x, v.y); ph.y = pkh2(v.z, v.w);
        ((uint2*)g_a16)[i] = ph;
    }
}

// ---------------- convert B ----------------
__global__ void k_convB(const float* __restrict__ attn_wm, const float* __restrict__ hop_wm) {
    int id = blockIdx.x * blockDim.x + threadIdx.x;
    if (id >= 2 * 512 * 512) return;
    int w = id >> 18;
    int r = id & 262143;
    int n = r >> 9;
    int k = r & 511;
    const float* src = w ? hop_wm : attn_wm;
    g_bt[w][n][k] = __float2half_rn(src[(size_t)k * 512 + n]);
}

// ---------------- GEMM: fp16 mma.sync, CTA 128x128, K=512 (unchanged) ----------------
__global__ void __launch_bounds__(256, 2) k_feat_mma() {
    __shared__ __align__(16) __half sA[2][128 * 40];
    __shared__ __align__(16) __half sB[2][128 * 40];
    int tid = threadIdx.x, wid = tid >> 5, lane = tid & 31;
    int rowBase = blockIdx.y * 128;
    int colBase = (blockIdx.x >> 1) * 128;
    int mat = blockIdx.x & 1;
    const __half* bsrc = &g_bt[mat][colBase][0];
    __half* outp = mat ? g_hf16 : g_af16;
    const __half* asrc = g_a16 + (size_t)rowBase * DIM;
    int wm = wid >> 1, wn = wid & 1;

    float acc[2][8][4];
#pragma unroll
    for (int mt = 0; mt < 2; mt++)
#pragma unroll
        for (int j = 0; j < 8; j++)
#pragma unroll
            for (int e = 0; e < 4; e++) acc[mt][j][e] = 0.f;

    uint32_t uA0 = s2u(&sA[0][0]), uB0 = s2u(&sB[0][0]);
    const uint32_t bufStride = 128 * 40 * 2;

    auto load = [&](int c, int buf) {
        const __half* A = asrc + c * 32;
        const __half* B = bsrc + c * 32;
        uint32_t dA = uA0 + buf * bufStride;
        uint32_t dB = uB0 + buf * bufStride;
#pragma unroll
        for (int i = 0; i < 2; i++) {
            int idx = i * 256 + tid;
            int r = idx >> 2, ch = idx & 3;
            cp16(dA + r * 80 + ch * 16, (const char*)(A + (size_t)r * 512) + ch * 16);
            cp16(dB + r * 80 + ch * 16, (const char*)(B + (size_t)r * 512) + ch * 16);
        }
        asm volatile("cp.async.commit_group;" ::: "memory");
    };

    load(0, 0);
    for (int c = 0; c < NCH; c++) {
        int buf = c & 1;
        if (c + 1 < NCH) load(c + 1, buf ^ 1);
        if (c + 1 < NCH)
            asm volatile("cp.async.wait_group 1;" ::: "memory");
        else
            asm volatile("cp.async.wait_group 0;" ::: "memory");
        __syncthreads();

        uint32_t bA = uA0 + buf * bufStride;
        uint32_t bB = uB0 + buf * bufStride;
#pragma unroll
        for (int ks = 0; ks < 2; ks++) {
            uint32_t a[2][4];
#pragma unroll
            for (int mt = 0; mt < 2; mt++) {
                int row = wm * 32 + mt * 16 + (lane & 15);
                int col = ks * 16 + (lane >> 4) * 8;
                ldm4(a[mt][0], a[mt][1], a[mt][2], a[mt][3], bA + (row * 40 + col) * 2);
            }
            uint32_t b[4][4];
#pragma unroll
            for (int p = 0; p < 4; p++) {
                int q = lane >> 3, rr = lane & 7;
                int n = wn * 64 + p * 16 + (q >> 1) * 8 + rr;
                int col = ks * 16 + (q & 1) * 8;
                ldm4(b[p][0], b[p][1], b[p][2], b[p][3], bB + (n * 40 + col) * 2);
            }
#pragma unroll
            for (int mt = 0; mt < 2; mt++)
#pragma unroll
                for (int j = 0; j < 8; j++)
                    mma16816(acc[mt][j], a[mt][0], a[mt][1], a[mt][2], a[mt][3],
                             b[j >> 1][(j & 1) * 2], b[j >> 1][(j & 1) * 2 + 1]);
        }
        __syncthreads();
    }

    int g = lane >> 2, tq = lane & 3;
#pragma unroll
    for (int mt = 0; mt < 2; mt++) {
        int r0 = rowBase + wm * 32 + mt * 16 + g;
#pragma unroll
        for (int j = 0; j < 8; j++) {
            int cc = colBase + wn * 64 + j * 8 + tq * 2;
            if (r0 < MPTS)
                *(__half2*)&outp[(size_t)r0 * DIM + cc] =
                    __floats2half2_rn(acc[mt][j][0], acc[mt][j][1]);
            if (r0 + 8 < MPTS)
                *(__half2*)&outp[(size_t)(r0 + 8) * DIM + cc] =
                    __floats2half2_rn(acc[mt][j][2], acc[mt][j][3]);
        }
    }
}

// ================= persistent step megakernel =================
__global__ void __launch_bounds__(256, 2) k_step(
    const float* __restrict__ w_ih, const float* __restrict__ w_hh,
    const float* __restrict__ b_ih, const float* __restrict__ b_hh,
    const float* __restrict__ hop_wq, const float* __restrict__ hop_v,
    const float* __restrict__ attn_wq, const float* __restrict__ attn_v,
    const float* __restrict__ gumbel, const float* __restrict__ attn_mem,
    const float* __restrict__ stop, float* __restrict__ out, int nb)
{
    __shared__ float sg[8][4];
    __shared__ float shh[8];
    __shared__ float smx[8], ssw[8], sacc[8][512];
    __shared__ float red[256];
    __shared__ float qn[8];
    __shared__ float sb[8]; __shared__ int si[8];
    __shared__ float sm[8]; __shared__ float ss[8];
    __shared__ float fb[256]; __shared__ int fi[256];
    __shared__ float fm[256]; __shared__ float fs[256];
    __shared__ int s_out, s_nd, islast;

    int bid = blockIdx.x;
    int tid = threadIdx.x, wid = tid >> 5, lane = tid & 31;
    const int tot = nb * 8;

    for (int t = 0; t < TSTEPS; t++) {
        // ---- phase A: gates + h,c + qh GEMV (blocks 0..63) ----
        if (bid < 64) {
            int kb = bid * 8;
            const float* hold = g_hbuf[t & 1];
            float* hnew = g_hbuf[(t + 1) & 1];
            const float* cold = g_cbuf[t & 1];
            float* cnew = g_cbuf[(t + 1) & 1];
            int j = kb + wid;
            const float* wi0 = w_ih + (size_t)j * DIM;
            const float* wi1 = w_ih + (size_t)(HID + j) * DIM;
            const float* wi2 = w_ih + (size_t)(2 * HID + j) * DIM;
            const float* wi3 = w_ih + (size_t)(3 * HID + j) * DIM;
            const float* wh0 = w_hh + (size_t)j * HID;
            const float* wh1 = w_hh + (size_t)(HID + j) * HID;
            const float* wh2 = w_hh + (size_t)(2 * HID + j) * HID;
            const float* wh3 = w_hh + (size_t)(3 * HID + j) * HID;
            float s0 = 0.f, s1 = 0.f, s2 = 0.f, s3 = 0.f;
#pragma unroll 4
            for (int k = lane; k < DIM; k += 32) {
                float xv = g_x[k], hv = hold[k];
                s0 += wi0[k] * xv + wh0[k] * hv;
                s1 += wi1[k] * xv + wh1[k] * hv;
                s2 += wi2[k] * xv + wh2[k] * hv;
                s3 += wi3[k] * xv + wh3[k] * hv;
            }
#pragma unroll
            for (int o = 16; o; o >>= 1) {
                s0 += __shfl_xor_sync(0xffffffffu, s0, o);
                s1 += __shfl_xor_sync(0xffffffffu, s1, o);
                s2 += __shfl_xor_sync(0xffffffffu, s2, o);
                s3 += __shfl_xor_sync(0xffffffffu, s3, o);
            }
            if (!lane) {
                sg[wid][0] = s0 + b_ih[j] + b_hh[j];
                sg[wid][1] = s1 + b_ih[HID + j] + b_hh[HID + j];
                sg[wid][2] = s2 + b_ih[2 * HID + j] + b_hh[2 * HID + j];
                sg[wid][3] = s3 + b_ih[3 * HID + j] + b_hh[3 * HID + j];
            }
            __syncthreads();
            if (tid < 8) {
                int jj = kb + tid;
                float gi = sigm(sg[tid][0]);
                float gf = sigm(sg[tid][1]);
                float gg = tanhe(sg[tid][2]);
                float go = sigm(sg[tid][3]);
                float c = gf * cold[jj] + gi * gg;
                float h = go * tanhe(c);
                cnew[jj] = c;
                hnew[jj] = h;
                shh[tid] = h;
            }
            __syncthreads();
            float a0 = 0.f, a1 = 0.f;
#pragma unroll
            for (int kk = 0; kk < 8; kk++) {
                float hv = shh[kk];
                const float* wr = hop_wq + (size_t)(kb + kk) * HID;
                a0 += hv * wr[tid];
                a1 += hv * wr[tid + 256];
            }
            atomicAdd(&g_qh[tid], a0);
            atomicAdd(&g_qh[tid + 256], a1);
        }
        gridbar(nb);

        // ---- phase B: hop pass (2 rows / iter for MLP) ----
        {
            if (bid == 0) { g_ba[tid] = 0.f; g_ba[tid + 256] = 0.f; }
            int gw = bid * 8 + wid;
            float q0[16], v0[16];
            {
                float4 a = *(const float4*)&g_qh[lane * 8];
                float4 b = *(const float4*)&g_qh[lane * 8 + 4];
                float4 c = *(const float4*)&g_qh[256 + lane * 8];
                float4 d = *(const float4*)&g_qh[256 + lane * 8 + 4];
                q0[0]=a.x;q0[1]=a.y;q0[2]=a.z;q0[3]=a.w; q0[4]=b.x;q0[5]=b.y;q0[6]=b.z;q0[7]=b.w;
                q0[8]=c.x;q0[9]=c.y;q0[10]=c.z;q0[11]=c.w; q0[12]=d.x;q0[13]=d.y;q0[14]=d.z;q0[15]=d.w;
                a = *(const float4*)&hop_v[lane * 8];
                b = *(const float4*)&hop_v[lane * 8 + 4];
                c = *(const float4*)&hop_v[256 + lane * 8];
                d = *(const float4*)&hop_v[256 + lane * 8 + 4];
                v0[0]=a.x;v0[1]=a.y;v0[2]=a.z;v0[3]=a.w; v0[4]=b.x;v0[5]=b.y;v0[6]=b.z;v0[7]=b.w;
                v0[8]=c.x;v0[9]=c.y;v0[10]=c.z;v0[11]=c.w; v0[12]=d.x;v0[13]=d.y;v0[14]=d.z;v0[15]=d.w;
            }
            float mx = NEGINF, sw = 0.f, acc[16];
#pragma unroll
            for (int i = 0; i < 16; i++) acc[i] = 0.f;

            for (int m0 = gw * 2; m0 < MPTS; m0 += 2 * tot) {
                int m1 = m0 + 1;
                bool vb = (m1 < MPTS);
                const uint4* ra = (const uint4*)(g_hf16 + (size_t)m0 * DIM);
                uint4 a0 = ra[lane];
                uint4 a1 = ra[32 + lane];
                uint4 b0p, b1p;
                if (vb) {
                    const uint4* rb = (const uint4*)(g_hf16 + (size_t)m1 * DIM);
                    b0p = rb[lane];
                    b1p = rb[32 + lane];
                }
                float sp_a = 0.f, sp_b = 0.f;
#pragma unroll
                for (int k = 0; k < 4; k++) {
                    float2 f0 = __half22float2(((const __half2*)&a0)[k]);
                    float2 f1 = __half22float2(((const __half2*)&a1)[k]);
                    sp_a += tanha(f0.x + q0[2*k])     * v0[2*k];
                    sp_a += tanha(f0.y + q0[2*k+1])   * v0[2*k+1];
                    sp_a += tanha(f1.x + q0[8+2*k])   * v0[8+2*k];
                    sp_a += tanha(f1.y + q0[8+2*k+1]) * v0[8+2*k+1];
                }
                if (vb) {
#pragma unroll
                    for (int k = 0; k < 4; k++) {
                        float2 f0 = __half22float2(((const __half2*)&b0p)[k]);
                        float2 f1 = __half22float2(((const __half2*)&b1p)[k]);
                        sp_b += tanha(f0.x + q0[2*k])     * v0[2*k];
                        sp_b += tanha(f0.y + q0[2*k+1])   * v0[2*k+1];
                        sp_b += tanha(f1.x + q0[8+2*k])   * v0[8+2*k];
                        sp_b += tanha(f1.y + q0[8+2*k+1]) * v0[8+2*k+1];
                    }
                }
#pragma unroll
                for (int o = 16; o; o >>= 1) {
                    sp_a += __shfl_xor_sync(0xffffffffu, sp_a, o);
                    sp_b += __shfl_xor_sync(0xffffffffu, sp_b, o);
                }
                // row m0 update
                if (sp_a > mx) {
                    float f = __expf(mx - sp_a);
                    sw *= f;
#pragma unroll
                    for (int i = 0; i < 16; i++) acc[i] *= f;
                    mx = sp_a;
                }
                {
                    float wgt = __expf(sp_a - mx);
                    sw += wgt;
#pragma unroll
                    for (int k = 0; k < 4; k++) {
                        float2 f0 = __half22float2(((const __half2*)&a0)[k]);
                        float2 f1 = __half22float2(((const __half2*)&a1)[k]);
                        acc[2*k]     += wgt * f0.x;
                        acc[2*k+1]   += wgt * f0.y;
                        acc[8+2*k]   += wgt * f1.x;
                        acc[8+2*k+1] += wgt * f1.y;
                    }
                }
                // row m1 update
                if (vb) {
                    if (sp_b > mx) {
                        float f = __expf(mx - sp_b);
                        sw *= f;
#pragma unroll
                        for (int i = 0; i < 16; i++) acc[i] *= f;
                        mx = sp_b;
                    }
                    float wgt = __expf(sp_b - mx);
                    sw += wgt;
#pragma unroll
                    for (int k = 0; k < 4; k++) {
                        float2 f0 = __half22float2(((const __half2*)&b0p)[k]);
                        float2 f1 = __half22float2(((const __half2*)&b1p)[k]);
                        acc[2*k]     += wgt * f0.x;
                        acc[2*k+1]   += wgt * f0.y;
                        acc[8+2*k]   += wgt * f1.x;
                        acc[8+2*k+1] += wgt * f1.y;
                    }
                }
            }
#pragma unroll
            for (int s = 0; s < 8; s++) {
                sacc[wid][lane * 8 + s] = acc[s];
                sacc[wid][256 + lane * 8 + s] = acc[8 + s];
            }
            if (!lane) { smx[wid] = mx; ssw[wid] = sw; }
            __syncthreads();

            float M = smx[0];
#pragma unroll
            for (int w = 1; w < 8; w++) M = fmaxf(M, smx[w]);
            for (int c = tid; c < 512; c += 256) {
                float a = 0.f;
#pragma unroll
                for (int w = 0; w < 8; w++) a += sacc[w][c] * __expf(smx[w] - M);
                g_hpart[bid][2 + c] = a;
            }
            if (tid == 0) {
                float W = 0.f;
#pragma unroll
                for (int w = 0; w < 8; w++) W += ssw[w] * __expf(smx[w] - M);
                g_hpart[bid][0] = M;
                g_hpart[bid][1] = W;
            }
            __syncthreads();
        }
        gridbar(nb);

        // ---- phase C: reduce hop partials + bias GEMV (blocks 0..63) ----
        if (bid < 64) {
            int kb = bid * 8;
            float m = NEGINF;
            for (int b = tid; b < nb; b += 256) m = fmaxf(m, g_hpart[b][0]);
            red[tid] = m; __syncthreads();
            for (int o = 128; o; o >>= 1) { if (tid < o) red[tid] = fmaxf(red[tid], red[tid + o]); __syncthreads(); }
            float M = red[0]; __syncthreads();

            float wsum = 0.f;
            for (int b = tid; b < nb; b += 256) wsum += __expf(g_hpart[b][0] - M) * g_hpart[b][1];
            red[tid] = wsum; __syncthreads();
            for (int o = 128; o; o >>= 1) { if (tid < o) red[tid] += red[tid + o]; __syncthreads(); }
            float W = red[0]; __syncthreads();

            {
                int g = tid >> 5, l = tid & 31;
                int k = kb + g;
                float a = 0.f;
                for (int b = l; b < nb; b += 32)
                    a += __expf(g_hpart[b][0] - M) * g_hpart[b][2 + k];
#pragma unroll
                for (int o = 16; o; o >>= 1) a += __shfl_xor_sync(0xffffffffu, a, o);
                if (l == 0) qn[g] = __fdividef(a, W);
            }
            __syncthreads();

            float a0 = 0.f, a1 = 0.f;
#pragma unroll
            for (int kk = 0; kk < 8; kk++) {
                float q = qn[kk];
                const float* wr = attn_wq + (size_t)(kb + kk) * HID;
                a0 += q * wr[tid];
                a1 += q * wr[tid + 256];
            }
            atomicAdd(&g_ba[tid], a0);
            atomicAdd(&g_ba[tid + 256], a1);
        }
        gridbar(nb);

        // ---- phase D: attn pass (4 rows / iter) + ticket-fused final ----
        {
            int gw = bid * 8 + wid;
            const float* gum = gumbel + (size_t)t * MPTS;
            float b0[16], v0[16];
            {
                float4 a = *(const float4*)&g_ba[lane * 8];
                float4 b = *(const float4*)&g_ba[lane * 8 + 4];
                float4 c = *(const float4*)&g_ba[256 + lane * 8];
                float4 d = *(const float4*)&g_ba[256 + lane * 8 + 4];
                b0[0]=a.x;b0[1]=a.y;b0[2]=a.z;b0[3]=a.w; b0[4]=b.x;b0[5]=b.y;b0[6]=b.z;b0[7]=b.w;
                b0[8]=c.x;b0[9]=c.y;b0[10]=c.z;b0[11]=c.w; b0[12]=d.x;b0[13]=d.y;b0[14]=d.z;b0[15]=d.w;
                a = *(const float4*)&attn_v[lane * 8];
                b = *(const float4*)&attn_v[lane * 8 + 4];
                c = *(const float4*)&attn_v[256 + lane * 8];
                d = *(const float4*)&attn_v[256 + lane * 8 + 4];
                v0[0]=a.x;v0[1]=a.y;v0[2]=a.z;v0[3]=a.w; v0[4]=b.x;v0[5]=b.y;v0[6]=b.z;v0[7]=b.w;
                v0[8]=c.x;v0[9]=c.y;v0[10]=c.z;v0[11]=c.w; v0[12]=d.x;v0[13]=d.y;v0[14]=d.z;v0[15]=d.w;
            }
            float mxs = NEGINF, ssum = 0.f, best = NEGINF;
            int bidx = 0x7fffffff;

            for (int m0 = gw * 4; m0 < MPTS; m0 += 4 * tot) {
                uint4 p[4][2];
                int nrow = MPTS - m0;
                if (nrow > 4) nrow = 4;
#pragma unroll
                for (int r = 0; r < 4; r++) {
                    if (r < nrow) {
                        const uint4* rp = (const uint4*)(g_af16 + (size_t)(m0 + r) * DIM);
                        p[r][0] = rp[lane];
                        p[r][1] = rp[32 + lane];
                    }
                }
#pragma unroll
                for (int r = 0; r < 4; r++) {
                    if (r >= nrow) break;
                    int m = m0 + r;
                    float sp = 0.f;
#pragma unroll
                    for (int k = 0; k < 4; k++) {
                        float2 f0 = __half22float2(((const __half2*)&p[r][0])[k]);
                        float2 f1 = __half22float2(((const __half2*)&p[r][1])[k]);
                        sp += tanha(f0.x + b0[2*k])     * v0[2*k];
                        sp += tanha(f0.y + b0[2*k+1])   * v0[2*k+1];
                        sp += tanha(f1.x + b0[8+2*k])   * v0[8+2*k];
                        sp += tanha(f1.y + b0[8+2*k+1]) * v0[8+2*k+1];
                    }
#pragma unroll
                    for (int o = 16; o; o >>= 1) sp += __shfl_xor_sync(0xffffffffu, sp, o);
                    float sc = g_sel[m] ? -1e18f : sp;
                    if (sc > mxs) { ssum *= __expf(mxs - sc); mxs = sc; }
                    ssum += __expf(sc - mxs);
                    float tv = sc + gum[m];
                    if (tv > best || (tv == best && m < bidx)) { best = tv; bidx = m; }
                }
            }
            if (!lane) { sb[wid] = best; si[wid] = bidx; sm[wid] = mxs; ss[wid] = ssum; }
            __syncthreads();
            if (tid == 0) {
                float B = sb[0]; int I = si[0];
                float M2 = sm[0], S = ss[0];
#pragma unroll
                for (int w = 1; w < 8; w++) {
                    if (sb[w] > B || (sb[w] == B && si[w] < I)) { B = sb[w]; I = si[w]; }
                    float m2 = sm[w], s2 = ss[w];
                    if (m2 > M2) { S = S * __expf(M2 - m2) + s2; M2 = m2; }
                    else S += s2 * __expf(m2 - M2);
                }
                g_apart[bid][0] = B; g_apart[bid][1] = M2;
                g_apart[bid][2] = S; g_aidx[bid] = I;
            }

            __threadfence();
            __syncthreads();
            if (tid == 0) {
                int v = atomicAdd(&g_ticket, 1);
                islast = ((v % nb) == nb - 1);
            }
            __syncthreads();
            if (islast) {
                g_qh[tid] = 0.f; g_qh[tid + 256] = 0.f;
                float B = NEGINF; int I = 0x7fffffff; float M = NEGINF; float S = 0.f;
                for (int b = tid; b < nb; b += 256) {
                    float bb = g_apart[b][0]; int ii = g_aidx[b];
                    if (bb > B || (bb == B && ii < I)) { B = bb; I = ii; }
                    float m2 = g_apart[b][1], s2 = g_apart[b][2];
                    if (m2 > M) { S = S * __expf(M - m2) + s2; M = m2; }
                    else S += s2 * __expf(m2 - M);
                }
                fb[tid] = B; fi[tid] = I; fm[tid] = M; fs[tid] = S;
                __syncthreads();
                for (int o = 128; o; o >>= 1) {
                    if (tid < o) {
                        if (fb[tid + o] > fb[tid] || (fb[tid + o] == fb[tid] && fi[tid + o] < fi[tid])) {
                            fb[tid] = fb[tid + o]; fi[tid] = fi[tid + o];
                        }
                        float m1 = fm[tid], s1 = fs[tid];
                        float m2 = fm[tid + o], s2 = fs[tid + o];
                        float Mn = fmaxf(m1, m2);
                        float Sn = 0.f;
                        if (s1 > 0.f) Sn += s1 * __expf(m1 - Mn);
                        if (s2 > 0.f) Sn += s2 * __expf(m2 - Mn);
                        fm[tid] = Mn; fs[tid] = Sn;
                    }
                    __syncthreads();
                }
                if (tid == 0) {
                    int done = g_done;
                    int o_ = fi[0];
                    float sc = fb[0] - gum[o_];
                    float lse = fm[0] + logf(fs[0]);
                    float logp = sc - lse;
                    out[t]          = done ? (float)NPTS : (float)o_;
                    out[TSTEPS + t] = done ? 0.f : logp;
                    if (!done) g_sel[o_] = 1;
                    int nd = done || (o_ == NPTS);
                    g_done = nd;
                    s_out = o_; s_nd = nd;
                }
                __syncthreads();
                if (!s_nd) {
                    int o_ = s_out;
                    const float* src = (o_ == NPTS) ? stop : attn_mem + (size_t)o_ * DIM;
                    g_x[tid] = src[tid];
                    g_x[tid + 256] = src[tid + 256];
                }
            }
        }
        gridbar(nb);
    }
}

// ---------------- launch ----------------
extern "C" void kernel_launch(void* const* d_in, const int* in_sizes, int n_in,
                              void* d_out, int out_size) {
    const float* attn_mem = (const float*)d_in[0];
    const float* stop     = (const float*)d_in[1];
    const float* init_h   = (const float*)d_in[2];
    const float* init_c   = (const float*)d_in[3];
    const float* init_i   = (const float*)d_in[4];
    const float* attn_wm  = (const float*)d_in[5];
    const float* attn_wq  = (const float*)d_in[6];
    const float* attn_v   = (const float*)d_in[7];
    const float* hop_wm   = (const float*)d_in[8];
    const float* hop_wq   = (const float*)d_in[9];
    const float* hop_v    = (const float*)d_in[10];
    const float* w_ih     = (const float*)d_in[11];
    const float* w_hh     = (const float*)d_in[12];
    const float* b_ih     = (const float*)d_in[13];
    const float* b_hh     = (const float*)d_in[14];
    const float* gumbel   = (const float*)d_in[15];
    float* out = (float*)d_out;

    static int nb = 0;
    if (nb == 0) {
        int sms = 0;
        cudaDeviceGetAttribute(&sms, cudaDevAttrMultiProcessorCount, 0);
        nb = 2 * sms;
        if (nb > NBMAX) nb = NBMAX;
        if (nb < 64) nb = 64;
    }

    k_init<<<(MPTS + 255) / 256, 256>>>(init_h, init_c, init_i);
    k_convA<<<8192, 256>>>(attn_mem, stop);
    k_convB<<<2048, 256>>>(attn_wm, hop_wm);

    dim3 gg(8, ROWT);
    k_feat_mma<<<gg, 256>>>();

    k_step<<<nb, 256>>>(w_ih, w_hh, b_ih, b_hh, hop_wq, hop_v,
                        attn_wq, attn_v, gumbel, attn_mem, stop, out, nb);
}

// round 11
// speedup vs baseline: 4.0062x; 1.0081x over previous
#include <cuda_runtime.h>
#include <cuda_fp16.h>
#include <cstdint>

#define NPTS   50000
#define MPTS   50001
#define DIM    512
#define HID    512
#define TSTEPS 16
#define NBMAX  320
#define NEGINF (__int_as_float(0xff800000))

#define PADM   50048           // 391 * 128
#define ROWT   391
#define NCH    16              // K = 512, 32-wide chunks

// ---------------- device scratch ----------------
__device__ __half g_af16[(size_t)MPTS * DIM];
__device__ __half g_hf16[(size_t)MPTS * DIM];
__device__ __half g_a16[(size_t)PADM * DIM];
__device__ __half g_bt[2][512][512];
__device__ float g_hbuf[2][HID];
__device__ float g_cbuf[2][HID];
__device__ float g_x[DIM];
__device__ float g_qh[HID];
__device__ float g_ba[HID];
__device__ unsigned char g_sel[MPTS];
__device__ int   g_done;
__device__ int   g_ticket;
__device__ volatile unsigned g_gen;
__device__ unsigned g_cnt;
__device__ float g_hpart[NBMAX][514];
__device__ float g_apart[NBMAX][3];
__device__ int   g_aidx[NBMAX];

// ---------------- helpers ----------------
__device__ __forceinline__ float tanhe(float x) {
    float e = __expf(2.f * x);
    return 1.f - __fdividef(2.f, e + 1.f);
}
__device__ __forceinline__ float tanha(float x) {
    float y; asm("tanh.approx.f32 %0, %1;" : "=f"(y) : "f"(x)); return y;
}
__device__ __forceinline__ float sigm(float x) {
    return __fdividef(1.f, 1.f + __expf(-x));
}
__device__ __forceinline__ uint32_t s2u(const void* p) {
    uint32_t a;
    asm("{ .reg .u64 t; cvta.to.shared.u64 t, %1; cvt.u32.u64 %0, t; }" : "=r"(a) : "l"(p));
    return a;
}
__device__ __forceinline__ void cp16(uint32_t dst, const void* src) {
    asm volatile("cp.async.cg.shared.global [%0], [%1], 16;" :: "r"(dst), "l"(src));
}
__device__ __forceinline__ void ldm4(uint32_t& r0, uint32_t& r1, uint32_t& r2, uint32_t& r3,
                                     uint32_t addr) {
    asm volatile("ldmatrix.sync.aligned.m8n8.x4.shared.b16 {%0,%1,%2,%3}, [%4];"
                 : "=r"(r0), "=r"(r1), "=r"(r2), "=r"(r3) : "r"(addr));
}
__device__ __forceinline__ void mma16816(float* c, uint32_t a0, uint32_t a1, uint32_t a2,
                                         uint32_t a3, uint32_t b0, uint32_t b1) {
    asm volatile(
        "mma.sync.aligned.m16n8k16.row.col.f32.f16.f16.f32 "
        "{%0,%1,%2,%3},{%4,%5,%6,%7},{%8,%9},{%0,%1,%2,%3};"
        : "+f"(c[0]), "+f"(c[1]), "+f"(c[2]), "+f"(c[3])
        : "r"(a0), "r"(a1), "r"(a2), "r"(a3), "r"(b0), "r"(b1));
}
__device__ __forceinline__ unsigned pkh2(float a, float b) {
    __half2 h = __floats2half2_rn(a, b);
    return *(unsigned*)&h;
}

// grid barrier
__device__ __forceinline__ void gridbar(int nb) {
    __threadfence();
    __syncthreads();
    if (threadIdx.x == 0) {
        unsigned gen = g_gen;
        unsigned v = atomicAdd(&g_cnt, 1);
        if (v == (unsigned)(nb - 1)) {
            g_cnt = 0;
            __threadfence();
            g_gen = gen + 1;
        } else {
            while (g_gen == gen) __nanosleep(64);
        }
    }
    __syncthreads();
}

// ---------------- K0: state init ----------------
__global__ void k_init(const float* __restrict__ ih, const float* __restrict__ ic,
                       const float* __restrict__ ii) {
    int i = blockIdx.x * blockDim.x + threadIdx.x;
    if (i < MPTS) g_sel[i] = 0;
    if (i < HID) { g_hbuf[0][i] = ih[i]; g_cbuf[0][i] = ic[i]; g_x[i] = ii[i]; g_qh[i] = 0.f; }
    if (i == 0) { g_done = 0; g_ticket = 0; g_gen = 0; g_cnt = 0; }
}

// ---------------- convert A ----------------
__global__ void k_convA(const float* __restrict__ mem, const float* __restrict__ stop) {
    const int total4 = PADM * DIM / 4;
    for (int i = blockIdx.x * blockDim.x + threadIdx.x; i < total4;
         i += gridDim.x * blockDim.x) {
        int row = i >> 7;
        int c4 = (i & 127) * 4;
        float4 v;
        if (row < NPTS)       v = *(const float4*)&mem[(size_t)row * DIM + c4];
        else if (row == NPTS) v = *(const float4*)&stop[c4];
        else                  v = make_float4(0.f, 0.f, 0.f, 0.f);
        uint2 ph;
        ph.x = pkh2(v.x, v.y); ph.y = pkh2(v.z, v.w);
        ((uint2*)g_a16)[i] = ph;
    }
}

// ---------------- convert B ----------------
__global__ void k_convB(const float* __restrict__ attn_wm, const float* __restrict__ hop_wm) {
    int id = blockIdx.x * blockDim.x + threadIdx.x;
    if (id >= 2 * 512 * 512) return;
    int w = id >> 18;
    int r = id & 262143;
    int n = r >> 9;
    int k = r & 511;
    const float* src = w ? hop_wm : attn_wm;
    g_bt[w][n][k] = __float2half_rn(src[(size_t)k * 512 + n]);
}

// ---------------- GEMM: fp16 mma.sync, CTA 128x128, K=512 (unchanged) ----------------
__global__ void __launch_bounds__(256, 2) k_feat_mma() {
    __shared__ __align__(16) __half sA[2][128 * 40];
    __shared__ __align__(16) __half sB[2][128 * 40];
    int tid = threadIdx.x, wid = tid >> 5, lane = tid & 31;
    int rowBase = blockIdx.y * 128;
    int colBase = (blockIdx.x >> 1) * 128;
    int mat = blockIdx.x & 1;
    const __half* bsrc = &g_bt[mat][colBase][0];
    __half* outp = mat ? g_hf16 : g_af16;
    const __half* asrc = g_a16 + (size_t)rowBase * DIM;
    int wm = wid >> 1, wn = wid & 1;

    float acc[2][8][4];
#pragma unroll
    for (int mt = 0; mt < 2; mt++)
#pragma unroll
        for (int j = 0; j < 8; j++)
#pragma unroll
            for (int e = 0; e < 4; e++) acc[mt][j][e] = 0.f;

    uint32_t uA0 = s2u(&sA[0][0]), uB0 = s2u(&sB[0][0]);
    const uint32_t bufStride = 128 * 40 * 2;

    auto load = [&](int c, int buf) {
        const __half* A = asrc + c * 32;
        const __half* B = bsrc + c * 32;
        uint32_t dA = uA0 + buf * bufStride;
        uint32_t dB = uB0 + buf * bufStride;
#pragma unroll
        for (int i = 0; i < 2; i++) {
            int idx = i * 256 + tid;
            int r = idx >> 2, ch = idx & 3;
            cp16(dA + r * 80 + ch * 16, (const char*)(A + (size_t)r * 512) + ch * 16);
            cp16(dB + r * 80 + ch * 16, (const char*)(B + (size_t)r * 512) + ch * 16);
        }
        asm volatile("cp.async.commit_group;" ::: "memory");
    };

    load(0, 0);
    for (int c = 0; c < NCH; c++) {
        int buf = c & 1;
        if (c + 1 < NCH) load(c + 1, buf ^ 1);
        if (c + 1 < NCH)
            asm volatile("cp.async.wait_group 1;" ::: "memory");
        else
            asm volatile("cp.async.wait_group 0;" ::: "memory");
        __syncthreads();

        uint32_t bA = uA0 + buf * bufStride;
        uint32_t bB = uB0 + buf * bufStride;
#pragma unroll
        for (int ks = 0; ks < 2; ks++) {
            uint32_t a[2][4];
#pragma unroll
            for (int mt = 0; mt < 2; mt++) {
                int row = wm * 32 + mt * 16 + (lane & 15);
                int col = ks * 16 + (lane >> 4) * 8;
                ldm4(a[mt][0], a[mt][1], a[mt][2], a[mt][3], bA + (row * 40 + col) * 2);
            }
            uint32_t b[4][4];
#pragma unroll
            for (int p = 0; p < 4; p++) {
                int q = lane >> 3, rr = lane & 7;
                int n = wn * 64 + p * 16 + (q >> 1) * 8 + rr;
                int col = ks * 16 + (q & 1) * 8;
                ldm4(b[p][0], b[p][1], b[p][2], b[p][3], bB + (n * 40 + col) * 2);
            }
#pragma unroll
            for (int mt = 0; mt < 2; mt++)
#pragma unroll
                for (int j = 0; j < 8; j++)
                    mma16816(acc[mt][j], a[mt][0], a[mt][1], a[mt][2], a[mt][3],
                             b[j >> 1][(j & 1) * 2], b[j >> 1][(j & 1) * 2 + 1]);
        }
        __syncthreads();
    }

    int g = lane >> 2, tq = lane & 3;
#pragma unroll
    for (int mt = 0; mt < 2; mt++) {
        int r0 = rowBase + wm * 32 + mt * 16 + g;
#pragma unroll
        for (int j = 0; j < 8; j++) {
            int cc = colBase + wn * 64 + j * 8 + tq * 2;
            if (r0 < MPTS)
                *(__half2*)&outp[(size_t)r0 * DIM + cc] =
                    __floats2half2_rn(acc[mt][j][0], acc[mt][j][1]);
            if (r0 + 8 < MPTS)
                *(__half2*)&outp[(size_t)(r0 + 8) * DIM + cc] =
                    __floats2half2_rn(acc[mt][j][2], acc[mt][j][3]);
        }
    }
}

// ================= persistent step megakernel =================
__global__ void __launch_bounds__(256, 2) k_step(
    const float* __restrict__ w_ih, const float* __restrict__ w_hh,
    const float* __restrict__ b_ih, const float* __restrict__ b_hh,
    const float* __restrict__ hop_wq, const float* __restrict__ hop_v,
    const float* __restrict__ attn_wq, const float* __restrict__ attn_v,
    const float* __restrict__ gumbel, const float* __restrict__ attn_mem,
    const float* __restrict__ stop, float* __restrict__ out, int nb)
{
    __shared__ float sg2[8][4];      // per-warp half-dots (4 units x 2 halves)
    __shared__ float shh[4];
    __shared__ float smx[8], ssw[8], sacc[8][512];
    __shared__ float red[256];
    __shared__ float qn[8];
    __shared__ float sb[8]; __shared__ int si[8];
    __shared__ float sm[8]; __shared__ float ss[8];
    __shared__ float fb[256]; __shared__ int fi[256];
    __shared__ float fm[256]; __shared__ float fs[256];
    __shared__ int s_out, s_nd, islast;

    int bid = blockIdx.x;
    int tid = threadIdx.x, wid = tid >> 5, lane = tid & 31;
    const int tot = nb * 8;

    for (int t = 0; t < TSTEPS; t++) {
        // ---- phase A: gates + h,c + qh GEMV (blocks 0..127, 4 units each, k-split warps) ----
        if (bid < 128) {
            int kb = bid * 4;
            const float* hold = g_hbuf[t & 1];
            float* hnew = g_hbuf[(t + 1) & 1];
            const float* cold = g_cbuf[t & 1];
            float* cnew = g_cbuf[(t + 1) & 1];
            int j = kb + (wid & 3);
            int k0 = (wid >> 2) * 256;          // warp's k-half
            const float* wi0 = w_ih + (size_t)j * DIM;
            const float* wi1 = w_ih + (size_t)(HID + j) * DIM;
            const float* wi2 = w_ih + (size_t)(2 * HID + j) * DIM;
            const float* wi3 = w_ih + (size_t)(3 * HID + j) * DIM;
            const float* wh0 = w_hh + (size_t)j * HID;
            const float* wh1 = w_hh + (size_t)(HID + j) * HID;
            const float* wh2 = w_hh + (size_t)(2 * HID + j) * HID;
            const float* wh3 = w_hh + (size_t)(3 * HID + j) * HID;
            float s0 = 0.f, s1 = 0.f, s2 = 0.f, s3 = 0.f;
#pragma unroll 4
            for (int k = k0 + lane; k < k0 + 256; k += 32) {
                float xv = g_x[k], hv = hold[k];
                s0 += wi0[k] * xv + wh0[k] * hv;
                s1 += wi1[k] * xv + wh1[k] * hv;
                s2 += wi2[k] * xv + wh2[k] * hv;
                s3 += wi3[k] * xv + wh3[k] * hv;
            }
#pragma unroll
            for (int o = 16; o; o >>= 1) {
                s0 += __shfl_xor_sync(0xffffffffu, s0, o);
                s1 += __shfl_xor_sync(0xffffffffu, s1, o);
                s2 += __shfl_xor_sync(0xffffffffu, s2, o);
                s3 += __shfl_xor_sync(0xffffffffu, s3, o);
            }
            if (!lane) { sg2[wid][0] = s0; sg2[wid][1] = s1; sg2[wid][2] = s2; sg2[wid][3] = s3; }
            __syncthreads();
            if (tid < 4) {
                int jj = kb + tid;
                float g0 = sg2[tid][0] + sg2[tid + 4][0] + b_ih[jj] + b_hh[jj];
                float g1 = sg2[tid][1] + sg2[tid + 4][1] + b_ih[HID + jj] + b_hh[HID + jj];
                float g2 = sg2[tid][2] + sg2[tid + 4][2] + b_ih[2 * HID + jj] + b_hh[2 * HID + jj];
                float g3 = sg2[tid][3] + sg2[tid + 4][3] + b_ih[3 * HID + jj] + b_hh[3 * HID + jj];
                float gi = sigm(g0);
                float gf = sigm(g1);
                float gg = tanhe(g2);
                float go = sigm(g3);
                float c = gf * cold[jj] + gi * gg;
                float h = go * tanhe(c);
                cnew[jj] = c;
                hnew[jj] = h;
                shh[tid] = h;
            }
            __syncthreads();
            float a0 = 0.f, a1 = 0.f;
#pragma unroll
            for (int kk = 0; kk < 4; kk++) {
                float hv = shh[kk];
                const float* wr = hop_wq + (size_t)(kb + kk) * HID;
                a0 += hv * wr[tid];
                a1 += hv * wr[tid + 256];
            }
            atomicAdd(&g_qh[tid], a0);
            atomicAdd(&g_qh[tid + 256], a1);
        }
        gridbar(nb);

        // ---- phase B: hop pass (4 rows / iter for MLP) ----
        {
            if (bid == 0) { g_ba[tid] = 0.f; g_ba[tid + 256] = 0.f; }
            int gw = bid * 8 + wid;
            float q0[16], v0[16];
            {
                float4 a = *(const float4*)&g_qh[lane * 8];
                float4 b = *(const float4*)&g_qh[lane * 8 + 4];
                float4 c = *(const float4*)&g_qh[256 + lane * 8];
                float4 d = *(const float4*)&g_qh[256 + lane * 8 + 4];
                q0[0]=a.x;q0[1]=a.y;q0[2]=a.z;q0[3]=a.w; q0[4]=b.x;q0[5]=b.y;q0[6]=b.z;q0[7]=b.w;
                q0[8]=c.x;q0[9]=c.y;q0[10]=c.z;q0[11]=c.w; q0[12]=d.x;q0[13]=d.y;q0[14]=d.z;q0[15]=d.w;
                a = *(const float4*)&hop_v[lane * 8];
                b = *(const float4*)&hop_v[lane * 8 + 4];
                c = *(const float4*)&hop_v[256 + lane * 8];
                d = *(const float4*)&hop_v[256 + lane * 8 + 4];
                v0[0]=a.x;v0[1]=a.y;v0[2]=a.z;v0[3]=a.w; v0[4]=b.x;v0[5]=b.y;v0[6]=b.z;v0[7]=b.w;
                v0[8]=c.x;v0[9]=c.y;v0[10]=c.z;v0[11]=c.w; v0[12]=d.x;v0[13]=d.y;v0[14]=d.z;v0[15]=d.w;
            }
            float mx = NEGINF, sw = 0.f, acc[16];
#pragma unroll
            for (int i = 0; i < 16; i++) acc[i] = 0.f;

            for (int m0 = gw * 4; m0 < MPTS; m0 += 4 * tot) {
                uint4 p[4][2];
                int nrow = MPTS - m0;
                if (nrow > 4) nrow = 4;
#pragma unroll
                for (int r = 0; r < 4; r++) {
                    if (r < nrow) {
                        const uint4* rp = (const uint4*)(g_hf16 + (size_t)(m0 + r) * DIM);
                        p[r][0] = rp[lane];
                        p[r][1] = rp[32 + lane];
                    }
                }
                float sp[4];
#pragma unroll
                for (int r = 0; r < 4; r++) {
                    sp[r] = 0.f;
                    if (r < nrow) {
#pragma unroll
                        for (int k = 0; k < 4; k++) {
                            float2 f0 = __half22float2(((const __half2*)&p[r][0])[k]);
                            float2 f1 = __half22float2(((const __half2*)&p[r][1])[k]);
                            sp[r] += tanha(f0.x + q0[2*k])     * v0[2*k];
                            sp[r] += tanha(f0.y + q0[2*k+1])   * v0[2*k+1];
                            sp[r] += tanha(f1.x + q0[8+2*k])   * v0[8+2*k];
                            sp[r] += tanha(f1.y + q0[8+2*k+1]) * v0[8+2*k+1];
                        }
                    }
                }
#pragma unroll
                for (int o = 16; o; o >>= 1) {
                    sp[0] += __shfl_xor_sync(0xffffffffu, sp[0], o);
                    sp[1] += __shfl_xor_sync(0xffffffffu, sp[1], o);
                    sp[2] += __shfl_xor_sync(0xffffffffu, sp[2], o);
                    sp[3] += __shfl_xor_sync(0xffffffffu, sp[3], o);
                }
#pragma unroll
                for (int r = 0; r < 4; r++) {
                    if (r >= nrow) break;
                    if (sp[r] > mx) {
                        float f = __expf(mx - sp[r]);
                        sw *= f;
#pragma unroll
                        for (int i = 0; i < 16; i++) acc[i] *= f;
                        mx = sp[r];
                    }
                    float wgt = __expf(sp[r] - mx);
                    sw += wgt;
#pragma unroll
                    for (int k = 0; k < 4; k++) {
                        float2 f0 = __half22float2(((const __half2*)&p[r][0])[k]);
                        float2 f1 = __half22float2(((const __half2*)&p[r][1])[k]);
                        acc[2*k]     += wgt * f0.x;
                        acc[2*k+1]   += wgt * f0.y;
                        acc[8+2*k]   += wgt * f1.x;
                        acc[8+2*k+1] += wgt * f1.y;
                    }
                }
            }
#pragma unroll
            for (int s = 0; s < 8; s++) {
                sacc[wid][lane * 8 + s] = acc[s];
                sacc[wid][256 + lane * 8 + s] = acc[8 + s];
            }
            if (!lane) { smx[wid] = mx; ssw[wid] = sw; }
            __syncthreads();

            float M = smx[0];
#pragma unroll
            for (int w = 1; w < 8; w++) M = fmaxf(M, smx[w]);
            for (int c = tid; c < 512; c += 256) {
                float a = 0.f;
#pragma unroll
                for (int w = 0; w < 8; w++) a += sacc[w][c] * __expf(smx[w] - M);
                g_hpart[bid][2 + c] = a;
            }
            if (tid == 0) {
                float W = 0.f;
#pragma unroll
                for (int w = 0; w < 8; w++) W += ssw[w] * __expf(smx[w] - M);
                g_hpart[bid][0] = M;
                g_hpart[bid][1] = W;
            }
            __syncthreads();
        }
        gridbar(nb);

        // ---- phase C: reduce hop partials + bias GEMV (blocks 0..63) ----
        if (bid < 64) {
            int kb = bid * 8;
            float m = NEGINF;
            for (int b = tid; b < nb; b += 256) m = fmaxf(m, g_hpart[b][0]);
            red[tid] = m; __syncthreads();
            for (int o = 128; o; o >>= 1) { if (tid < o) red[tid] = fmaxf(red[tid], red[tid + o]); __syncthreads(); }
            float M = red[0]; __syncthreads();

            float wsum = 0.f;
            for (int b = tid; b < nb; b += 256) wsum += __expf(g_hpart[b][0] - M) * g_hpart[b][1];
            red[tid] = wsum; __syncthreads();
            for (int o = 128; o; o >>= 1) { if (tid < o) red[tid] += red[tid + o]; __syncthreads(); }
            float W = red[0]; __syncthreads();

            {
                int g = tid >> 5, l = tid & 31;
                int k = kb + g;
                float a = 0.f;
                for (int b = l; b < nb; b += 32)
                    a += __expf(g_hpart[b][0] - M) * g_hpart[b][2 + k];
#pragma unroll
                for (int o = 16; o; o >>= 1) a += __shfl_xor_sync(0xffffffffu, a, o);
                if (l == 0) qn[g] = __fdividef(a, W);
            }
            __syncthreads();

            float a0 = 0.f, a1 = 0.f;
#pragma unroll
            for (int kk = 0; kk < 8; kk++) {
                float q = qn[kk];
                const float* wr = attn_wq + (size_t)(kb + kk) * HID;
                a0 += q * wr[tid];
                a1 += q * wr[tid + 256];
            }
            atomicAdd(&g_ba[tid], a0);
            atomicAdd(&g_ba[tid + 256], a1);
        }
        gridbar(nb);

        // ---- phase D: attn pass (4 rows / iter) + ticket-fused final ----
        {
            int gw = bid * 8 + wid;
            const float* gum = gumbel + (size_t)t * MPTS;
            float b0[16], v0[16];
            {
                float4 a = *(const float4*)&g_ba[lane * 8];
                float4 b = *(const float4*)&g_ba[lane * 8 + 4];
                float4 c = *(const float4*)&g_ba[256 + lane * 8];
                float4 d = *(const float4*)&g_ba[256 + lane * 8 + 4];
                b0[0]=a.x;b0[1]=a.y;b0[2]=a.z;b0[3]=a.w; b0[4]=b.x;b0[5]=b.y;b0[6]=b.z;b0[7]=b.w;
                b0[8]=c.x;b0[9]=c.y;b0[10]=c.z;b0[11]=c.w; b0[12]=d.x;b0[13]=d.y;b0[14]=d.z;b0[15]=d.w;
                a = *(const float4*)&attn_v[lane * 8];
                b = *(const float4*)&attn_v[lane * 8 + 4];
                c = *(const float4*)&attn_v[256 + lane * 8];
                d = *(const float4*)&attn_v[256 + lane * 8 + 4];
                v0[0]=a.x;v0[1]=a.y;v0[2]=a.z;v0[3]=a.w; v0[4]=b.x;v0[5]=b.y;v0[6]=b.z;v0[7]=b.w;
                v0[8]=c.x;v0[9]=c.y;v0[10]=c.z;v0[11]=c.w; v0[12]=d.x;v0[13]=d.y;v0[14]=d.z;v0[15]=d.w;
            }
            float mxs = NEGINF, ssum = 0.f, best = NEGINF;
            int bidx = 0x7fffffff;

            for (int m0 = gw * 4; m0 < MPTS; m0 += 4 * tot) {
                uint4 p[4][2];
                int nrow = MPTS - m0;
                if (nrow > 4) nrow = 4;
#pragma unroll
                for (int r = 0; r < 4; r++) {
                    if (r < nrow) {
                        const uint4* rp = (const uint4*)(g_af16 + (size_t)(m0 + r) * DIM);
                        p[r][0] = rp[lane];
                        p[r][1] = rp[32 + lane];
                    }
                }
#pragma unroll
                for (int r = 0; r < 4; r++) {
                    if (r >= nrow) break;
                    int m = m0 + r;
                    float sp = 0.f;
#pragma unroll
                    for (int k = 0; k < 4; k++) {
                        float2 f0 = __half22float2(((const __half2*)&p[r][0])[k]);
                        float2 f1 = __half22float2(((const __half2*)&p[r][1])[k]);
                        sp += tanha(f0.x + b0[2*k])     * v0[2*k];
                        sp += tanha(f0.y + b0[2*k+1])   * v0[2*k+1];
                        sp += tanha(f1.x + b0[8+2*k])   * v0[8+2*k];
                        sp += tanha(f1.y + b0[8+2*k+1]) * v0[8+2*k+1];
                    }
#pragma unroll
                    for (int o = 16; o; o >>= 1) sp += __shfl_xor_sync(0xffffffffu, sp, o);
                    float sc = g_sel[m] ? -1e18f : sp;
                    if (sc > mxs) { ssum *= __expf(mxs - sc); mxs = sc; }
                    ssum += __expf(sc - mxs);
                    float tv = sc + gum[m];
                    if (tv > best || (tv == best && m < bidx)) { best = tv; bidx = m; }
                }
            }
            if (!lane) { sb[wid] = best; si[wid] = bidx; sm[wid] = mxs; ss[wid] = ssum; }
            __syncthreads();
            if (tid == 0) {
                float B = sb[0]; int I = si[0];
                float M2 = sm[0], S = ss[0];
#pragma unroll
                for (int w = 1; w < 8; w++) {
                    if (sb[w] > B || (sb[w] == B && si[w] < I)) { B = sb[w]; I = si[w]; }
                    float m2 = sm[w], s2 = ss[w];
                    if (m2 > M2) { S = S * __expf(M2 - m2) + s2; M2 = m2; }
                    else S += s2 * __expf(m2 - M2);
                }
                g_apart[bid][0] = B; g_apart[bid][1] = M2;
                g_apart[bid][2] = S; g_aidx[bid] = I;
            }

            __threadfence();
            __syncthreads();
            if (tid == 0) {
                int v = atomicAdd(&g_ticket, 1);
                islast = ((v % nb) == nb - 1);
            }
            __syncthreads();
            if (islast) {
                g_qh[tid] = 0.f; g_qh[tid + 256] = 0.f;
                float B = NEGINF; int I = 0x7fffffff; float M = NEGINF; float S = 0.f;
                for (int b = tid; b < nb; b += 256) {
                    float bb = g_apart[b][0]; int ii = g_aidx[b];
                    if (bb > B || (bb == B && ii < I)) { B = bb; I = ii; }
                    float m2 = g_apart[b][1], s2 = g_apart[b][2];
                    if (m2 > M) { S = S * __expf(M - m2) + s2; M = m2; }
                    else S += s2 * __expf(m2 - M);
                }
                fb[tid] = B; fi[tid] = I; fm[tid] = M; fs[tid] = S;
                __syncthreads();
                for (int o = 128; o; o >>= 1) {
                    if (tid < o) {
                        if (fb[tid + o] > fb[tid] || (fb[tid + o] == fb[tid] && fi[tid + o] < fi[tid])) {
                            fb[tid] = fb[tid + o]; fi[tid] = fi[tid + o];
                        }
                        float m1 = fm[tid], s1 = fs[tid];
                        float m2 = fm[tid + o], s2 = fs[tid + o];
                        float Mn = fmaxf(m1, m2);
                        float Sn = 0.f;
                        if (s1 > 0.f) Sn += s1 * __expf(m1 - Mn);
                        if (s2 > 0.f) Sn += s2 * __expf(m2 - Mn);
                        fm[tid] = Mn; fs[tid] = Sn;
                    }
                    __syncthreads();
                }
                if (tid == 0) {
                    int done = g_done;
                    int o_ = fi[0];
                    float sc = fb[0] - gum[o_];
                    float lse = fm[0] + logf(fs[0]);
                    float logp = sc - lse;
                    out[t]          = done ? (float)NPTS : (float)o_;
                    out[TSTEPS + t] = done ? 0.f : logp;
                    if (!done) g_sel[o_] = 1;
                    int nd = done || (o_ == NPTS);
                    g_done = nd;
                    s_out = o_; s_nd = nd;
                }
                __syncthreads();
                if (!s_nd) {
                    int o_ = s_out;
                    const float* src = (o_ == NPTS) ? stop : attn_mem + (size_t)o_ * DIM;
                    g_x[tid] = src[tid];
                    g_x[tid + 256] = src[tid + 256];
                }
            }
        }
        gridbar(nb);
    }
}

// ---------------- launch ----------------
extern "C" void kernel_launch(void* const* d_in, const int* in_sizes, int n_in,
                              void* d_out, int out_size) {
    const float* attn_mem = (const float*)d_in[0];
    const float* stop     = (const float*)d_in[1];
    const float* init_h   = (const float*)d_in[2];
    const float* init_c   = (const float*)d_in[3];
    const float* init_i   = (const float*)d_in[4];
    const float* attn_wm  = (const float*)d_in[5];
    const float* attn_wq  = (const float*)d_in[6];
    const float* attn_v   = (const float*)d_in[7];
    const float* hop_wm   = (const float*)d_in[8];
    const float* hop_wq   = (const float*)d_in[9];
    const float* hop_v    = (const float*)d_in[10];
    const float* w_ih     = (const float*)d_in[11];
    const float* w_hh     = (const float*)d_in[12];
    const float* b_ih     = (const float*)d_in[13];
    const float* b_hh     = (const float*)d_in[14];
    const float* gumbel   = (const float*)d_in[15];
    float* out = (float*)d_out;

    static int nb = 0;
    if (nb == 0) {
        int sms = 0;
        cudaDeviceGetAttribute(&sms, cudaDevAttrMultiProcessorCount, 0);
        nb = 2 * sms;
        if (nb > NBMAX) nb = NBMAX;
        if (nb < 128) nb = 128;
    }

    k_init<<<(MPTS + 255) / 256, 256>>>(init_h, init_c, init_i);
    k_convA<<<8192, 256>>>(attn_mem, stop);
    k_convB<<<2048, 256>>>(attn_wm, hop_wm);

    dim3 gg(8, ROWT);
    k_feat_mma<<<gg, 256>>>();

    k_step<<<nb, 256>>>(w_ih, w_hh, b_ih, b_hh, hop_wq, hop_v,
                        attn_wq, attn_v, gumbel, attn_mem, stop, out, nb);
}

// round 12
// speedup vs baseline: 4.0963x; 1.0225x over previous
#include <cuda_runtime.h>
#include <cuda_fp16.h>
#include <cstdint>

#define NPTS   50000
#define MPTS   50001
#define DIM    512
#define HID    512
#define TSTEPS 16
#define NBMAX  320
#define NEGINF (__int_as_float(0xff800000))

#define PADM   50048           // 391 * 128
#define ROWT   391
#define NCH    8               // K = 512, 64-wide chunks
#define STGH   (128 * 72 * 2)  // halfs per stage (A + B)
#define FEAT_SMEM (2 * STGH * 2)  // bytes: 2 stages

// ---------------- device scratch ----------------
__device__ __half g_af16[(size_t)MPTS * DIM];
__device__ __half g_hf16[(size_t)MPTS * DIM];
__device__ __half g_a16[(size_t)PADM * DIM];
__device__ __half g_bt[2][512][512];
__device__ float g_hbuf[2][HID];
__device__ float g_cbuf[2][HID];
__device__ float g_x[DIM];
__device__ float g_qh[HID];
__device__ float g_ba[HID];
__device__ unsigned char g_sel[MPTS];
__device__ int   g_done;
__device__ int   g_ticket;
__device__ volatile int g_xready;
__device__ volatile unsigned g_gen;
__device__ unsigned g_cnt2[8 * 16];   // padded counters (64B apart)
__device__ unsigned g_root;
__device__ float g_hpart[NBMAX][514];
__device__ float g_apart[NBMAX][3];
__device__ int   g_aidx[NBMAX];

// ---------------- helpers ----------------
__device__ __forceinline__ float tanhe(float x) {
    float e = __expf(2.f * x);
    return 1.f - __fdividef(2.f, e + 1.f);
}
__device__ __forceinline__ float tanha(float x) {
    float y; asm("tanh.approx.f32 %0, %1;" : "=f"(y) : "f"(x)); return y;
}
__device__ __forceinline__ float sigm(float x) {
    return __fdividef(1.f, 1.f + __expf(-x));
}
__device__ __forceinline__ uint32_t s2u(const void* p) {
    uint32_t a;
    asm("{ .reg .u64 t; cvta.to.shared.u64 t, %1; cvt.u32.u64 %0, t; }" : "=r"(a) : "l"(p));
    return a;
}
__device__ __forceinline__ void cp16(uint32_t dst, const void* src) {
    asm volatile("cp.async.cg.shared.global [%0], [%1], 16;" :: "r"(dst), "l"(src));
}
__device__ __forceinline__ void ldm4(uint32_t& r0, uint32_t& r1, uint32_t& r2, uint32_t& r3,
                                     uint32_t addr) {
    asm volatile("ldmatrix.sync.aligned.m8n8.x4.shared.b16 {%0,%1,%2,%3}, [%4];"
                 : "=r"(r0), "=r"(r1), "=r"(r2), "=r"(r3) : "r"(addr));
}
__device__ __forceinline__ void mma16816(float* c, uint32_t a0, uint32_t a1, uint32_t a2,
                                         uint32_t a3, uint32_t b0, uint32_t b1) {
    asm volatile(
        "mma.sync.aligned.m16n8k16.row.col.f32.f16.f16.f32 "
        "{%0,%1,%2,%3},{%4,%5,%6,%7},{%8,%9},{%0,%1,%2,%3};"
        : "+f"(c[0]), "+f"(c[1]), "+f"(c[2]), "+f"(c[3])
        : "r"(a0), "r"(a1), "r"(a2), "r"(a3), "r"(b0), "r"(b1));
}
__device__ __forceinline__ unsigned pkh2(float a, float b) {
    __half2 h = __floats2half2_rn(a, b);
    return *(unsigned*)&h;
}

// two-level grid barrier
__device__ __forceinline__ void gridbar(int nb) {
    __threadfence();
    __syncthreads();
    if (threadIdx.x == 0) {
        unsigned gen = g_gen;
        int grp = blockIdx.x & 7;
        unsigned quota = (unsigned)((nb - grp + 7) >> 3);
        unsigned v = atomicAdd(&g_cnt2[grp * 16], 1);
        if (v == quota - 1) {
            g_cnt2[grp * 16] = 0;
            unsigned r = atomicAdd(&g_root, 1);
            if (r == 7) {
                g_root = 0;
                __threadfence();
                g_gen = gen + 1;
            } else {
                while (g_gen == gen) __nanosleep(32);
            }
        } else {
            while (g_gen == gen) __nanosleep(32);
        }
    }
    __syncthreads();
}

// ---------------- K0: state init ----------------
__global__ void k_init(const float* __restrict__ ih, const float* __restrict__ ic,
                       const float* __restrict__ ii) {
    int i = blockIdx.x * blockDim.x + threadIdx.x;
    if (i < MPTS) g_sel[i] = 0;
    if (i < HID) { g_hbuf[0][i] = ih[i]; g_cbuf[0][i] = ic[i]; g_x[i] = ii[i]; g_qh[i] = 0.f; }
    if (i < 128) g_cnt2[i] = 0;
    if (i == 0) { g_done = 0; g_ticket = 0; g_gen = 0; g_root = 0; g_xready = 0; }
}

// ---------------- convert A ----------------
__global__ void k_convA(const float* __restrict__ mem, const float* __restrict__ stop) {
    const int total4 = PADM * DIM / 4;
    for (int i = blockIdx.x * blockDim.x + threadIdx.x; i < total4;
         i += gridDim.x * blockDim.x) {
        int row = i >> 7;
        int c4 = (i & 127) * 4;
        float4 v;
        if (row < NPTS)       v = *(const float4*)&mem[(size_t)row * DIM + c4];
        else if (row == NPTS) v = *(const float4*)&stop[c4];
        else                  v = make_float4(0.f, 0.f, 0.f, 0.f);
        uint2 ph;
        ph.x = pkh2(v.x, v.y); ph.y = pkh2(v.z, v.w);
        ((uint2*)g_a16)[i] = ph;
    }
}

// ---------------- convert B ----------------
__global__ void k_convB(const float* __restrict__ attn_wm, const float* __restrict__ hop_wm) {
    int id = blockIdx.x * blockDim.x + threadIdx.x;
    if (id >= 2 * 512 * 512) return;
    int w = id >> 18;
    int r = id & 262143;
    int n = r >> 9;
    int k = r & 511;
    const float* src = w ? hop_wm : attn_wm;
    g_bt[w][n][k] = __float2half_rn(src[(size_t)k * 512 + n]);
}

// ---------------- GEMM: fp16 mma.sync, CTA 128x128, K=512, chunk 64 ----------------
__global__ void __launch_bounds__(256, 2) k_feat_mma() {
    extern __shared__ __align__(16) __half dsm[];
    int tid = threadIdx.x, wid = tid >> 5, lane = tid & 31;
    int rowBase = blockIdx.y * 128;
    int colBase = (blockIdx.x >> 1) * 128;
    int mat = blockIdx.x & 1;
    const __half* bsrc = &g_bt[mat][colBase][0];
    __half* outp = mat ? g_hf16 : g_af16;
    const __half* asrc = g_a16 + (size_t)rowBase * DIM;
    int wm = wid >> 1, wn = wid & 1;

    float acc[2][8][4];
#pragma unroll
    for (int mt = 0; mt < 2; mt++)
#pragma unroll
        for (int j = 0; j < 8; j++)
#pragma unroll
            for (int e = 0; e < 4; e++) acc[mt][j][e] = 0.f;

    uint32_t u0 = s2u(dsm);

    auto load = [&](int c, int buf) {
        const __half* A = asrc + c * 64;
        const __half* B = bsrc + c * 64;
        uint32_t dA = u0 + buf * (STGH * 2);
        uint32_t dB = dA + 128 * 72 * 2;
#pragma unroll
        for (int i = 0; i < 4; i++) {
            int idx = i * 256 + tid;
            int r = idx >> 3, ch = idx & 7;
            cp16(dA + r * 144 + ch * 16, (const char*)(A + (size_t)r * 512) + ch * 16);
            cp16(dB + r * 144 + ch * 16, (const char*)(B + (size_t)r * 512) + ch * 16);
        }
        asm volatile("cp.async.commit_group;" ::: "memory");
    };

    load(0, 0);
    for (int c = 0; c < NCH; c++) {
        int buf = c & 1;
        if (c + 1 < NCH) load(c + 1, buf ^ 1);
        if (c + 1 < NCH)
            asm volatile("cp.async.wait_group 1;" ::: "memory");
        else
            asm volatile("cp.async.wait_group 0;" ::: "memory");
        __syncthreads();

        uint32_t bA = u0 + buf * (STGH * 2);
        uint32_t bB = bA + 128 * 72 * 2;
#pragma unroll
        for (int ks = 0; ks < 4; ks++) {
            uint32_t a[2][4];
#pragma unroll
            for (int mt = 0; mt < 2; mt++) {
                int row = wm * 32 + mt * 16 + (lane & 15);
                int col = ks * 16 + (lane >> 4) * 8;
                ldm4(a[mt][0], a[mt][1], a[mt][2], a[mt][3], bA + (row * 72 + col) * 2);
            }
            uint32_t b[4][4];
#pragma unroll
            for (int p = 0; p < 4; p++) {
                int q = lane >> 3, rr = lane & 7;
                int n = wn * 64 + p * 16 + (q >> 1) * 8 + rr;
                int col = ks * 16 + (q & 1) * 8;
                ldm4(b[p][0], b[p][1], b[p][2], b[p][3], bB + (n * 72 + col) * 2);
            }
#pragma unroll
            for (int mt = 0; mt < 2; mt++)
#pragma unroll
                for (int j = 0; j < 8; j++)
                    mma16816(acc[mt][j], a[mt][0], a[mt][1], a[mt][2], a[mt][3],
                             b[j >> 1][(j & 1) * 2], b[j >> 1][(j & 1) * 2 + 1]);
        }
        __syncthreads();
    }

    int g = lane >> 2, tq = lane & 3;
#pragma unroll
    for (int mt = 0; mt < 2; mt++) {
        int r0 = rowBase + wm * 32 + mt * 16 + g;
#pragma unroll
        for (int j = 0; j < 8; j++) {
            int cc = colBase + wn * 64 + j * 8 + tq * 2;
            if (r0 < MPTS)
                *(__half2*)&outp[(size_t)r0 * DIM + cc] =
                    __floats2half2_rn(acc[mt][j][0], acc[mt][j][1]);
            if (r0 + 8 < MPTS)
                *(__half2*)&outp[(size_t)(r0 + 8) * DIM + cc] =
                    __floats2half2_rn(acc[mt][j][2], acc[mt][j][3]);
        }
    }
}

// ================= persistent step megakernel =================
__global__ void __launch_bounds__(256, 2) k_step(
    const float* __restrict__ w_ih, const float* __restrict__ w_hh,
    const float* __restrict__ b_ih, const float* __restrict__ b_hh,
    const float* __restrict__ hop_wq, const float* __restrict__ hop_v,
    const float* __restrict__ attn_wq, const float* __restrict__ attn_v,
    const float* __restrict__ gumbel, const float* __restrict__ attn_mem,
    const float* __restrict__ stop, float* __restrict__ out, int nb)
{
    __shared__ float sg2[8][4];
    __shared__ float shh[4];
    __shared__ float smx[8], ssw[8], sacc[8][512];
    __shared__ float red[256];
    __shared__ float qn[8];
    __shared__ float sb[8]; __shared__ int si[8];
    __shared__ float sm[8]; __shared__ float ss[8];
    __shared__ float fb[256]; __shared__ int fi[256];
    __shared__ float fm[256]; __shared__ float fs[256];
    __shared__ int s_out, s_nd, islast;

    int bid = blockIdx.x;
    int tid = threadIdx.x, wid = tid >> 5, lane = tid & 31;
    const int tot = nb * 8;

    for (int t = 0; t < TSTEPS; t++) {
        // ---- phase A (flag-gated): gates + h,c + qh GEMV (blocks 0..127) ----
        if (bid < 128) {
            if (tid == 0) { while (g_xready < t) __nanosleep(32); }
            __syncthreads();
            __threadfence();
            int kb = bid * 4;
            const float* hold = g_hbuf[t & 1];
            float* hnew = g_hbuf[(t + 1) & 1];
            const float* cold = g_cbuf[t & 1];
            float* cnew = g_cbuf[(t + 1) & 1];
            int j = kb + (wid & 3);
            int k0 = (wid >> 2) * 256;
            const float* wi0 = w_ih + (size_t)j * DIM;
            const float* wi1 = w_ih + (size_t)(HID + j) * DIM;
            const float* wi2 = w_ih + (size_t)(2 * HID + j) * DIM;
            const float* wi3 = w_ih + (size_t)(3 * HID + j) * DIM;
            const float* wh0 = w_hh + (size_t)j * HID;
            const float* wh1 = w_hh + (size_t)(HID + j) * HID;
            const float* wh2 = w_hh + (size_t)(2 * HID + j) * HID;
            const float* wh3 = w_hh + (size_t)(3 * HID + j) * HID;
            float s0 = 0.f, s1 = 0.f, s2 = 0.f, s3 = 0.f;
#pragma unroll 4
            for (int k = k0 + lane; k < k0 + 256; k += 32) {
                float xv = g_x[k], hv = hold[k];
                s0 += wi0[k] * xv + wh0[k] * hv;
                s1 += wi1[k] * xv + wh1[k] * hv;
                s2 += wi2[k] * xv + wh2[k] * hv;
                s3 += wi3[k] * xv + wh3[k] * hv;
            }
#pragma unroll
            for (int o = 16; o; o >>= 1) {
                s0 += __shfl_xor_sync(0xffffffffu, s0, o);
                s1 += __shfl_xor_sync(0xffffffffu, s1, o);
                s2 += __shfl_xor_sync(0xffffffffu, s2, o);
                s3 += __shfl_xor_sync(0xffffffffu, s3, o);
            }
            if (!lane) { sg2[wid][0] = s0; sg2[wid][1] = s1; sg2[wid][2] = s2; sg2[wid][3] = s3; }
            __syncthreads();
            if (tid < 4) {
                int jj = kb + tid;
                float g0 = sg2[tid][0] + sg2[tid + 4][0] + b_ih[jj] + b_hh[jj];
                float g1 = sg2[tid][1] + sg2[tid + 4][1] + b_ih[HID + jj] + b_hh[HID + jj];
                float g2 = sg2[tid][2] + sg2[tid + 4][2] + b_ih[2 * HID + jj] + b_hh[2 * HID + jj];
                float g3 = sg2[tid][3] + sg2[tid + 4][3] + b_ih[3 * HID + jj] + b_hh[3 * HID + jj];
                float gi = sigm(g0);
                float gf = sigm(g1);
                float gg = tanhe(g2);
                float go = sigm(g3);
                float c = gf * cold[jj] + gi * gg;
                float h = go * tanhe(c);
                cnew[jj] = c;
                hnew[jj] = h;
                shh[tid] = h;
            }
            __syncthreads();
            float a0 = 0.f, a1 = 0.f;
#pragma unroll
            for (int kk = 0; kk < 4; kk++) {
                float hv = shh[kk];
                const float* wr = hop_wq + (size_t)(kb + kk) * HID;
                a0 += hv * wr[tid];
                a1 += hv * wr[tid + 256];
            }
            atomicAdd(&g_qh[tid], a0);
            atomicAdd(&g_qh[tid + 256], a1);
        }
        gridbar(nb);

        // ---- phase B: hop pass (4 rows / iter) ----
        {
            if (bid == 0) { g_ba[tid] = 0.f; g_ba[tid + 256] = 0.f; }
            int gw = bid * 8 + wid;
            float q0[16], v0[16];
            {
                float4 a = *(const float4*)&g_qh[lane * 8];
                float4 b = *(const float4*)&g_qh[lane * 8 + 4];
                float4 c = *(const float4*)&g_qh[256 + lane * 8];
                float4 d = *(const float4*)&g_qh[256 + lane * 8 + 4];
                q0[0]=a.x;q0[1]=a.y;q0[2]=a.z;q0[3]=a.w; q0[4]=b.x;q0[5]=b.y;q0[6]=b.z;q0[7]=b.w;
                q0[8]=c.x;q0[9]=c.y;q0[10]=c.z;q0[11]=c.w; q0[12]=d.x;q0[13]=d.y;q0[14]=d.z;q0[15]=d.w;
                a = *(const float4*)&hop_v[lane * 8];
                b = *(const float4*)&hop_v[lane * 8 + 4];
                c = *(const float4*)&hop_v[256 + lane * 8];
                d = *(const float4*)&hop_v[256 + lane * 8 + 4];
                v0[0]=a.x;v0[1]=a.y;v0[2]=a.z;v0[3]=a.w; v0[4]=b.x;v0[5]=b.y;v0[6]=b.z;v0[7]=b.w;
                v0[8]=c.x;v0[9]=c.y;v0[10]=c.z;v0[11]=c.w; v0[12]=d.x;v0[13]=d.y;v0[14]=d.z;v0[15]=d.w;
            }
            float mx = NEGINF, sw = 0.f, acc[16];
#pragma unroll
            for (int i = 0; i < 16; i++) acc[i] = 0.f;

            for (int m0 = gw * 4; m0 < MPTS; m0 += 4 * tot) {
                uint4 p[4][2];
                int nrow = MPTS - m0;
                if (nrow > 4) nrow = 4;
#pragma unroll
                for (int r = 0; r < 4; r++) {
                    if (r < nrow) {
                        const uint4* rp = (const uint4*)(g_hf16 + (size_t)(m0 + r) * DIM);
                        p[r][0] = rp[lane];
                        p[r][1] = rp[32 + lane];
                    }
                }
                float sp[4];
#pragma unroll
                for (int r = 0; r < 4; r++) {
                    sp[r] = 0.f;
                    if (r < nrow) {
#pragma unroll
                        for (int k = 0; k < 4; k++) {
                            float2 f0 = __half22float2(((const __half2*)&p[r][0])[k]);
                            float2 f1 = __half22float2(((const __half2*)&p[r][1])[k]);
                            sp[r] += tanha(f0.x + q0[2*k])     * v0[2*k];
                            sp[r] += tanha(f0.y + q0[2*k+1])   * v0[2*k+1];
                            sp[r] += tanha(f1.x + q0[8+2*k])   * v0[8+2*k];
                            sp[r] += tanha(f1.y + q0[8+2*k+1]) * v0[8+2*k+1];
                        }
                    }
                }
#pragma unroll
                for (int o = 16; o; o >>= 1) {
                    sp[0] += __shfl_xor_sync(0xffffffffu, sp[0], o);
                    sp[1] += __shfl_xor_sync(0xffffffffu, sp[1], o);
                    sp[2] += __shfl_xor_sync(0xffffffffu, sp[2], o);
                    sp[3] += __shfl_xor_sync(0xffffffffu, sp[3], o);
                }
#pragma unroll
                for (int r = 0; r < 4; r++) {
                    if (r >= nrow) break;
                    if (sp[r] > mx) {
                        float f = __expf(mx - sp[r]);
                        sw *= f;
#pragma unroll
                        for (int i = 0; i < 16; i++) acc[i] *= f;
                        mx = sp[r];
                    }
                    float wgt = __expf(sp[r] - mx);
                    sw += wgt;
#pragma unroll
                    for (int k = 0; k < 4; k++) {
                        float2 f0 = __half22float2(((const __half2*)&p[r][0])[k]);
                        float2 f1 = __half22float2(((const __half2*)&p[r][1])[k]);
                        acc[2*k]     += wgt * f0.x;
                        acc[2*k+1]   += wgt * f0.y;
                        acc[8+2*k]   += wgt * f1.x;
                        acc[8+2*k+1] += wgt * f1.y;
                    }
                }
            }
#pragma unroll
            for (int s = 0; s < 8; s++) {
                sacc[wid][lane * 8 + s] = acc[s];
                sacc[wid][256 + lane * 8 + s] = acc[8 + s];
            }
            if (!lane) { smx[wid] = mx; ssw[wid] = sw; }
            __syncthreads();

            float M = smx[0];
#pragma unroll
            for (int w = 1; w < 8; w++) M = fmaxf(M, smx[w]);
            for (int c = tid; c < 512; c += 256) {
                float a = 0.f;
#pragma unroll
                for (int w = 0; w < 8; w++) a += sacc[w][c] * __expf(smx[w] - M);
                g_hpart[bid][2 + c] = a;
            }
            if (tid == 0) {
                float W = 0.f;
#pragma unroll
                for (int w = 0; w < 8; w++) W += ssw[w] * __expf(smx[w] - M);
                g_hpart[bid][0] = M;
                g_hpart[bid][1] = W;
            }
            __syncthreads();
        }
        gridbar(nb);

        // ---- phase C: reduce hop partials + bias GEMV (blocks 0..63) ----
        if (bid < 64) {
            int kb = bid * 8;
            float m = NEGINF;
            for (int b = tid; b < nb; b += 256) m = fmaxf(m, g_hpart[b][0]);
            red[tid] = m; __syncthreads();
            for (int o = 128; o; o >>= 1) { if (tid < o) red[tid] = fmaxf(red[tid], red[tid + o]); __syncthreads(); }
            float M = red[0]; __syncthreads();

            float wsum = 0.f;
            for (int b = tid; b < nb; b += 256) wsum += __expf(g_hpart[b][0] - M) * g_hpart[b][1];
            red[tid] = wsum; __syncthreads();
            for (int o = 128; o; o >>= 1) { if (tid < o) red[tid] += red[tid + o]; __syncthreads(); }
            float W = red[0]; __syncthreads();

            {
                int g = tid >> 5, l = tid & 31;
                int k = kb + g;
                float a = 0.f;
                for (int b = l; b < nb; b += 32)
                    a += __expf(g_hpart[b][0] - M) * g_hpart[b][2 + k];
#pragma unroll
                for (int o = 16; o; o >>= 1) a += __shfl_xor_sync(0xffffffffu, a, o);
                if (l == 0) qn[g] = __fdividef(a, W);
            }
            __syncthreads();

            float a0 = 0.f, a1 = 0.f;
#pragma unroll
            for (int kk = 0; kk < 8; kk++) {
                float q = qn[kk];
                const float* wr = attn_wq + (size_t)(kb + kk) * HID;
                a0 += q * wr[tid];
                a1 += q * wr[tid + 256];
            }
            atomicAdd(&g_ba[tid], a0);
            atomicAdd(&g_ba[tid + 256], a1);
        }
        gridbar(nb);

        // ---- phase D: attn pass (4 rows / iter) + ticket-fused final + flag ----
        {
            int gw = bid * 8 + wid;
            const float* gum = gumbel + (size_t)t * MPTS;
            float b0[16], v0[16];
            {
                float4 a = *(const float4*)&g_ba[lane * 8];
                float4 b = *(const float4*)&g_ba[lane * 8 + 4];
                float4 c = *(const float4*)&g_ba[256 + lane * 8];
                float4 d = *(const float4*)&g_ba[256 + lane * 8 + 4];
                b0[0]=a.x;b0[1]=a.y;b0[2]=a.z;b0[3]=a.w; b0[4]=b.x;b0[5]=b.y;b0[6]=b.z;b0[7]=b.w;
                b0[8]=c.x;b0[9]=c.y;b0[10]=c.z;b0[11]=c.w; b0[12]=d.x;b0[13]=d.y;b0[14]=d.z;b0[15]=d.w;
                a = *(const float4*)&attn_v[lane * 8];
                b = *(const float4*)&attn_v[lane * 8 + 4];
                c = *(const float4*)&attn_v[256 + lane * 8];
                d = *(const float4*)&attn_v[256 + lane * 8 + 4];
                v0[0]=a.x;v0[1]=a.y;v0[2]=a.z;v0[3]=a.w; v0[4]=b.x;v0[5]=b.y;v0[6]=b.z;v0[7]=b.w;
                v0[8]=c.x;v0[9]=c.y;v0[10]=c.z;v0[11]=c.w; v0[12]=d.x;v0[13]=d.y;v0[14]=d.z;v0[15]=d.w;
            }
            float mxs = NEGINF, ssum = 0.f, best = NEGINF;
            int bidx = 0x7fffffff;

            for (int m0 = gw * 4; m0 < MPTS; m0 += 4 * tot) {
                uint4 p[4][2];
                int nrow = MPTS - m0;
                if (nrow > 4) nrow = 4;
#pragma unroll
                for (int r = 0; r < 4; r++) {
                    if (r < nrow) {
                        const uint4* rp = (const uint4*)(g_af16 + (size_t)(m0 + r) * DIM);
                        p[r][0] = rp[lane];
                        p[r][1] = rp[32 + lane];
                    }
                }
#pragma unroll
                for (int r = 0; r < 4; r++) {
                    if (r >= nrow) break;
                    int m = m0 + r;
                    float sp = 0.f;
#pragma unroll
                    for (int k = 0; k < 4; k++) {
                        float2 f0 = __half22float2(((const __half2*)&p[r][0])[k]);
                        float2 f1 = __half22float2(((const __half2*)&p[r][1])[k]);
                        sp += tanha(f0.x + b0[2*k])     * v0[2*k];
                        sp += tanha(f0.y + b0[2*k+1])   * v0[2*k+1];
                        sp += tanha(f1.x + b0[8+2*k])   * v0[8+2*k];
                        sp += tanha(f1.y + b0[8+2*k+1]) * v0[8+2*k+1];
                    }
#pragma unroll
                    for (int o = 16; o; o >>= 1) sp += __shfl_xor_sync(0xffffffffu, sp, o);
                    float sc = g_sel[m] ? -1e18f : sp;
                    if (sc > mxs) { ssum *= __expf(mxs - sc); mxs = sc; }
                    ssum += __expf(sc - mxs);
                    float tv = sc + gum[m];
                    if (tv > best || (tv == best && m < bidx)) { best = tv; bidx = m; }
                }
            }
            if (!lane) { sb[wid] = best; si[wid] = bidx; sm[wid] = mxs; ss[wid] = ssum; }
            __syncthreads();
            if (tid == 0) {
                float B = sb[0]; int I = si[0];
                float M2 = sm[0], S = ss[0];
#pragma unroll
                for (int w = 1; w < 8; w++) {
                    if (sb[w] > B || (sb[w] == B && si[w] < I)) { B = sb[w]; I = si[w]; }
                    float m2 = sm[w], s2 = ss[w];
                    if (m2 > M2) { S = S * __expf(M2 - m2) + s2; M2 = m2; }
                    else S += s2 * __expf(m2 - M2);
                }
                g_apart[bid][0] = B; g_apart[bid][1] = M2;
                g_apart[bid][2] = S; g_aidx[bid] = I;
            }

            __threadfence();
            __syncthreads();
            if (tid == 0) {
                int v = atomicAdd(&g_ticket, 1);
                islast = ((v % nb) == nb - 1);
            }
            __syncthreads();
            if (islast) {
                g_qh[tid] = 0.f; g_qh[tid + 256] = 0.f;
                float B = NEGINF; int I = 0x7fffffff; float M = NEGINF; float S = 0.f;
                for (int b = tid; b < nb; b += 256) {
                    float bb = g_apart[b][0]; int ii = g_aidx[b];
                    if (bb > B || (bb == B && ii < I)) { B = bb; I = ii; }
                    float m2 = g_apart[b][1], s2 = g_apart[b][2];
                    if (m2 > M) { S = S * __expf(M - m2) + s2; M = m2; }
                    else S += s2 * __expf(m2 - M);
                }
                fb[tid] = B; fi[tid] = I; fm[tid] = M; fs[tid] = S;
                __syncthreads();
                for (int o = 128; o; o >>= 1) {
                    if (tid < o) {
                        if (fb[tid + o] > fb[tid] || (fb[tid + o] == fb[tid] && fi[tid + o] < fi[tid])) {
                            fb[tid] = fb[tid + o]; fi[tid] = fi[tid + o];
                        }
                        float m1 = fm[tid], s1 = fs[tid];
                        float m2 = fm[tid + o], s2 = fs[tid + o];
                        float Mn = fmaxf(m1, m2);
                        float Sn = 0.f;
                        if (s1 > 0.f) Sn += s1 * __expf(m1 - Mn);
                        if (s2 > 0.f) Sn += s2 * __expf(m2 - Mn);
                        fm[tid] = Mn; fs[tid] = Sn;
                    }
                    __syncthreads();
                }
                if (tid == 0) {
                    int done = g_done;
                    int o_ = fi[0];
                    float sc = fb[0] - gum[o_];
                    float lse = fm[0] + logf(fs[0]);
                    float logp = sc - lse;
                    out[t]          = done ? (float)NPTS : (float)o_;
                    out[TSTEPS + t] = done ? 0.f : logp;
                    if (!done) g_sel[o_] = 1;
                    int nd = done || (o_ == NPTS);
                    g_done = nd;
                    s_out = o_; s_nd = nd;
                }
                __syncthreads();
                if (!s_nd) {
                    int o_ = s_out;
                    const float* src = (o_ == NPTS) ? stop : attn_mem + (size_t)o_ * DIM;
                    g_x[tid] = src[tid];
                    g_x[tid + 256] = src[tid + 256];
                }
                __threadfence();
                __syncthreads();
                if (tid == 0) g_xready = t + 1;   // release x/h/qh for phase A(t+1)
            }
        }
        // no gridbar here: phase A is flag-gated; pre-B gridbar orders everything else
    }
}

// ---------------- launch ----------------
extern "C" void kernel_launch(void* const* d_in, const int* in_sizes, int n_in,
                              void* d_out, int out_size) {
    const float* attn_mem = (const float*)d_in[0];
    const float* stop     = (const float*)d_in[1];
    const float* init_h   = (const float*)d_in[2];
    const float* init_c   = (const float*)d_in[3];
    const float* init_i   = (const float*)d_in[4];
    const float* attn_wm  = (const float*)d_in[5];
    const float* attn_wq  = (const float*)d_in[6];
    const float* attn_v   = (const float*)d_in[7];
    const float* hop_wm   = (const float*)d_in[8];
    const float* hop_wq   = (const float*)d_in[9];
    const float* hop_v    = (const float*)d_in[10];
    const float* w_ih     = (const float*)d_in[11];
    const float* w_hh     = (const float*)d_in[12];
    const float* b_ih     = (const float*)d_in[13];
    const float* b_hh     = (const float*)d_in[14];
    const float* gumbel   = (const float*)d_in[15];
    float* out = (float*)d_out;

    static int nb = 0;
    if (nb == 0) {
        int sms = 0;
        cudaDeviceGetAttribute(&sms, cudaDevAttrMultiProcessorCount, 0);
        nb = 2 * sms;
        if (nb > NBMAX) nb = NBMAX;
        if (nb < 128) nb = 128;
        cudaFuncSetAttribute(k_feat_mma, cudaFuncAttributeMaxDynamicSharedMemorySize, FEAT_SMEM);
    }

    k_init<<<(MPTS + 255) / 256, 256>>>(init_h, init_c, init_i);
    k_convA<<<8192, 256>>>(attn_mem, stop);
    k_convB<<<2048, 256>>>(attn_wm, hop_wm);

    dim3 gg(8, ROWT);
    k_feat_mma<<<gg, 256, FEAT_SMEM>>>();

    k_step<<<nb, 256>>>(w_ih, w_hh, b_ih, b_hh, hop_wq, hop_v,
                        attn_wq, attn_v, gumbel, attn_mem, stop, out, nb);
}